// round 10
// baseline (speedup 1.0000x reference)
#include <cuda_runtime.h>
#include <math.h>
#include <stdint.h>

#define S 2048
#define D 1024
#define NH 8
#define NKV 2
#define HD 128
#define WS 64
#define NE 16
#define HDIM 512
#define NA (S*2)

// ---------------- scratch (static device globals; no allocation) ------------
__device__ float g_h[S*D];
__device__ float g_q[S*D];
__device__ float g_k[S*NKV*HD];
__device__ float g_v[S*NKV*HD];
__device__ float g_attn[S*D];
__device__ float g_x1[S*D];
__device__ float g_h2[S*D];
__device__ float g_probs[S*NE];
__device__ float g_topw[S*2];
__device__ int   g_topi[S*2];
__device__ int   g_cnt[NE];
__device__ int   g_off[NE];
__device__ int   g_cur[NE];
__device__ int   g_atok[NA];
__device__ float g_aw[NA];
__device__ int   g_tslot[S*2];
__device__ float g_hmid[NA*HDIM];
__device__ float g_y[NA*D];
__device__ float g_colsum[NE];

// ---------------- RMSNorm ----------------------------------------------------
__global__ void rmsnorm_kernel(const float* __restrict__ x,
                               const float* __restrict__ w,
                               float* __restrict__ o) {
    int row = blockIdx.x;
    int tid = threadIdx.x;
    const float4* x4 = (const float4*)(x + (size_t)row * D);
    float4 v = x4[tid];
    float ss = v.x*v.x + v.y*v.y + v.z*v.z + v.w*v.w;
    __shared__ float red[8];
    #pragma unroll
    for (int s = 16; s; s >>= 1) ss += __shfl_xor_sync(0xffffffffu, ss, s);
    if ((tid & 31) == 0) red[tid >> 5] = ss;
    __syncthreads();
    if (tid < 32) {
        float t = (tid < 8) ? red[tid] : 0.f;
        #pragma unroll
        for (int s = 4; s; s >>= 1) t += __shfl_xor_sync(0xffffffffu, t, s);
        if (tid == 0) red[0] = t;
    }
    __syncthreads();
    float r = rsqrtf(red[0] * (1.0f / (float)D) + 1e-6f);
    const float4* w4 = (const float4*)w;
    float4 wv = w4[tid];
    float4 out;
    out.x = v.x * r * wv.x; out.y = v.y * r * wv.y;
    out.z = v.z * r * wv.z; out.w = v.w * r * wv.w;
    ((float4*)(o + (size_t)row * D))[tid] = out;
}

// =============================================================================
// GEMM geometry: CTA tile 128x128x16, 8 warps (2x4), warp tile 64x32.
// =============================================================================
#define BM 128
#define BN 128
#define BKT 16

// tf32 path (MoE, 1-term)
#define ASTR 20
#define BSTR 136
#define APLANE (BM*ASTR)   // 2560 words
#define BPLANE (BKT*BSTR)  // 2176 words

// bf16 path (attention GEMMs, 3-term split)
#define ASTRH 12
#define BSTRH 136
#define APLANEH (BM*ASTRH)       // 1536 words
#define BPLANEH (8*BSTRH)        // 1088 words
#define HSTAGE (2*APLANEH + 2*BPLANEH)   // 5248 words

static __device__ __forceinline__ uint32_t f2tf(float x) {
    uint32_t r; asm("cvt.rna.tf32.f32 %0, %1;" : "=r"(r) : "f"(x)); return r;
}
static __device__ __forceinline__ uint32_t packbf2(float lo_k, float hi_k) {
    uint32_t r; asm("cvt.rn.bf16x2.f32 %0, %1, %2;" : "=r"(r) : "f"(hi_k), "f"(lo_k));
    return r;
}
static __device__ __forceinline__ void mma8(float* d, const uint32_t* a, const uint32_t* b) {
    asm volatile("mma.sync.aligned.m16n8k8.row.col.f32.tf32.tf32.f32 "
        "{%0,%1,%2,%3}, {%4,%5,%6,%7}, {%8,%9}, {%0,%1,%2,%3};\n"
        : "+f"(d[0]), "+f"(d[1]), "+f"(d[2]), "+f"(d[3])
        : "r"(a[0]), "r"(a[1]), "r"(a[2]), "r"(a[3]), "r"(b[0]), "r"(b[1]));
}
static __device__ __forceinline__ void mma16(float* d, const uint32_t* a, const uint32_t* b) {
    asm volatile("mma.sync.aligned.m16n8k16.row.col.f32.bf16.bf16.f32 "
        "{%0,%1,%2,%3}, {%4,%5,%6,%7}, {%8,%9}, {%0,%1,%2,%3};\n"
        : "+f"(d[0]), "+f"(d[1]), "+f"(d[2]), "+f"(d[3])
        : "r"(a[0]), "r"(a[1]), "r"(a[2]), "r"(a[3]), "r"(b[0]), "r"(b[1]));
}

// shared epilogue: bias [+resid][silu], write C ; warp tile 64x32 (i = 0..3)
template<int XEPI>
static __device__ __forceinline__ void gemm_epilogue(
    float acc[4][4][4], const float* __restrict__ bias, const float* __restrict__ resid,
    float* __restrict__ C, int M, int Nld, int m0, int n0, int wm, int wn, int g, int tg)
{
    #pragma unroll
    for (int i = 0; i < 4; i++) {
        int rr0 = m0 + wm + i*16 + g;
        int rr1 = rr0 + 8;
        #pragma unroll
        for (int j = 0; j < 4; j++) {
            int c = n0 + wn + j*8 + tg*2;
            float b0v = bias[c], b1v = bias[c+1];
            if (rr0 < M) {
                float t0 = acc[i][j][0] + b0v;
                float t1 = acc[i][j][1] + b1v;
                if (XEPI == 1) {
                    t0 += resid[(size_t)rr0*Nld + c];
                    t1 += resid[(size_t)rr0*Nld + c + 1];
                }
                if (XEPI == 2) {
                    t0 = t0 / (1.f + expf(-t0));
                    t1 = t1 / (1.f + expf(-t1));
                }
                float2 o; o.x = t0; o.y = t1;
                *(float2*)&C[(size_t)rr0*Nld + c] = o;
            }
            if (rr1 < M) {
                float t0 = acc[i][j][2] + b0v;
                float t1 = acc[i][j][3] + b1v;
                if (XEPI == 1) {
                    t0 += resid[(size_t)rr1*Nld + c];
                    t1 += resid[(size_t)rr1*Nld + c + 1];
                }
                if (XEPI == 2) {
                    t0 = t0 / (1.f + expf(-t0));
                    t1 = t1 / (1.f + expf(-t1));
                }
                float2 o; o.x = t0; o.y = t1;
                *(float2*)&C[(size_t)rr1*Nld + c] = o;
            }
        }
    }
}

// =============================================================================
// bf16 3-term split GEMM core
// stage layout: [Ahi | Alo | Bhi | Blo]
// =============================================================================
static __device__ __forceinline__ void store_stage_bf16(
    uint32_t* base, float4 ra0, float4 ra1, float4 rb0v, float4 rb1v,
    int arow0, int arow1, int pa0, int pr, int bc)
{
    // A rows arow0 (ra0) and arow1 (ra1), k-pairs pa0, pa0+1
    {
        uint32_t p0 = packbf2(ra0.x, ra0.y);
        uint32_t p1 = packbf2(ra0.z, ra0.w);
        base[arow0*ASTRH + pa0]     = p0;
        base[arow0*ASTRH + pa0 + 1] = p1;
        float l0 = ra0.x - __uint_as_float(p0 << 16);
        float l1 = ra0.y - __uint_as_float(p0 & 0xffff0000u);
        float l2 = ra0.z - __uint_as_float(p1 << 16);
        float l3 = ra0.w - __uint_as_float(p1 & 0xffff0000u);
        base[APLANEH + arow0*ASTRH + pa0]     = packbf2(l0, l1);
        base[APLANEH + arow0*ASTRH + pa0 + 1] = packbf2(l2, l3);
    }
    {
        uint32_t p0 = packbf2(ra1.x, ra1.y);
        uint32_t p1 = packbf2(ra1.z, ra1.w);
        base[arow1*ASTRH + pa0]     = p0;
        base[arow1*ASTRH + pa0 + 1] = p1;
        float l0 = ra1.x - __uint_as_float(p0 << 16);
        float l1 = ra1.y - __uint_as_float(p0 & 0xffff0000u);
        float l2 = ra1.z - __uint_as_float(p1 << 16);
        float l3 = ra1.w - __uint_as_float(p1 & 0xffff0000u);
        base[APLANEH + arow1*ASTRH + pa0]     = packbf2(l0, l1);
        base[APLANEH + arow1*ASTRH + pa0 + 1] = packbf2(l2, l3);
    }
    // B pair-row pr: packs k=2pr (lo half) and k=2pr+1 (hi half), 4 cols
    float b0a[4] = {rb0v.x, rb0v.y, rb0v.z, rb0v.w};
    float b1a[4] = {rb1v.x, rb1v.y, rb1v.z, rb1v.w};
    uint32_t hp[4], lp[4];
    #pragma unroll
    for (int j = 0; j < 4; j++) {
        uint32_t h = packbf2(b0a[j], b1a[j]);
        hp[j] = h;
        float ll0 = b0a[j] - __uint_as_float(h << 16);
        float ll1 = b1a[j] - __uint_as_float(h & 0xffff0000u);
        lp[j] = packbf2(ll0, ll1);
    }
    *(uint4*)&base[2*APLANEH + pr*BSTRH + bc] = make_uint4(hp[0], hp[1], hp[2], hp[3]);
    *(uint4*)&base[2*APLANEH + BPLANEH + pr*BSTRH + bc] = make_uint4(lp[0], lp[1], lp[2], lp[3]);
}

template<int XEPI>
static __device__ __forceinline__ void gemm_core_bf16(
    uint32_t* Hsm,
    const float* __restrict__ A, const float* __restrict__ B,
    const float* __restrict__ bias, const float* __restrict__ resid,
    float* __restrict__ C, int M, int Nld, int K, int m0, int n0)
{
    int tid = threadIdx.x;
    int arow0 = tid >> 2, arow1 = arow0 + 64;     // two A rows per thread
    int ac = (tid & 3) * 4;
    int pa0 = (tid & 3) * 2;
    int r0 = m0 + arow0, r1 = m0 + arow1;
    bool v0 = r0 < M, v1 = r1 < M;
    const float* Ar0 = A + (size_t)(v0 ? r0 : 0) * K;
    const float* Ar1 = A + (size_t)(v1 ? r1 : 0) * K;
    int pr = tid >> 5;
    int bc = (tid & 31) * 4;
    const float* Bp0 = B + (size_t)(2*pr) * Nld + n0 + bc;
    const float* Bp1 = Bp0 + Nld;

    int lane = tid & 31, g = lane >> 2, tg = lane & 3;
    int wm = (tid >> 7) * 64;
    int wn = ((tid >> 5) & 3) * 32;

    float acc[4][4][4];
    #pragma unroll
    for (int i = 0; i < 4; i++)
        #pragma unroll
        for (int j = 0; j < 4; j++)
            #pragma unroll
            for (int c = 0; c < 4; c++) acc[i][j][c] = 0.f;

    float4 ra0  = v0 ? *(const float4*)(Ar0 + ac) : make_float4(0.f,0.f,0.f,0.f);
    float4 ra1  = v1 ? *(const float4*)(Ar1 + ac) : make_float4(0.f,0.f,0.f,0.f);
    float4 rb0v = *(const float4*)(Bp0);
    float4 rb1v = *(const float4*)(Bp1);
    store_stage_bf16(Hsm, ra0, ra1, rb0v, rb1v, arow0, arow1, pa0, pr, bc);
    __syncthreads();
    int cur = 0;

    for (int k0 = 0; k0 < K; k0 += BKT) {
        int kn = k0 + BKT;
        bool more = kn < K;
        if (more) {
            ra0  = v0 ? *(const float4*)(Ar0 + kn + ac) : make_float4(0.f,0.f,0.f,0.f);
            ra1  = v1 ? *(const float4*)(Ar1 + kn + ac) : make_float4(0.f,0.f,0.f,0.f);
            rb0v = *(const float4*)(Bp0 + (size_t)kn * Nld);
            rb1v = *(const float4*)(Bp1 + (size_t)kn * Nld);
        }
        const uint32_t* Ah = Hsm + cur * HSTAGE;
        const uint32_t* Al = Ah + APLANEH;
        const uint32_t* Bh = Ah + 2*APLANEH;
        const uint32_t* Bl = Bh + BPLANEH;

        // b-frags for all 4 j (hi + lo)
        uint32_t bh[4][2], bl[4][2];
        #pragma unroll
        for (int j = 0; j < 4; j++) {
            int nb = wn + j*8 + g;
            bh[j][0] = Bh[tg*BSTRH + nb];       bh[j][1] = Bh[(tg+4)*BSTRH + nb];
            bl[j][0] = Bl[tg*BSTRH + nb];       bl[j][1] = Bl[(tg+4)*BSTRH + nb];
        }
        // per-i: load a-frags (hi+lo), run 3 terms over 4 j
        #pragma unroll
        for (int i = 0; i < 4; i++) {
            int mb = wm + i*16 + g;
            uint32_t ah[4], al[4];
            ah[0] = Ah[mb*ASTRH + tg];       ah[1] = Ah[(mb+8)*ASTRH + tg];
            ah[2] = Ah[mb*ASTRH + tg+4];     ah[3] = Ah[(mb+8)*ASTRH + tg+4];
            al[0] = Al[mb*ASTRH + tg];       al[1] = Al[(mb+8)*ASTRH + tg];
            al[2] = Al[mb*ASTRH + tg+4];     al[3] = Al[(mb+8)*ASTRH + tg+4];
            #pragma unroll
            for (int j = 0; j < 4; j++) mma16(acc[i][j], ah, bh[j]);
            #pragma unroll
            for (int j = 0; j < 4; j++) mma16(acc[i][j], ah, bl[j]);
            #pragma unroll
            for (int j = 0; j < 4; j++) mma16(acc[i][j], al, bh[j]);
        }

        if (more) {
            store_stage_bf16(Hsm + (cur ^ 1) * HSTAGE, ra0, ra1, rb0v, rb1v,
                             arow0, arow1, pa0, pr, bc);
            __syncthreads();
            cur ^= 1;
        }
    }
    gemm_epilogue<XEPI>(acc, bias, resid, C, M, Nld, m0, n0, wm, wn, g, tg);
}

// =============================================================================
// tf32 single-term GEMM core (MoE path), 128x128 tile
// =============================================================================
#define STORE_TILE(stg) do { \
    uint32_t* Ab = Asm + (stg) * APLANE; \
    uint32_t* Bb = Bsm + (stg) * BPLANE; \
    float av0[4] = {ra0.x, ra0.y, ra0.z, ra0.w}; \
    float av1[4] = {ra1.x, ra1.y, ra1.z, ra1.w}; \
    _Pragma("unroll") \
    for (int j = 0; j < 4; j++) { \
        Ab[arow0*ASTR + ac + j] = f2tf(av0[j]); \
        Ab[arow1*ASTR + ac + j] = f2tf(av1[j]); \
    } \
    float bvv[8] = {rb0v.x, rb0v.y, rb0v.z, rb0v.w, rb1v.x, rb1v.y, rb1v.z, rb1v.w}; \
    _Pragma("unroll") \
    for (int j = 0; j < 8; j++) { \
        int row = (j < 4) ? brow : (brow + 8); \
        Bb[row*BSTR + bc + (j & 3)] = f2tf(bvv[j]); \
    } \
} while (0)

template<int XEPI, int XGATHER>
static __device__ __forceinline__ void gemm_core_tf32(
    uint32_t* Asm, uint32_t* Bsm,
    const float* __restrict__ A, const float* __restrict__ B,
    const float* __restrict__ bias, const float* __restrict__ resid,
    float* __restrict__ C, int M, int Nld, int K, int m0, int n0,
    const int* __restrict__ rowidx)
{
    int tid = threadIdx.x;
    int arow0 = tid >> 2, arow1 = arow0 + 64;
    int ac = (tid & 3) * 4;
    int r0 = m0 + arow0, r1 = m0 + arow1;
    bool v0 = r0 < M, v1 = r1 < M;
    int gr0 = v0 ? (XGATHER ? rowidx[r0] : r0) : 0;
    int gr1 = v1 ? (XGATHER ? rowidx[r1] : r1) : 0;
    const float* Ar0 = A + (size_t)gr0 * K;
    const float* Ar1 = A + (size_t)gr1 * K;
    int brow = tid >> 5;
    int bc = (tid & 31) * 4;
    const float* Bp0 = B + (size_t)brow * Nld + n0 + bc;
    const float* Bp1 = Bp0 + (size_t)8 * Nld;

    int lane = tid & 31, g = lane >> 2, tg = lane & 3;
    int wm = (tid >> 7) * 64;
    int wn = ((tid >> 5) & 3) * 32;

    float acc[4][4][4];
    #pragma unroll
    for (int i = 0; i < 4; i++)
        #pragma unroll
        for (int j = 0; j < 4; j++)
            #pragma unroll
            for (int c = 0; c < 4; c++) acc[i][j][c] = 0.f;

    float4 ra0  = v0 ? *(const float4*)(Ar0 + ac) : make_float4(0.f,0.f,0.f,0.f);
    float4 ra1  = v1 ? *(const float4*)(Ar1 + ac) : make_float4(0.f,0.f,0.f,0.f);
    float4 rb0v = *(const float4*)(Bp0);
    float4 rb1v = *(const float4*)(Bp1);
    STORE_TILE(0);
    __syncthreads();
    int cur = 0;

    for (int k0 = 0; k0 < K; k0 += BKT) {
        int kn = k0 + BKT;
        bool more = kn < K;
        if (more) {
            ra0  = v0 ? *(const float4*)(Ar0 + kn + ac) : make_float4(0.f,0.f,0.f,0.f);
            ra1  = v1 ? *(const float4*)(Ar1 + kn + ac) : make_float4(0.f,0.f,0.f,0.f);
            rb0v = *(const float4*)(Bp0 + (size_t)kn * Nld);
            rb1v = *(const float4*)(Bp1 + (size_t)kn * Nld);
        }
        const uint32_t* Ab = Asm + cur * APLANE;
        const uint32_t* Bb = Bsm + cur * BPLANE;
        #pragma unroll
        for (int ks = 0; ks < BKT; ks += 8) {
            uint32_t bf[4][2];
            #pragma unroll
            for (int j = 0; j < 4; j++) {
                int nb = wn + j*8 + g;
                bf[j][0] = Bb[(ks+tg)*BSTR + nb];
                bf[j][1] = Bb[(ks+tg+4)*BSTR + nb];
            }
            #pragma unroll
            for (int i = 0; i < 4; i++) {
                int mb = wm + i*16 + g;
                uint32_t af[4];
                af[0] = Ab[mb*ASTR + ks+tg];
                af[1] = Ab[(mb+8)*ASTR + ks+tg];
                af[2] = Ab[mb*ASTR + ks+tg+4];
                af[3] = Ab[(mb+8)*ASTR + ks+tg+4];
                #pragma unroll
                for (int j = 0; j < 4; j++) mma8(acc[i][j], af, bf[j]);
            }
        }
        if (more) {
            STORE_TILE(cur ^ 1);
            __syncthreads();
            cur ^= 1;
        }
    }
    gemm_epilogue<XEPI>(acc, bias, resid, C, M, Nld, m0, n0, wm, wn, g, tg);
}

// ---- fused QKV (bf16 3-term): grid (12, 16) ---------------------------------
__global__ void __launch_bounds__(256, 2) qkv_kernel(
    const float* __restrict__ h,
    const float* __restrict__ wq, const float* __restrict__ bq,
    const float* __restrict__ wk, const float* __restrict__ bk,
    const float* __restrict__ wv, const float* __restrict__ bv)
{
    __shared__ __align__(16) uint32_t Hsm[2*HSTAGE];
    int x = blockIdx.x, m0 = blockIdx.y * BM;
    if (x < 8)
        gemm_core_bf16<0>(Hsm, h, wq, bq, nullptr, g_q, S, 1024, 1024, m0, x*128);
    else if (x < 10)
        gemm_core_bf16<0>(Hsm, h, wk, bk, nullptr, g_k, S, 256, 1024, m0, (x-8)*128);
    else
        gemm_core_bf16<0>(Hsm, h, wv, bv, nullptr, g_v, S, 256, 1024, m0, (x-10)*128);
}

// ---- O-proj + residual (bf16 3-term): grid (8, 16) --------------------------
__global__ void __launch_bounds__(256, 2) oproj_kernel(
    const float* __restrict__ wo, const float* __restrict__ bo,
    const float* __restrict__ x)
{
    __shared__ __align__(16) uint32_t Hsm[2*HSTAGE];
    gemm_core_bf16<1>(Hsm, g_attn, wo, bo, x, g_x1, S, 1024, 1024,
                      blockIdx.y*BM, blockIdx.x*BN);
}

// ---- MoE expert GEMMs (1xTF32, grouped) -------------------------------------
__global__ void __launch_bounds__(256, 2) moe1_kernel(
    const float* __restrict__ h2, const float* __restrict__ w1,
    const float* __restrict__ b1)
{
    int e = blockIdx.z;
    int M = g_cnt[e];
    int m0 = blockIdx.y * BM;
    if (m0 >= M) return;
    int o = g_off[e];
    __shared__ uint32_t sA[2*APLANE];
    __shared__ uint32_t sB[2*BPLANE];
    gemm_core_tf32<2,1>(sA, sB, h2, w1 + (size_t)e*1024*512, b1 + (size_t)e*512,
                        nullptr, g_hmid + (size_t)o*512, M, 512, 1024,
                        m0, blockIdx.x*BN, g_atok + o);
}

__global__ void __launch_bounds__(256, 2) moe2_kernel(
    const float* __restrict__ w2, const float* __restrict__ b2)
{
    int e = blockIdx.z;
    int M = g_cnt[e];
    int m0 = blockIdx.y * BM;
    if (m0 >= M) return;
    int o = g_off[e];
    __shared__ uint32_t sA[2*APLANE];
    __shared__ uint32_t sB[2*BPLANE];
    gemm_core_tf32<0,0>(sA, sB, g_hmid + (size_t)o*512, w2 + (size_t)e*512*1024,
                        b2 + (size_t)e*1024, nullptr, g_y + (size_t)o*1024,
                        M, 1024, 512, m0, blockIdx.x*BN, nullptr);
}

// ---------------- sliding-window attention, 1 warp = 1 query row ------------
__global__ void attn_kernel(const float* __restrict__ sinkp) {
    int warp = threadIdx.x >> 5, lane = threadIdx.x & 31;
    int i = blockIdx.x * 8 + warp;
    int h = blockIdx.y;
    int kvh = h >> 2;  // NH/NKV = 4
    const float scale = 0.08838834764831845f;  // 1/sqrt(128)

    float qr[4];
    const float* qp = g_q + (size_t)i * D + h * HD;
    #pragma unroll
    for (int c = 0; c < 4; c++) qr[c] = qp[lane + 32 * c];

    int jstart = (i >= (WS - 1)) ? (i - (WS - 1)) : 0;
    int cnt = i - jstart + 1;

    float s0 = -1e30f, s1 = -1e30f;
    for (int jj = 0; jj < cnt; ++jj) {
        const float* kp = g_k + (size_t)(jstart + jj) * (NKV * HD) + kvh * HD;
        float p = qr[0]*kp[lane] + qr[1]*kp[lane+32] + qr[2]*kp[lane+64] + qr[3]*kp[lane+96];
        #pragma unroll
        for (int s = 16; s; s >>= 1) p += __shfl_xor_sync(0xffffffffu, p, s);
        p *= scale;
        if ((jj & 31) == lane) { if (jj < 32) s0 = p; else s1 = p; }
    }
    float sink = *sinkp;
    float m = fmaxf(s0, s1);
    #pragma unroll
    for (int s = 16; s; s >>= 1) m = fmaxf(m, __shfl_xor_sync(0xffffffffu, m, s));
    m = fmaxf(m, sink);
    float e0 = expf(s0 - m), e1 = expf(s1 - m);
    float dsum = e0 + e1;
    #pragma unroll
    for (int s = 16; s; s >>= 1) dsum += __shfl_xor_sync(0xffffffffu, dsum, s);
    dsum += expf(sink - m);
    float inv = 1.f / dsum;

    float o0 = 0.f, o1 = 0.f, o2 = 0.f, o3 = 0.f;
    for (int jj = 0; jj < cnt; ++jj) {
        float pv = (jj < 32) ? e0 : e1;
        float p = __shfl_sync(0xffffffffu, pv, jj & 31);
        const float* vp = g_v + (size_t)(jstart + jj) * (NKV * HD) + kvh * HD;
        o0 += p * vp[lane];      o1 += p * vp[lane + 32];
        o2 += p * vp[lane + 64]; o3 += p * vp[lane + 96];
    }
    float* op = g_attn + (size_t)i * D + h * HD;
    op[lane]      = o0 * inv; op[lane + 32] = o1 * inv;
    op[lane + 64] = o2 * inv; op[lane + 96] = o3 * inv;
}

// ---------------- router: 1 warp = 1 token ----------------------------------
__global__ void router_kernel(const float* __restrict__ rw, const float* __restrict__ rb) {
    int warp = threadIdx.x >> 5, lane = threadIdx.x & 31;
    int t = blockIdx.x * 8 + warp;
    float acc[NE];
    #pragma unroll
    for (int e = 0; e < NE; e++) acc[e] = 0.f;
    const float* xr = g_h2 + (size_t)t * D;
    for (int d = lane; d < D; d += 32) {
        float xv = xr[d];
        const float* rr = rw + d * NE;
        #pragma unroll
        for (int e = 0; e < NE; e++) acc[e] += xv * rr[e];
    }
    #pragma unroll
    for (int e = 0; e < NE; e++) {
        float a = acc[e];
        #pragma unroll
        for (int s = 16; s; s >>= 1) a += __shfl_xor_sync(0xffffffffu, a, s);
        acc[e] = a;
    }
    if (lane == 0) {
        float logit[NE]; float m = -1e30f;
        #pragma unroll
        for (int e = 0; e < NE; e++) { logit[e] = (acc[e] + rb[e]) * 10.f; m = fmaxf(m, logit[e]); }
        float pe[NE]; float ssum = 0.f;
        #pragma unroll
        for (int e = 0; e < NE; e++) { pe[e] = expf(logit[e] - m); ssum += pe[e]; }
        float invs = 1.f / ssum;
        #pragma unroll
        for (int e = 0; e < NE; e++) g_probs[t * NE + e] = pe[e] * invs;
        int i0 = 0; float v0 = logit[0];
        #pragma unroll
        for (int e = 1; e < NE; e++) if (logit[e] > v0) { v0 = logit[e]; i0 = e; }
        int i1 = -1; float v1 = -1e30f;
        #pragma unroll
        for (int e = 0; e < NE; e++) if (e != i0 && logit[e] > v1) { v1 = logit[e]; i1 = e; }
        float ex = expf(v1 - v0);
        float w0 = 1.f / (1.f + ex);
        g_topi[t*2] = i0; g_topi[t*2+1] = i1;
        g_topw[t*2] = w0; g_topw[t*2+1] = 1.f - w0;
        atomicAdd(&g_cnt[i0], 1); atomicAdd(&g_cnt[i1], 1);
    }
}

__global__ void zero_kernel() {
    int t = threadIdx.x;
    if (t < NE) { g_cnt[t] = 0; g_cur[t] = 0; }
}

__global__ void offsets_kernel() {
    if (threadIdx.x == 0) {
        int s = 0;
        for (int e = 0; e < NE; e++) { g_off[e] = s; s += g_cnt[e]; }
    }
}

__global__ void place_kernel() {
    int t = blockIdx.x * blockDim.x + threadIdx.x;
    if (t >= S) return;
    #pragma unroll
    for (int k2 = 0; k2 < 2; k2++) {
        int e = g_topi[t*2 + k2];
        int slot = g_off[e] + atomicAdd(&g_cur[e], 1);
        g_atok[slot] = t;
        g_aw[slot] = g_topw[t*2 + k2];
        g_tslot[t*2 + k2] = slot;
    }
}

__global__ void colsum_kernel() {
    int e = blockIdx.x; int tid = threadIdx.x;
    float s = 0.f;
    for (int t = tid; t < S; t += 256) s += g_probs[t * NE + e];
    __shared__ float red[256];
    red[tid] = s; __syncthreads();
    for (int st = 128; st; st >>= 1) { if (tid < st) red[tid] += red[tid + st]; __syncthreads(); }
    if (tid == 0) g_colsum[e] = red[0];
}

__global__ void combine_kernel(float* __restrict__ out) {
    int t = blockIdx.x; int c = threadIdx.x;
    int s0 = g_tslot[t*2], s1 = g_tslot[t*2+1];
    float w0 = g_aw[s0], w1 = g_aw[s1];
    const float4* x14 = (const float4*)(g_x1 + (size_t)t * D);
    const float4* y0  = (const float4*)(g_y + (size_t)s0 * D);
    const float4* y1  = (const float4*)(g_y + (size_t)s1 * D);
    float4 a = x14[c], b = y0[c], d2 = y1[c];
    float4 o;
    o.x = a.x + w0*b.x + w1*d2.x; o.y = a.y + w0*b.y + w1*d2.y;
    o.z = a.z + w0*b.z + w1*d2.z; o.w = a.w + w0*b.w + w1*d2.w;
    ((float4*)out)[(size_t)t * (D/4) + c] = o;
}

__global__ void aux_kernel(float* __restrict__ out, int out_size) {
    int tid = threadIdx.x;
    float v = (tid < NE) ? g_colsum[tid] * g_colsum[tid] : 0.f;
    #pragma unroll
    for (int s = 16; s; s >>= 1) v += __shfl_xor_sync(0xffffffffu, v, s);
    if (tid == 0) {
        float aux = v * (1.0f / (float)NE) * 1e-5f;
        for (int idx = S * D; idx < out_size; ++idx) out[idx] = aux;
    }
}

// ---------------- launch -----------------------------------------------------
extern "C" void kernel_launch(void* const* d_in, const int* in_sizes, int n_in,
                              void* d_out, int out_size) {
    const float* x    = (const float*)d_in[0];
    const float* n1w  = (const float*)d_in[1];
    const float* wq   = (const float*)d_in[2];
    const float* bq   = (const float*)d_in[3];
    const float* wk   = (const float*)d_in[4];
    const float* bk   = (const float*)d_in[5];
    const float* wv   = (const float*)d_in[6];
    const float* bv   = (const float*)d_in[7];
    const float* wo   = (const float*)d_in[8];
    const float* bo   = (const float*)d_in[9];
    const float* sink = (const float*)d_in[10];
    const float* n2w  = (const float*)d_in[11];
    const float* rw   = (const float*)d_in[12];
    const float* rb   = (const float*)d_in[13];
    const float* w1   = (const float*)d_in[14];
    const float* b1   = (const float*)d_in[15];
    const float* w2   = (const float*)d_in[16];
    const float* b2   = (const float*)d_in[17];
    float* out = (float*)d_out;

    void* p;
    cudaGetSymbolAddress(&p, g_h);    float* hB    = (float*)p;
    cudaGetSymbolAddress(&p, g_x1);   float* x1B   = (float*)p;
    cudaGetSymbolAddress(&p, g_h2);   float* h2B   = (float*)p;

    // 1) RMSNorm1
    rmsnorm_kernel<<<S, 256>>>(x, n1w, hB);

    // 2) fused QKV projections (bf16x2 3-term tensor cores, 128x128 tiles)
    qkv_kernel<<<dim3(12, 16), 256>>>(hB, wq, bq, wk, bk, wv, bv);

    // 3) sliding-window attention with sink
    attn_kernel<<<dim3(S/8, NH), 256>>>(sink);

    // 4) O-proj + residual (bf16x2 3-term)
    oproj_kernel<<<dim3(8, 16), 256>>>(wo, bo, x);

    // 5) RMSNorm2
    rmsnorm_kernel<<<S, 256>>>(x1B, n2w, h2B);

    // 6) router + grouping
    zero_kernel<<<1, 32>>>();
    router_kernel<<<S/8, 256>>>(rw, rb);
    offsets_kernel<<<1, 32>>>();
    place_kernel<<<8, 256>>>();
    colsum_kernel<<<NE, 256>>>();

    // 7) grouped MoE GEMMs (top-2 only, 1xTF32, 128x128 tiles)
    moe1_kernel<<<dim3(4, 16, NE), 256>>>(h2B, w1, b1);
    moe2_kernel<<<dim3(8, 16, NE), 256>>>(w2, b2);

    // 8) combine + residual, aux loss
    combine_kernel<<<S, 256>>>(out);
    aux_kernel<<<1, 32>>>(out, out_size);
}

// round 11
// speedup vs baseline: 1.0505x; 1.0505x over previous
#include <cuda_runtime.h>
#include <math.h>
#include <stdint.h>

#define S 2048
#define D 1024
#define NH 8
#define NKV 2
#define HD 128
#define WS 64
#define NE 16
#define HDIM 512
#define NA (S*2)

// ---------------- scratch (static device globals; no allocation) ------------
__device__ float g_h[S*D];
__device__ float g_q[S*D];
__device__ float g_k[S*NKV*HD];
__device__ float g_v[S*NKV*HD];
__device__ float g_attn[S*D];
__device__ float g_x1[S*D];
__device__ float g_h2[S*D];
__device__ float g_probs[S*NE];
__device__ float g_topw[S*2];
__device__ int   g_topi[S*2];
__device__ int   g_cnt[NE];
__device__ int   g_off[NE];
__device__ int   g_cur[NE];
__device__ int   g_atok[NA];
__device__ float g_aw[NA];
__device__ int   g_tslot[S*2];
__device__ float g_hmid[NA*HDIM];
__device__ float g_y[NA*D];
__device__ float g_colsum[NE];

// ---------------- RMSNorm ----------------------------------------------------
__global__ void rmsnorm_kernel(const float* __restrict__ x,
                               const float* __restrict__ w,
                               float* __restrict__ o) {
    int row = blockIdx.x;
    int tid = threadIdx.x;
    const float4* x4 = (const float4*)(x + (size_t)row * D);
    float4 v = x4[tid];
    float ss = v.x*v.x + v.y*v.y + v.z*v.z + v.w*v.w;
    __shared__ float red[8];
    #pragma unroll
    for (int s = 16; s; s >>= 1) ss += __shfl_xor_sync(0xffffffffu, ss, s);
    if ((tid & 31) == 0) red[tid >> 5] = ss;
    __syncthreads();
    if (tid < 32) {
        float t = (tid < 8) ? red[tid] : 0.f;
        #pragma unroll
        for (int s = 4; s; s >>= 1) t += __shfl_xor_sync(0xffffffffu, t, s);
        if (tid == 0) red[0] = t;
    }
    __syncthreads();
    float r = rsqrtf(red[0] * (1.0f / (float)D) + 1e-6f);
    const float4* w4 = (const float4*)w;
    float4 wv = w4[tid];
    float4 out;
    out.x = v.x * r * wv.x; out.y = v.y * r * wv.y;
    out.z = v.z * r * wv.z; out.w = v.w * r * wv.w;
    ((float4*)(o + (size_t)row * D))[tid] = out;
}

// =============================================================================
// GEMM geometry (R7 proven config): CTA tile 64x128x16, 8 warps, warp 32x32.
// =============================================================================
#define BM 64
#define BN 128
#define BKT 16

// tf32 path (MoE, 1-term)
#define ASTR 20
#define BSTR 136
#define APLANE (BM*ASTR)   // 1280 words
#define BPLANE (BKT*BSTR)  // 2176 words

// bf16 path (attention GEMMs, 3-term split)
#define ASTRH 12
#define BSTRH 136
#define APLANEH (BM*ASTRH)       // 768 words
#define BPLANEH (8*BSTRH)        // 1088 words
#define HSTAGE (2*APLANEH + 2*BPLANEH)   // 3712 words

static __device__ __forceinline__ uint32_t f2tf(float x) {
    uint32_t r; asm("cvt.rna.tf32.f32 %0, %1;" : "=r"(r) : "f"(x)); return r;
}
static __device__ __forceinline__ uint32_t packbf2(float lo_k, float hi_k) {
    uint32_t r; asm("cvt.rn.bf16x2.f32 %0, %1, %2;" : "=r"(r) : "f"(hi_k), "f"(lo_k));
    return r;
}
static __device__ __forceinline__ void mma8(float* d, const uint32_t* a, const uint32_t* b) {
    asm volatile("mma.sync.aligned.m16n8k8.row.col.f32.tf32.tf32.f32 "
        "{%0,%1,%2,%3}, {%4,%5,%6,%7}, {%8,%9}, {%0,%1,%2,%3};\n"
        : "+f"(d[0]), "+f"(d[1]), "+f"(d[2]), "+f"(d[3])
        : "r"(a[0]), "r"(a[1]), "r"(a[2]), "r"(a[3]), "r"(b[0]), "r"(b[1]));
}
static __device__ __forceinline__ void mma16(float* d, const uint32_t* a, const uint32_t* b) {
    asm volatile("mma.sync.aligned.m16n8k16.row.col.f32.bf16.bf16.f32 "
        "{%0,%1,%2,%3}, {%4,%5,%6,%7}, {%8,%9}, {%0,%1,%2,%3};\n"
        : "+f"(d[0]), "+f"(d[1]), "+f"(d[2]), "+f"(d[3])
        : "r"(a[0]), "r"(a[1]), "r"(a[2]), "r"(a[3]), "r"(b[0]), "r"(b[1]));
}

// shared epilogue: bias [+resid][silu], write C
template<int XEPI>
static __device__ __forceinline__ void gemm_epilogue(
    float acc[2][4][4], const float* __restrict__ bias, const float* __restrict__ resid,
    float* __restrict__ C, int M, int Nld, int m0, int n0, int wm, int wn, int g, int tg)
{
    #pragma unroll
    for (int i = 0; i < 2; i++) {
        int rr0 = m0 + wm + i*16 + g;
        int rr1 = rr0 + 8;
        #pragma unroll
        for (int j = 0; j < 4; j++) {
            int c = n0 + wn + j*8 + tg*2;
            float b0v = bias[c], b1v = bias[c+1];
            if (rr0 < M) {
                float t0 = acc[i][j][0] + b0v;
                float t1 = acc[i][j][1] + b1v;
                if (XEPI == 1) {
                    t0 += resid[(size_t)rr0*Nld + c];
                    t1 += resid[(size_t)rr0*Nld + c + 1];
                }
                if (XEPI == 2) {
                    t0 = t0 / (1.f + expf(-t0));
                    t1 = t1 / (1.f + expf(-t1));
                }
                float2 o; o.x = t0; o.y = t1;
                *(float2*)&C[(size_t)rr0*Nld + c] = o;
            }
            if (rr1 < M) {
                float t0 = acc[i][j][2] + b0v;
                float t1 = acc[i][j][3] + b1v;
                if (XEPI == 1) {
                    t0 += resid[(size_t)rr1*Nld + c];
                    t1 += resid[(size_t)rr1*Nld + c + 1];
                }
                if (XEPI == 2) {
                    t0 = t0 / (1.f + expf(-t0));
                    t1 = t1 / (1.f + expf(-t1));
                }
                float2 o; o.x = t0; o.y = t1;
                *(float2*)&C[(size_t)rr1*Nld + c] = o;
            }
        }
    }
}

// =============================================================================
// bf16 3-term split GEMM core
// =============================================================================
static __device__ __forceinline__ void store_stage_bf16(
    uint32_t* base, float4 ra, float4 rb0v, float4 rb1v,
    int arow, int pa0, int pr, int bc)
{
    uint32_t p0 = packbf2(ra.x, ra.y);
    uint32_t p1 = packbf2(ra.z, ra.w);
    base[arow*ASTRH + pa0]     = p0;
    base[arow*ASTRH + pa0 + 1] = p1;
    float l0 = ra.x - __uint_as_float(p0 << 16);
    float l1 = ra.y - __uint_as_float(p0 & 0xffff0000u);
    float l2 = ra.z - __uint_as_float(p1 << 16);
    float l3 = ra.w - __uint_as_float(p1 & 0xffff0000u);
    base[APLANEH + arow*ASTRH + pa0]     = packbf2(l0, l1);
    base[APLANEH + arow*ASTRH + pa0 + 1] = packbf2(l2, l3);
    float b0a[4] = {rb0v.x, rb0v.y, rb0v.z, rb0v.w};
    float b1a[4] = {rb1v.x, rb1v.y, rb1v.z, rb1v.w};
    uint32_t hp[4], lp[4];
    #pragma unroll
    for (int j = 0; j < 4; j++) {
        uint32_t h = packbf2(b0a[j], b1a[j]);
        hp[j] = h;
        float ll0 = b0a[j] - __uint_as_float(h << 16);
        float ll1 = b1a[j] - __uint_as_float(h & 0xffff0000u);
        lp[j] = packbf2(ll0, ll1);
    }
    *(uint4*)&base[2*APLANEH + pr*BSTRH + bc] = make_uint4(hp[0], hp[1], hp[2], hp[3]);
    *(uint4*)&base[2*APLANEH + BPLANEH + pr*BSTRH + bc] = make_uint4(lp[0], lp[1], lp[2], lp[3]);
}

template<int XEPI>
static __device__ __forceinline__ void gemm_core_bf16(
    uint32_t* Hsm,
    const float* __restrict__ A, const float* __restrict__ B,
    const float* __restrict__ bias, const float* __restrict__ resid,
    float* __restrict__ C, int M, int Nld, int K, int m0, int n0)
{
    int tid = threadIdx.x;
    int arow = tid >> 2;
    int ac = (tid & 3) * 4;
    int pa0 = (tid & 3) * 2;
    int r0 = m0 + arow;
    bool v0 = r0 < M;
    const float* Ar0 = A + (size_t)(v0 ? r0 : 0) * K;
    int pr = tid >> 5;
    int bc = (tid & 31) * 4;
    const float* Bp0 = B + (size_t)(2*pr) * Nld + n0 + bc;
    const float* Bp1 = Bp0 + Nld;

    int lane = tid & 31, g = lane >> 2, tg = lane & 3;
    int wm = (tid >> 7) * 32;
    int wn = ((tid >> 5) & 3) * 32;

    float acc[2][4][4];
    #pragma unroll
    for (int i = 0; i < 2; i++)
        #pragma unroll
        for (int j = 0; j < 4; j++)
            #pragma unroll
            for (int c = 0; c < 4; c++) acc[i][j][c] = 0.f;

    float4 ra   = v0 ? *(const float4*)(Ar0 + ac) : make_float4(0.f,0.f,0.f,0.f);
    float4 rb0v = *(const float4*)(Bp0);
    float4 rb1v = *(const float4*)(Bp1);
    store_stage_bf16(Hsm, ra, rb0v, rb1v, arow, pa0, pr, bc);
    __syncthreads();
    int cur = 0;

    for (int k0 = 0; k0 < K; k0 += BKT) {
        int kn = k0 + BKT;
        bool more = kn < K;
        if (more) {
            ra   = v0 ? *(const float4*)(Ar0 + kn + ac) : make_float4(0.f,0.f,0.f,0.f);
            rb0v = *(const float4*)(Bp0 + (size_t)kn * Nld);
            rb1v = *(const float4*)(Bp1 + (size_t)kn * Nld);
        }
        const uint32_t* Ah = Hsm + cur * HSTAGE;
        const uint32_t* Al = Ah + APLANEH;
        const uint32_t* Bh = Ah + 2*APLANEH;
        const uint32_t* Bl = Bh + BPLANEH;

        uint32_t ah[2][4], al[2][4], bh[4][2], bl[4][2];
        #pragma unroll
        for (int i = 0; i < 2; i++) {
            int mb = wm + i*16 + g;
            ah[i][0] = Ah[mb*ASTRH + tg];       ah[i][1] = Ah[(mb+8)*ASTRH + tg];
            ah[i][2] = Ah[mb*ASTRH + tg+4];     ah[i][3] = Ah[(mb+8)*ASTRH + tg+4];
            al[i][0] = Al[mb*ASTRH + tg];       al[i][1] = Al[(mb+8)*ASTRH + tg];
            al[i][2] = Al[mb*ASTRH + tg+4];     al[i][3] = Al[(mb+8)*ASTRH + tg+4];
        }
        #pragma unroll
        for (int j = 0; j < 4; j++) {
            int nb = wn + j*8 + g;
            bh[j][0] = Bh[tg*BSTRH + nb];       bh[j][1] = Bh[(tg+4)*BSTRH + nb];
            bl[j][0] = Bl[tg*BSTRH + nb];       bl[j][1] = Bl[(tg+4)*BSTRH + nb];
        }
        #pragma unroll
        for (int i = 0; i < 2; i++)
            #pragma unroll
            for (int j = 0; j < 4; j++) mma16(acc[i][j], ah[i], bh[j]);
        #pragma unroll
        for (int i = 0; i < 2; i++)
            #pragma unroll
            for (int j = 0; j < 4; j++) mma16(acc[i][j], ah[i], bl[j]);
        #pragma unroll
        for (int i = 0; i < 2; i++)
            #pragma unroll
            for (int j = 0; j < 4; j++) mma16(acc[i][j], al[i], bh[j]);

        if (more) {
            store_stage_bf16(Hsm + (cur ^ 1) * HSTAGE, ra, rb0v, rb1v, arow, pa0, pr, bc);
            __syncthreads();
            cur ^= 1;
        }
    }
    gemm_epilogue<XEPI>(acc, bias, resid, C, M, Nld, m0, n0, wm, wn, g, tg);
}

// =============================================================================
// tf32 single-term GEMM core (MoE path)
// =============================================================================
#define STORE_TILE(stg) do { \
    uint32_t* Ab = Asm + (stg) * APLANE; \
    uint32_t* Bb = Bsm + (stg) * BPLANE; \
    float av[4] = {ra.x, ra.y, ra.z, ra.w}; \
    _Pragma("unroll") \
    for (int j = 0; j < 4; j++) Ab[arow*ASTR + ac + j] = f2tf(av[j]); \
    float bvv[8] = {rb0v.x, rb0v.y, rb0v.z, rb0v.w, rb1v.x, rb1v.y, rb1v.z, rb1v.w}; \
    _Pragma("unroll") \
    for (int j = 0; j < 8; j++) { \
        int row = (j < 4) ? brow : (brow + 8); \
        Bb[row*BSTR + bc + (j & 3)] = f2tf(bvv[j]); \
    } \
} while (0)

template<int XEPI, int XGATHER>
static __device__ __forceinline__ void gemm_core_tf32(
    uint32_t* Asm, uint32_t* Bsm,
    const float* __restrict__ A, const float* __restrict__ B,
    const float* __restrict__ bias, const float* __restrict__ resid,
    float* __restrict__ C, int M, int Nld, int K, int m0, int n0,
    const int* __restrict__ rowidx)
{
    int tid = threadIdx.x;
    int arow = tid >> 2;
    int ac = (tid & 3) * 4;
    int r0 = m0 + arow;
    bool v0 = r0 < M;
    int gr0 = v0 ? (XGATHER ? rowidx[r0] : r0) : 0;
    const float* Ar0 = A + (size_t)gr0 * K;
    int brow = tid >> 5;
    int bc = (tid & 31) * 4;
    const float* Bp0 = B + (size_t)brow * Nld + n0 + bc;
    const float* Bp1 = Bp0 + (size_t)8 * Nld;

    int lane = tid & 31, g = lane >> 2, tg = lane & 3;
    int wm = (tid >> 7) * 32;
    int wn = ((tid >> 5) & 3) * 32;

    float acc[2][4][4];
    #pragma unroll
    for (int i = 0; i < 2; i++)
        #pragma unroll
        for (int j = 0; j < 4; j++)
            #pragma unroll
            for (int c = 0; c < 4; c++) acc[i][j][c] = 0.f;

    float4 ra  = v0 ? *(const float4*)(Ar0 + ac) : make_float4(0.f,0.f,0.f,0.f);
    float4 rb0v = *(const float4*)(Bp0);
    float4 rb1v = *(const float4*)(Bp1);
    STORE_TILE(0);
    __syncthreads();
    int cur = 0;

    for (int k0 = 0; k0 < K; k0 += BKT) {
        int kn = k0 + BKT;
        bool more = kn < K;
        if (more) {
            ra  = v0 ? *(const float4*)(Ar0 + kn + ac) : make_float4(0.f,0.f,0.f,0.f);
            rb0v = *(const float4*)(Bp0 + (size_t)kn * Nld);
            rb1v = *(const float4*)(Bp1 + (size_t)kn * Nld);
        }
        const uint32_t* Ab = Asm + cur * APLANE;
        const uint32_t* Bb = Bsm + cur * BPLANE;
        #pragma unroll
        for (int ks = 0; ks < BKT; ks += 8) {
            uint32_t af[2][4], bf[4][2];
            #pragma unroll
            for (int i = 0; i < 2; i++) {
                int mb = wm + i*16 + g;
                af[i][0] = Ab[mb*ASTR + ks+tg];
                af[i][1] = Ab[(mb+8)*ASTR + ks+tg];
                af[i][2] = Ab[mb*ASTR + ks+tg+4];
                af[i][3] = Ab[(mb+8)*ASTR + ks+tg+4];
            }
            #pragma unroll
            for (int j = 0; j < 4; j++) {
                int nb = wn + j*8 + g;
                bf[j][0] = Bb[(ks+tg)*BSTR + nb];
                bf[j][1] = Bb[(ks+tg+4)*BSTR + nb];
            }
            #pragma unroll
            for (int i = 0; i < 2; i++)
                #pragma unroll
                for (int j = 0; j < 4; j++) mma8(acc[i][j], af[i], bf[j]);
        }
        if (more) {
            STORE_TILE(cur ^ 1);
            __syncthreads();
            cur ^= 1;
        }
    }
    gemm_epilogue<XEPI>(acc, bias, resid, C, M, Nld, m0, n0, wm, wn, g, tg);
}

// ---- fused QKV (bf16 3-term): grid (12, 32) ---------------------------------
__global__ void __launch_bounds__(256, 2) qkv_kernel(
    const float* __restrict__ h,
    const float* __restrict__ wq, const float* __restrict__ bq,
    const float* __restrict__ wk, const float* __restrict__ bk,
    const float* __restrict__ wv, const float* __restrict__ bv)
{
    __shared__ __align__(16) uint32_t Hsm[2*HSTAGE];
    int x = blockIdx.x, m0 = blockIdx.y * BM;
    if (x < 8)
        gemm_core_bf16<0>(Hsm, h, wq, bq, nullptr, g_q, S, 1024, 1024, m0, x*128);
    else if (x < 10)
        gemm_core_bf16<0>(Hsm, h, wk, bk, nullptr, g_k, S, 256, 1024, m0, (x-8)*128);
    else
        gemm_core_bf16<0>(Hsm, h, wv, bv, nullptr, g_v, S, 256, 1024, m0, (x-10)*128);
}

// ---- O-proj + residual (bf16 3-term): grid (8, 32) --------------------------
__global__ void __launch_bounds__(256, 2) oproj_kernel(
    const float* __restrict__ wo, const float* __restrict__ bo,
    const float* __restrict__ x)
{
    __shared__ __align__(16) uint32_t Hsm[2*HSTAGE];
    gemm_core_bf16<1>(Hsm, g_attn, wo, bo, x, g_x1, S, 1024, 1024,
                      blockIdx.y*BM, blockIdx.x*BN);
}

// ---- MoE expert GEMMs (1xTF32, grouped) -------------------------------------
__global__ void __launch_bounds__(256, 2) moe1_kernel(
    const float* __restrict__ h2, const float* __restrict__ w1,
    const float* __restrict__ b1)
{
    int e = blockIdx.z;
    int M = g_cnt[e];
    int m0 = blockIdx.y * BM;
    if (m0 >= M) return;
    int o = g_off[e];
    __shared__ uint32_t sA[2*APLANE];
    __shared__ uint32_t sB[2*BPLANE];
    gemm_core_tf32<2,1>(sA, sB, h2, w1 + (size_t)e*1024*512, b1 + (size_t)e*512,
                        nullptr, g_hmid + (size_t)o*512, M, 512, 1024,
                        m0, blockIdx.x*BN, g_atok + o);
}

__global__ void __launch_bounds__(256, 2) moe2_kernel(
    const float* __restrict__ w2, const float* __restrict__ b2)
{
    int e = blockIdx.z;
    int M = g_cnt[e];
    int m0 = blockIdx.y * BM;
    if (m0 >= M) return;
    int o = g_off[e];
    __shared__ uint32_t sA[2*APLANE];
    __shared__ uint32_t sB[2*BPLANE];
    gemm_core_tf32<0,0>(sA, sB, g_hmid + (size_t)o*512, w2 + (size_t)e*512*1024,
                        b2 + (size_t)e*1024, nullptr, g_y + (size_t)o*1024,
                        M, 1024, 512, m0, blockIdx.x*BN, nullptr);
}

// =============================================================================
// sliding-window attention: smem-staged K/V window, lane-parallel scores.
// block = 8 queries x 1 head; warp = 1 query; lane L owns keys jj=L and jj=32+L.
// =============================================================================
#define AROWS 72
#define ASTRIDE 132   // odd multiple of float4 (33) -> conflict-free LDS.128
#define ATTN_SMEM ((2*AROWS*ASTRIDE + 8*ASTRIDE) * 4)

__global__ void __launch_bounds__(256, 2) attn_kernel(const float* __restrict__ sinkp) {
    extern __shared__ float sm[];
    float* sK = sm;                        // [AROWS][ASTRIDE]
    float* sV = sm + AROWS*ASTRIDE;
    float* sQ = sm + 2*AROWS*ASTRIDE;      // [8][ASTRIDE]
    int tid = threadIdx.x, warp = tid >> 5, lane = tid & 31;
    int b = blockIdx.x, h = blockIdx.y, kvh = h >> 2;
    int i0 = b * 8;
    int jmin = (i0 >= (WS-1)) ? (i0 - (WS-1)) : 0;
    int nrows = (i0 + 8) - jmin;           // <= 71

    // stage K,V window (coalesced float4)
    for (int idx = tid; idx < nrows * 32; idx += 256) {
        int r = idx >> 5, c = idx & 31;
        const float* kp = g_k + (size_t)(jmin + r) * (NKV*HD) + kvh*HD + c*4;
        const float* vp = g_v + (size_t)(jmin + r) * (NKV*HD) + kvh*HD + c*4;
        *(float4*)(sK + r*ASTRIDE + c*4) = *(const float4*)kp;
        *(float4*)(sV + r*ASTRIDE + c*4) = *(const float4*)vp;
    }
    // stage Q rows
    for (int idx = tid; idx < 8 * 32; idx += 256) {
        int r = idx >> 5, c = idx & 31;
        *(float4*)(sQ + r*ASTRIDE + c*4) =
            *(const float4*)(g_q + (size_t)(i0 + r) * D + h*HD + c*4);
    }
    __syncthreads();

    int i = i0 + warp;
    int jstart = (i >= (WS-1)) ? (i - (WS-1)) : 0;
    int cnt = i - jstart + 1;
    int base = jstart - jmin;
    const float scale = 0.08838834764831845f;  // 1/sqrt(128)

    // scores: lane owns jj=lane and jj=32+lane
    float s0 = -1e30f, s1 = -1e30f;
    {
        bool u0 = lane < cnt, u1 = (32 + lane) < cnt;
        const float* q  = sQ + warp * ASTRIDE;
        const float* k0 = sK + (base + lane) * ASTRIDE;
        const float* k1 = sK + (base + 32 + lane) * ASTRIDE;
        float a0=0.f,a1=0.f,a2=0.f,a3=0.f, c0=0.f,c1=0.f,c2=0.f,c3=0.f;
        #pragma unroll 8
        for (int c4 = 0; c4 < 32; c4++) {
            float4 q4  = *(const float4*)(q  + c4*4);
            float4 k04 = *(const float4*)(k0 + c4*4);
            float4 k14 = *(const float4*)(k1 + c4*4);
            a0 += q4.x*k04.x; a1 += q4.y*k04.y; a2 += q4.z*k04.z; a3 += q4.w*k04.w;
            c0 += q4.x*k14.x; c1 += q4.y*k14.y; c2 += q4.z*k14.z; c3 += q4.w*k14.w;
        }
        if (u0) s0 = ((a0+a1) + (a2+a3)) * scale;
        if (u1) s1 = ((c0+c1) + (c2+c3)) * scale;
    }

    float sink = *sinkp;
    float m = fmaxf(s0, s1);
    #pragma unroll
    for (int s = 16; s; s >>= 1) m = fmaxf(m, __shfl_xor_sync(0xffffffffu, m, s));
    m = fmaxf(m, sink);
    float e0 = expf(s0 - m), e1 = expf(s1 - m);
    float dsum = e0 + e1;
    #pragma unroll
    for (int s = 16; s; s >>= 1) dsum += __shfl_xor_sync(0xffffffffu, dsum, s);
    dsum += expf(sink - m);
    float inv = 1.f / dsum;

    float o0 = 0.f, o1 = 0.f, o2 = 0.f, o3 = 0.f;
    for (int jj = 0; jj < cnt; ++jj) {
        float pv = (jj < 32) ? e0 : e1;
        float p = __shfl_sync(0xffffffffu, pv, jj & 31);
        const float* vr = sV + (base + jj) * ASTRIDE;
        o0 += p * vr[lane];      o1 += p * vr[lane + 32];
        o2 += p * vr[lane + 64]; o3 += p * vr[lane + 96];
    }
    float* op = g_attn + (size_t)i * D + h * HD;
    op[lane]      = o0 * inv; op[lane + 32] = o1 * inv;
    op[lane + 64] = o2 * inv; op[lane + 96] = o3 * inv;
}

// ---------------- router: 1 warp = 1 token ----------------------------------
__global__ void router_kernel(const float* __restrict__ rw, const float* __restrict__ rb) {
    int warp = threadIdx.x >> 5, lane = threadIdx.x & 31;
    int t = blockIdx.x * 8 + warp;
    float acc[NE];
    #pragma unroll
    for (int e = 0; e < NE; e++) acc[e] = 0.f;
    const float* xr = g_h2 + (size_t)t * D;
    for (int d = lane; d < D; d += 32) {
        float xv = xr[d];
        const float* rr = rw + d * NE;
        #pragma unroll
        for (int e = 0; e < NE; e++) acc[e] += xv * rr[e];
    }
    #pragma unroll
    for (int e = 0; e < NE; e++) {
        float a = acc[e];
        #pragma unroll
        for (int s = 16; s; s >>= 1) a += __shfl_xor_sync(0xffffffffu, a, s);
        acc[e] = a;
    }
    if (lane == 0) {
        float logit[NE]; float m = -1e30f;
        #pragma unroll
        for (int e = 0; e < NE; e++) { logit[e] = (acc[e] + rb[e]) * 10.f; m = fmaxf(m, logit[e]); }
        float pe[NE]; float ssum = 0.f;
        #pragma unroll
        for (int e = 0; e < NE; e++) { pe[e] = expf(logit[e] - m); ssum += pe[e]; }
        float invs = 1.f / ssum;
        #pragma unroll
        for (int e = 0; e < NE; e++) g_probs[t * NE + e] = pe[e] * invs;
        int i0 = 0; float v0 = logit[0];
        #pragma unroll
        for (int e = 1; e < NE; e++) if (logit[e] > v0) { v0 = logit[e]; i0 = e; }
        int i1 = -1; float v1 = -1e30f;
        #pragma unroll
        for (int e = 0; e < NE; e++) if (e != i0 && logit[e] > v1) { v1 = logit[e]; i1 = e; }
        float ex = expf(v1 - v0);
        float w0 = 1.f / (1.f + ex);
        g_topi[t*2] = i0; g_topi[t*2+1] = i1;
        g_topw[t*2] = w0; g_topw[t*2+1] = 1.f - w0;
        atomicAdd(&g_cnt[i0], 1); atomicAdd(&g_cnt[i1], 1);
    }
}

__global__ void zero_kernel() {
    int t = threadIdx.x;
    if (t < NE) { g_cnt[t] = 0; g_cur[t] = 0; }
}

__global__ void offsets_kernel() {
    if (threadIdx.x == 0) {
        int s = 0;
        for (int e = 0; e < NE; e++) { g_off[e] = s; s += g_cnt[e]; }
    }
}

__global__ void place_kernel() {
    int t = blockIdx.x * blockDim.x + threadIdx.x;
    if (t >= S) return;
    #pragma unroll
    for (int k2 = 0; k2 < 2; k2++) {
        int e = g_topi[t*2 + k2];
        int slot = g_off[e] + atomicAdd(&g_cur[e], 1);
        g_atok[slot] = t;
        g_aw[slot] = g_topw[t*2 + k2];
        g_tslot[t*2 + k2] = slot;
    }
}

__global__ void colsum_kernel() {
    int e = blockIdx.x; int tid = threadIdx.x;
    float s = 0.f;
    for (int t = tid; t < S; t += 256) s += g_probs[t * NE + e];
    __shared__ float red[256];
    red[tid] = s; __syncthreads();
    for (int st = 128; st; st >>= 1) { if (tid < st) red[tid] += red[tid + st]; __syncthreads(); }
    if (tid == 0) g_colsum[e] = red[0];
}

__global__ void combine_kernel(float* __restrict__ out) {
    int t = blockIdx.x; int c = threadIdx.x;
    int s0 = g_tslot[t*2], s1 = g_tslot[t*2+1];
    float w0 = g_aw[s0], w1 = g_aw[s1];
    const float4* x14 = (const float4*)(g_x1 + (size_t)t * D);
    const float4* y0  = (const float4*)(g_y + (size_t)s0 * D);
    const float4* y1  = (const float4*)(g_y + (size_t)s1 * D);
    float4 a = x14[c], b = y0[c], d2 = y1[c];
    float4 o;
    o.x = a.x + w0*b.x + w1*d2.x; o.y = a.y + w0*b.y + w1*d2.y;
    o.z = a.z + w0*b.z + w1*d2.z; o.w = a.w + w0*b.w + w1*d2.w;
    ((float4*)out)[(size_t)t * (D/4) + c] = o;
}

__global__ void aux_kernel(float* __restrict__ out, int out_size) {
    int tid = threadIdx.x;
    float v = (tid < NE) ? g_colsum[tid] * g_colsum[tid] : 0.f;
    #pragma unroll
    for (int s = 16; s; s >>= 1) v += __shfl_xor_sync(0xffffffffu, v, s);
    if (tid == 0) {
        float aux = v * (1.0f / (float)NE) * 1e-5f;
        for (int idx = S * D; idx < out_size; ++idx) out[idx] = aux;
    }
}

// ---------------- launch -----------------------------------------------------
extern "C" void kernel_launch(void* const* d_in, const int* in_sizes, int n_in,
                              void* d_out, int out_size) {
    const float* x    = (const float*)d_in[0];
    const float* n1w  = (const float*)d_in[1];
    const float* wq   = (const float*)d_in[2];
    const float* bq   = (const float*)d_in[3];
    const float* wk   = (const float*)d_in[4];
    const float* bk   = (const float*)d_in[5];
    const float* wv   = (const float*)d_in[6];
    const float* bv   = (const float*)d_in[7];
    const float* wo   = (const float*)d_in[8];
    const float* bo   = (const float*)d_in[9];
    const float* sink = (const float*)d_in[10];
    const float* n2w  = (const float*)d_in[11];
    const float* rw   = (const float*)d_in[12];
    const float* rb   = (const float*)d_in[13];
    const float* w1   = (const float*)d_in[14];
    const float* b1   = (const float*)d_in[15];
    const float* w2   = (const float*)d_in[16];
    const float* b2   = (const float*)d_in[17];
    float* out = (float*)d_out;

    void* p;
    cudaGetSymbolAddress(&p, g_h);    float* hB    = (float*)p;
    cudaGetSymbolAddress(&p, g_x1);   float* x1B   = (float*)p;
    cudaGetSymbolAddress(&p, g_h2);   float* h2B   = (float*)p;

    cudaFuncSetAttribute(attn_kernel, cudaFuncAttributeMaxDynamicSharedMemorySize, ATTN_SMEM);

    // 1) RMSNorm1
    rmsnorm_kernel<<<S, 256>>>(x, n1w, hB);

    // 2) fused QKV projections (bf16x2 3-term tensor cores)
    qkv_kernel<<<dim3(12, 32), 256>>>(hB, wq, bq, wk, bk, wv, bv);

    // 3) sliding-window attention (smem-staged window)
    attn_kernel<<<dim3(S/8, NH), 256, ATTN_SMEM>>>(sink);

    // 4) O-proj + residual (bf16x2 3-term)
    oproj_kernel<<<dim3(8, 32), 256>>>(wo, bo, x);

    // 5) RMSNorm2
    rmsnorm_kernel<<<S, 256>>>(x1B, n2w, h2B);

    // 6) router + grouping
    zero_kernel<<<1, 32>>>();
    router_kernel<<<S/8, 256>>>(rw, rb);
    offsets_kernel<<<1, 32>>>();
    place_kernel<<<8, 256>>>();
    colsum_kernel<<<NE, 256>>>();

    // 7) grouped MoE GEMMs (top-2 only, 1xTF32)
    moe1_kernel<<<dim3(4, 32, NE), 256>>>(h2B, w1, b1);
    moe2_kernel<<<dim3(8, 32, NE), 256>>>(w2, b2);

    // 8) combine + residual, aux loss
    combine_kernel<<<S, 256>>>(out);
    aux_kernel<<<1, 32>>>(out, out_size);
}

// round 12
// speedup vs baseline: 1.0845x; 1.0324x over previous
#include <cuda_runtime.h>
#include <math.h>
#include <stdint.h>

#define S 2048
#define D 1024
#define NH 8
#define NKV 2
#define HD 128
#define WS 64
#define NE 16
#define HDIM 512
#define NA (S*2)

// ---------------- scratch (static device globals; no allocation) ------------
__device__ float g_h[S*D];
__device__ float g_q[S*D];
__device__ float g_k[S*NKV*HD];
__device__ float g_v[S*NKV*HD];
__device__ float g_attn[S*D];
__device__ float g_x1[S*D];
__device__ float g_h2[S*D];
__device__ float g_probs[S*NE];
__device__ float g_topw[S*2];
__device__ int   g_topi[S*2];
__device__ int   g_cnt[NE];
__device__ int   g_off[NE];
__device__ int   g_cur[NE];
__device__ int   g_atok[NA];
__device__ float g_aw[NA];
__device__ int   g_tslot[S*2];
__device__ float g_hmid[NA*HDIM];
__device__ float g_y[NA*D];
__device__ float g_colsum[NE];

// ---------------- RMSNorm ----------------------------------------------------
__global__ void rmsnorm_kernel(const float* __restrict__ x,
                               const float* __restrict__ w,
                               float* __restrict__ o) {
    int row = blockIdx.x;
    int tid = threadIdx.x;
    const float4* x4 = (const float4*)(x + (size_t)row * D);
    float4 v = x4[tid];
    float ss = v.x*v.x + v.y*v.y + v.z*v.z + v.w*v.w;
    __shared__ float red[8];
    #pragma unroll
    for (int s = 16; s; s >>= 1) ss += __shfl_xor_sync(0xffffffffu, ss, s);
    if ((tid & 31) == 0) red[tid >> 5] = ss;
    __syncthreads();
    if (tid < 32) {
        float t = (tid < 8) ? red[tid] : 0.f;
        #pragma unroll
        for (int s = 4; s; s >>= 1) t += __shfl_xor_sync(0xffffffffu, t, s);
        if (tid == 0) red[0] = t;
    }
    __syncthreads();
    float r = rsqrtf(red[0] * (1.0f / (float)D) + 1e-6f);
    const float4* w4 = (const float4*)w;
    float4 wv = w4[tid];
    float4 out;
    out.x = v.x * r * wv.x; out.y = v.y * r * wv.y;
    out.z = v.z * r * wv.z; out.w = v.w * r * wv.w;
    ((float4*)(o + (size_t)row * D))[tid] = out;
}

// =============================================================================
// GEMM geometry: CTA tile 64x128x16, 8 warps, warp 32x32 (R7 proven config).
// All GEMMs: bf16 3-term split (hi*hi + hi*lo + lo*hi), ~fp32 accuracy,
// 12 m16n8k16 per warp per k16 (vs 16 m16n8k8 for 1xtf32 -> 25% fewer instr).
// =============================================================================
#define BM 64
#define BN 128
#define BKT 16

#define ASTRH 12
#define BSTRH 136
#define APLANEH (BM*ASTRH)       // 768 words
#define BPLANEH (8*BSTRH)        // 1088 words
#define HSTAGE (2*APLANEH + 2*BPLANEH)   // 3712 words

static __device__ __forceinline__ uint32_t packbf2(float lo_k, float hi_k) {
    uint32_t r; asm("cvt.rn.bf16x2.f32 %0, %1, %2;" : "=r"(r) : "f"(hi_k), "f"(lo_k));
    return r;
}
static __device__ __forceinline__ void mma16(float* d, const uint32_t* a, const uint32_t* b) {
    asm volatile("mma.sync.aligned.m16n8k16.row.col.f32.bf16.bf16.f32 "
        "{%0,%1,%2,%3}, {%4,%5,%6,%7}, {%8,%9}, {%0,%1,%2,%3};\n"
        : "+f"(d[0]), "+f"(d[1]), "+f"(d[2]), "+f"(d[3])
        : "r"(a[0]), "r"(a[1]), "r"(a[2]), "r"(a[3]), "r"(b[0]), "r"(b[1]));
}

// shared epilogue: bias [+resid][silu], write C
template<int XEPI>
static __device__ __forceinline__ void gemm_epilogue(
    float acc[2][4][4], const float* __restrict__ bias, const float* __restrict__ resid,
    float* __restrict__ C, int M, int Nld, int m0, int n0, int wm, int wn, int g, int tg)
{
    #pragma unroll
    for (int i = 0; i < 2; i++) {
        int rr0 = m0 + wm + i*16 + g;
        int rr1 = rr0 + 8;
        #pragma unroll
        for (int j = 0; j < 4; j++) {
            int c = n0 + wn + j*8 + tg*2;
            float b0v = bias[c], b1v = bias[c+1];
            if (rr0 < M) {
                float t0 = acc[i][j][0] + b0v;
                float t1 = acc[i][j][1] + b1v;
                if (XEPI == 1) {
                    t0 += resid[(size_t)rr0*Nld + c];
                    t1 += resid[(size_t)rr0*Nld + c + 1];
                }
                if (XEPI == 2) {
                    t0 = t0 / (1.f + expf(-t0));
                    t1 = t1 / (1.f + expf(-t1));
                }
                float2 o; o.x = t0; o.y = t1;
                *(float2*)&C[(size_t)rr0*Nld + c] = o;
            }
            if (rr1 < M) {
                float t0 = acc[i][j][2] + b0v;
                float t1 = acc[i][j][3] + b1v;
                if (XEPI == 1) {
                    t0 += resid[(size_t)rr1*Nld + c];
                    t1 += resid[(size_t)rr1*Nld + c + 1];
                }
                if (XEPI == 2) {
                    t0 = t0 / (1.f + expf(-t0));
                    t1 = t1 / (1.f + expf(-t1));
                }
                float2 o; o.x = t0; o.y = t1;
                *(float2*)&C[(size_t)rr1*Nld + c] = o;
            }
        }
    }
}

// =============================================================================
// bf16 3-term split GEMM core (all GEMMs)
// =============================================================================
static __device__ __forceinline__ void store_stage_bf16(
    uint32_t* base, float4 ra, float4 rb0v, float4 rb1v,
    int arow, int pa0, int pr, int bc)
{
    uint32_t p0 = packbf2(ra.x, ra.y);
    uint32_t p1 = packbf2(ra.z, ra.w);
    base[arow*ASTRH + pa0]     = p0;
    base[arow*ASTRH + pa0 + 1] = p1;
    float l0 = ra.x - __uint_as_float(p0 << 16);
    float l1 = ra.y - __uint_as_float(p0 & 0xffff0000u);
    float l2 = ra.z - __uint_as_float(p1 << 16);
    float l3 = ra.w - __uint_as_float(p1 & 0xffff0000u);
    base[APLANEH + arow*ASTRH + pa0]     = packbf2(l0, l1);
    base[APLANEH + arow*ASTRH + pa0 + 1] = packbf2(l2, l3);
    float b0a[4] = {rb0v.x, rb0v.y, rb0v.z, rb0v.w};
    float b1a[4] = {rb1v.x, rb1v.y, rb1v.z, rb1v.w};
    uint32_t hp[4], lp[4];
    #pragma unroll
    for (int j = 0; j < 4; j++) {
        uint32_t h = packbf2(b0a[j], b1a[j]);
        hp[j] = h;
        float ll0 = b0a[j] - __uint_as_float(h << 16);
        float ll1 = b1a[j] - __uint_as_float(h & 0xffff0000u);
        lp[j] = packbf2(ll0, ll1);
    }
    *(uint4*)&base[2*APLANEH + pr*BSTRH + bc] = make_uint4(hp[0], hp[1], hp[2], hp[3]);
    *(uint4*)&base[2*APLANEH + BPLANEH + pr*BSTRH + bc] = make_uint4(lp[0], lp[1], lp[2], lp[3]);
}

template<int XEPI, int XGATHER>
static __device__ __forceinline__ void gemm_core_bf16(
    uint32_t* Hsm,
    const float* __restrict__ A, const float* __restrict__ B,
    const float* __restrict__ bias, const float* __restrict__ resid,
    float* __restrict__ C, int M, int Nld, int K, int m0, int n0,
    const int* __restrict__ rowidx)
{
    int tid = threadIdx.x;
    int arow = tid >> 2;
    int ac = (tid & 3) * 4;
    int pa0 = (tid & 3) * 2;
    int r0 = m0 + arow;
    bool v0 = r0 < M;
    int gr0 = v0 ? (XGATHER ? rowidx[r0] : r0) : 0;
    const float* Ar0 = A + (size_t)gr0 * K;
    int pr = tid >> 5;
    int bc = (tid & 31) * 4;
    const float* Bp0 = B + (size_t)(2*pr) * Nld + n0 + bc;
    const float* Bp1 = Bp0 + Nld;

    int lane = tid & 31, g = lane >> 2, tg = lane & 3;
    int wm = (tid >> 7) * 32;
    int wn = ((tid >> 5) & 3) * 32;

    float acc[2][4][4];
    #pragma unroll
    for (int i = 0; i < 2; i++)
        #pragma unroll
        for (int j = 0; j < 4; j++)
            #pragma unroll
            for (int c = 0; c < 4; c++) acc[i][j][c] = 0.f;

    float4 ra   = v0 ? *(const float4*)(Ar0 + ac) : make_float4(0.f,0.f,0.f,0.f);
    float4 rb0v = *(const float4*)(Bp0);
    float4 rb1v = *(const float4*)(Bp1);
    store_stage_bf16(Hsm, ra, rb0v, rb1v, arow, pa0, pr, bc);
    __syncthreads();
    int cur = 0;

    for (int k0 = 0; k0 < K; k0 += BKT) {
        int kn = k0 + BKT;
        bool more = kn < K;
        if (more) {
            ra   = v0 ? *(const float4*)(Ar0 + kn + ac) : make_float4(0.f,0.f,0.f,0.f);
            rb0v = *(const float4*)(Bp0 + (size_t)kn * Nld);
            rb1v = *(const float4*)(Bp1 + (size_t)kn * Nld);
        }
        const uint32_t* Ah = Hsm + cur * HSTAGE;
        const uint32_t* Al = Ah + APLANEH;
        const uint32_t* Bh = Ah + 2*APLANEH;
        const uint32_t* Bl = Bh + BPLANEH;

        uint32_t ah[2][4], al[2][4], bh[4][2], bl[4][2];
        #pragma unroll
        for (int i = 0; i < 2; i++) {
            int mb = wm + i*16 + g;
            ah[i][0] = Ah[mb*ASTRH + tg];       ah[i][1] = Ah[(mb+8)*ASTRH + tg];
            ah[i][2] = Ah[mb*ASTRH + tg+4];     ah[i][3] = Ah[(mb+8)*ASTRH + tg+4];
            al[i][0] = Al[mb*ASTRH + tg];       al[i][1] = Al[(mb+8)*ASTRH + tg];
            al[i][2] = Al[mb*ASTRH + tg+4];     al[i][3] = Al[(mb+8)*ASTRH + tg+4];
        }
        #pragma unroll
        for (int j = 0; j < 4; j++) {
            int nb = wn + j*8 + g;
            bh[j][0] = Bh[tg*BSTRH + nb];       bh[j][1] = Bh[(tg+4)*BSTRH + nb];
            bl[j][0] = Bl[tg*BSTRH + nb];       bl[j][1] = Bl[(tg+4)*BSTRH + nb];
        }
        #pragma unroll
        for (int i = 0; i < 2; i++)
            #pragma unroll
            for (int j = 0; j < 4; j++) mma16(acc[i][j], ah[i], bh[j]);
        #pragma unroll
        for (int i = 0; i < 2; i++)
            #pragma unroll
            for (int j = 0; j < 4; j++) mma16(acc[i][j], ah[i], bl[j]);
        #pragma unroll
        for (int i = 0; i < 2; i++)
            #pragma unroll
            for (int j = 0; j < 4; j++) mma16(acc[i][j], al[i], bh[j]);

        if (more) {
            store_stage_bf16(Hsm + (cur ^ 1) * HSTAGE, ra, rb0v, rb1v, arow, pa0, pr, bc);
            __syncthreads();
            cur ^= 1;
        }
    }
    gemm_epilogue<XEPI>(acc, bias, resid, C, M, Nld, m0, n0, wm, wn, g, tg);
}

// ---- fused QKV: grid (12, 32) ------------------------------------------------
__global__ void __launch_bounds__(256, 2) qkv_kernel(
    const float* __restrict__ h,
    const float* __restrict__ wq, const float* __restrict__ bq,
    const float* __restrict__ wk, const float* __restrict__ bk,
    const float* __restrict__ wv, const float* __restrict__ bv)
{
    __shared__ __align__(16) uint32_t Hsm[2*HSTAGE];
    int x = blockIdx.x, m0 = blockIdx.y * BM;
    if (x < 8)
        gemm_core_bf16<0,0>(Hsm, h, wq, bq, nullptr, g_q, S, 1024, 1024, m0, x*128, nullptr);
    else if (x < 10)
        gemm_core_bf16<0,0>(Hsm, h, wk, bk, nullptr, g_k, S, 256, 1024, m0, (x-8)*128, nullptr);
    else
        gemm_core_bf16<0,0>(Hsm, h, wv, bv, nullptr, g_v, S, 256, 1024, m0, (x-10)*128, nullptr);
}

// ---- O-proj + residual: grid (8, 32) -----------------------------------------
__global__ void __launch_bounds__(256, 2) oproj_kernel(
    const float* __restrict__ wo, const float* __restrict__ bo,
    const float* __restrict__ x)
{
    __shared__ __align__(16) uint32_t Hsm[2*HSTAGE];
    gemm_core_bf16<1,0>(Hsm, g_attn, wo, bo, x, g_x1, S, 1024, 1024,
                        blockIdx.y*BM, blockIdx.x*BN, nullptr);
}

// ---- MoE expert GEMMs (bf16 3-term, grouped) ----------------------------------
__global__ void __launch_bounds__(256, 2) moe1_kernel(
    const float* __restrict__ h2, const float* __restrict__ w1,
    const float* __restrict__ b1)
{
    int e = blockIdx.z;
    int M = g_cnt[e];
    int m0 = blockIdx.y * BM;
    if (m0 >= M) return;
    int o = g_off[e];
    __shared__ __align__(16) uint32_t Hsm[2*HSTAGE];
    gemm_core_bf16<2,1>(Hsm, h2, w1 + (size_t)e*1024*512, b1 + (size_t)e*512,
                        nullptr, g_hmid + (size_t)o*512, M, 512, 1024,
                        m0, blockIdx.x*BN, g_atok + o);
}

__global__ void __launch_bounds__(256, 2) moe2_kernel(
    const float* __restrict__ w2, const float* __restrict__ b2)
{
    int e = blockIdx.z;
    int M = g_cnt[e];
    int m0 = blockIdx.y * BM;
    if (m0 >= M) return;
    int o = g_off[e];
    __shared__ __align__(16) uint32_t Hsm[2*HSTAGE];
    gemm_core_bf16<0,0>(Hsm, g_hmid + (size_t)o*512, w2 + (size_t)e*512*1024,
                        b2 + (size_t)e*1024, nullptr, g_y + (size_t)o*1024,
                        M, 1024, 512, m0, blockIdx.x*BN, nullptr);
}

// =============================================================================
// sliding-window attention: smem-staged K/V window, lane-parallel scores.
// =============================================================================
#define AROWS 72
#define ASTRIDE 132
#define ATTN_SMEM ((2*AROWS*ASTRIDE + 8*ASTRIDE) * 4)

__global__ void __launch_bounds__(256, 2) attn_kernel(const float* __restrict__ sinkp) {
    extern __shared__ float sm[];
    float* sK = sm;
    float* sV = sm + AROWS*ASTRIDE;
    float* sQ = sm + 2*AROWS*ASTRIDE;
    int tid = threadIdx.x, warp = tid >> 5, lane = tid & 31;
    int b = blockIdx.x, h = blockIdx.y, kvh = h >> 2;
    int i0 = b * 8;
    int jmin = (i0 >= (WS-1)) ? (i0 - (WS-1)) : 0;
    int nrows = (i0 + 8) - jmin;

    for (int idx = tid; idx < nrows * 32; idx += 256) {
        int r = idx >> 5, c = idx & 31;
        const float* kp = g_k + (size_t)(jmin + r) * (NKV*HD) + kvh*HD + c*4;
        const float* vp = g_v + (size_t)(jmin + r) * (NKV*HD) + kvh*HD + c*4;
        *(float4*)(sK + r*ASTRIDE + c*4) = *(const float4*)kp;
        *(float4*)(sV + r*ASTRIDE + c*4) = *(const float4*)vp;
    }
    for (int idx = tid; idx < 8 * 32; idx += 256) {
        int r = idx >> 5, c = idx & 31;
        *(float4*)(sQ + r*ASTRIDE + c*4) =
            *(const float4*)(g_q + (size_t)(i0 + r) * D + h*HD + c*4);
    }
    __syncthreads();

    int i = i0 + warp;
    int jstart = (i >= (WS-1)) ? (i - (WS-1)) : 0;
    int cnt = i - jstart + 1;
    int base = jstart - jmin;
    const float scale = 0.08838834764831845f;

    float s0 = -1e30f, s1 = -1e30f;
    {
        bool u0 = lane < cnt, u1 = (32 + lane) < cnt;
        const float* q  = sQ + warp * ASTRIDE;
        const float* k0 = sK + (base + lane) * ASTRIDE;
        const float* k1 = sK + (base + 32 + lane) * ASTRIDE;
        float a0=0.f,a1=0.f,a2=0.f,a3=0.f, c0=0.f,c1=0.f,c2=0.f,c3=0.f;
        #pragma unroll 8
        for (int c4 = 0; c4 < 32; c4++) {
            float4 q4  = *(const float4*)(q  + c4*4);
            float4 k04 = *(const float4*)(k0 + c4*4);
            float4 k14 = *(const float4*)(k1 + c4*4);
            a0 += q4.x*k04.x; a1 += q4.y*k04.y; a2 += q4.z*k04.z; a3 += q4.w*k04.w;
            c0 += q4.x*k14.x; c1 += q4.y*k14.y; c2 += q4.z*k14.z; c3 += q4.w*k14.w;
        }
        if (u0) s0 = ((a0+a1) + (a2+a3)) * scale;
        if (u1) s1 = ((c0+c1) + (c2+c3)) * scale;
    }

    float sink = *sinkp;
    float m = fmaxf(s0, s1);
    #pragma unroll
    for (int s = 16; s; s >>= 1) m = fmaxf(m, __shfl_xor_sync(0xffffffffu, m, s));
    m = fmaxf(m, sink);
    float e0 = expf(s0 - m), e1 = expf(s1 - m);
    float dsum = e0 + e1;
    #pragma unroll
    for (int s = 16; s; s >>= 1) dsum += __shfl_xor_sync(0xffffffffu, dsum, s);
    dsum += expf(sink - m);
    float inv = 1.f / dsum;

    float o0 = 0.f, o1 = 0.f, o2 = 0.f, o3 = 0.f;
    for (int jj = 0; jj < cnt; ++jj) {
        float pv = (jj < 32) ? e0 : e1;
        float p = __shfl_sync(0xffffffffu, pv, jj & 31);
        const float* vr = sV + (base + jj) * ASTRIDE;
        o0 += p * vr[lane];      o1 += p * vr[lane + 32];
        o2 += p * vr[lane + 64]; o3 += p * vr[lane + 96];
    }
    float* op = g_attn + (size_t)i * D + h * HD;
    op[lane]      = o0 * inv; op[lane + 32] = o1 * inv;
    op[lane + 64] = o2 * inv; op[lane + 96] = o3 * inv;
}

// ---------------- router: 1 warp = 1 token ----------------------------------
__global__ void router_kernel(const float* __restrict__ rw, const float* __restrict__ rb) {
    int warp = threadIdx.x >> 5, lane = threadIdx.x & 31;
    int t = blockIdx.x * 8 + warp;
    float acc[NE];
    #pragma unroll
    for (int e = 0; e < NE; e++) acc[e] = 0.f;
    const float* xr = g_h2 + (size_t)t * D;
    for (int d = lane; d < D; d += 32) {
        float xv = xr[d];
        const float* rr = rw + d * NE;
        #pragma unroll
        for (int e = 0; e < NE; e++) acc[e] += xv * rr[e];
    }
    #pragma unroll
    for (int e = 0; e < NE; e++) {
        float a = acc[e];
        #pragma unroll
        for (int s = 16; s; s >>= 1) a += __shfl_xor_sync(0xffffffffu, a, s);
        acc[e] = a;
    }
    if (lane == 0) {
        float logit[NE]; float m = -1e30f;
        #pragma unroll
        for (int e = 0; e < NE; e++) { logit[e] = (acc[e] + rb[e]) * 10.f; m = fmaxf(m, logit[e]); }
        float pe[NE]; float ssum = 0.f;
        #pragma unroll
        for (int e = 0; e < NE; e++) { pe[e] = expf(logit[e] - m); ssum += pe[e]; }
        float invs = 1.f / ssum;
        #pragma unroll
        for (int e = 0; e < NE; e++) g_probs[t * NE + e] = pe[e] * invs;
        int i0 = 0; float v0 = logit[0];
        #pragma unroll
        for (int e = 1; e < NE; e++) if (logit[e] > v0) { v0 = logit[e]; i0 = e; }
        int i1 = -1; float v1 = -1e30f;
        #pragma unroll
        for (int e = 0; e < NE; e++) if (e != i0 && logit[e] > v1) { v1 = logit[e]; i1 = e; }
        float ex = expf(v1 - v0);
        float w0 = 1.f / (1.f + ex);
        g_topi[t*2] = i0; g_topi[t*2+1] = i1;
        g_topw[t*2] = w0; g_topw[t*2+1] = 1.f - w0;
        atomicAdd(&g_cnt[i0], 1); atomicAdd(&g_cnt[i1], 1);
    }
}

__global__ void zero_kernel() {
    int t = threadIdx.x;
    if (t < NE) { g_cnt[t] = 0; g_cur[t] = 0; }
}

// offsets + place merged: one block, 1024 threads, 2 tokens each
__global__ void place_kernel() {
    if (threadIdx.x == 0) {
        int s = 0;
        for (int e = 0; e < NE; e++) { g_off[e] = s; s += g_cnt[e]; }
    }
    __syncthreads();
    #pragma unroll
    for (int half = 0; half < 2; half++) {
        int t = threadIdx.x + half * 1024;
        #pragma unroll
        for (int k2 = 0; k2 < 2; k2++) {
            int e = g_topi[t*2 + k2];
            int slot = g_off[e] + atomicAdd(&g_cur[e], 1);
            g_atok[slot] = t;
            g_aw[slot] = g_topw[t*2 + k2];
            g_tslot[t*2 + k2] = slot;
        }
    }
}

__global__ void colsum_kernel() {
    int e = blockIdx.x; int tid = threadIdx.x;
    float s = 0.f;
    for (int t = tid; t < S; t += 256) s += g_probs[t * NE + e];
    __shared__ float red[256];
    red[tid] = s; __syncthreads();
    for (int st = 128; st; st >>= 1) { if (tid < st) red[tid] += red[tid + st]; __syncthreads(); }
    if (tid == 0) g_colsum[e] = red[0];
}

__global__ void combine_kernel(float* __restrict__ out) {
    int t = blockIdx.x; int c = threadIdx.x;
    int s0 = g_tslot[t*2], s1 = g_tslot[t*2+1];
    float w0 = g_aw[s0], w1 = g_aw[s1];
    const float4* x14 = (const float4*)(g_x1 + (size_t)t * D);
    const float4* y0  = (const float4*)(g_y + (size_t)s0 * D);
    const float4* y1  = (const float4*)(g_y + (size_t)s1 * D);
    float4 a = x14[c], b = y0[c], d2 = y1[c];
    float4 o;
    o.x = a.x + w0*b.x + w1*d2.x; o.y = a.y + w0*b.y + w1*d2.y;
    o.z = a.z + w0*b.z + w1*d2.z; o.w = a.w + w0*b.w + w1*d2.w;
    ((float4*)out)[(size_t)t * (D/4) + c] = o;
}

__global__ void aux_kernel(float* __restrict__ out, int out_size) {
    int tid = threadIdx.x;
    float v = (tid < NE) ? g_colsum[tid] * g_colsum[tid] : 0.f;
    #pragma unroll
    for (int s = 16; s; s >>= 1) v += __shfl_xor_sync(0xffffffffu, v, s);
    if (tid == 0) {
        float aux = v * (1.0f / (float)NE) * 1e-5f;
        for (int idx = S * D; idx < out_size; ++idx) out[idx] = aux;
    }
}

// ---------------- launch -----------------------------------------------------
extern "C" void kernel_launch(void* const* d_in, const int* in_sizes, int n_in,
                              void* d_out, int out_size) {
    const float* x    = (const float*)d_in[0];
    const float* n1w  = (const float*)d_in[1];
    const float* wq   = (const float*)d_in[2];
    const float* bq   = (const float*)d_in[3];
    const float* wk   = (const float*)d_in[4];
    const float* bk   = (const float*)d_in[5];
    const float* wv   = (const float*)d_in[6];
    const float* bv   = (const float*)d_in[7];
    const float* wo   = (const float*)d_in[8];
    const float* bo   = (const float*)d_in[9];
    const float* sink = (const float*)d_in[10];
    const float* n2w  = (const float*)d_in[11];
    const float* rw   = (const float*)d_in[12];
    const float* rb   = (const float*)d_in[13];
    const float* w1   = (const float*)d_in[14];
    const float* b1   = (const float*)d_in[15];
    const float* w2   = (const float*)d_in[16];
    const float* b2   = (const float*)d_in[17];
    float* out = (float*)d_out;

    void* p;
    cudaGetSymbolAddress(&p, g_h);    float* hB    = (float*)p;
    cudaGetSymbolAddress(&p, g_x1);   float* x1B   = (float*)p;
    cudaGetSymbolAddress(&p, g_h2);   float* h2B   = (float*)p;

    cudaFuncSetAttribute(attn_kernel, cudaFuncAttributeMaxDynamicSharedMemorySize, ATTN_SMEM);

    // 1) RMSNorm1
    rmsnorm_kernel<<<S, 256>>>(x, n1w, hB);

    // 2) fused QKV projections (bf16 3-term tensor cores)
    qkv_kernel<<<dim3(12, 32), 256>>>(hB, wq, bq, wk, bk, wv, bv);

    // 3) sliding-window attention (smem-staged window)
    attn_kernel<<<dim3(S/8, NH), 256, ATTN_SMEM>>>(sink);

    // 4) O-proj + residual
    oproj_kernel<<<dim3(8, 32), 256>>>(wo, bo, x);

    // 5) RMSNorm2
    rmsnorm_kernel<<<S, 256>>>(x1B, n2w, h2B);

    // 6) router + grouping
    zero_kernel<<<1, 32>>>();
    router_kernel<<<S/8, 256>>>(rw, rb);
    place_kernel<<<1, 1024>>>();
    colsum_kernel<<<NE, 256>>>();

    // 7) grouped MoE GEMMs (top-2 only, bf16 3-term)
    moe1_kernel<<<dim3(4, 32, NE), 256>>>(h2B, w1, b1);
    moe2_kernel<<<dim3(8, 32, NE), 256>>>(w2, b2);

    // 8) combine + residual, aux loss
    combine_kernel<<<S, 256>>>(out);
    aux_kernel<<<1, 32>>>(out, out_size);
}

// round 13
// speedup vs baseline: 1.0893x; 1.0045x over previous
#include <cuda_runtime.h>
#include <math.h>
#include <stdint.h>

#define S 2048
#define D 1024
#define NH 8
#define NKV 2
#define HD 128
#define WS 64
#define NE 16
#define HDIM 512
#define NA (S*2)

// ---------------- scratch (static device globals; no allocation) ------------
__device__ float g_h[S*D];
__device__ float g_q[S*D];
__device__ float g_k[S*NKV*HD];
__device__ float g_v[S*NKV*HD];
__device__ float g_attn[S*D];
__device__ float g_x1[S*D];
__device__ float g_h2[S*D];
__device__ float g_probs[S*NE];
__device__ float g_topw[S*2];
__device__ int   g_topi[S*2];
__device__ int   g_cnt[NE];
__device__ int   g_off[NE];
__device__ int   g_cur[NE];
__device__ int   g_atok[NA];
__device__ float g_aw[NA];
__device__ int   g_tslot[S*2];
__device__ float g_hmid[NA*HDIM];
__device__ float g_y[NA*D];
__device__ float g_colsum[NE];

// ---------------- RMSNorm ----------------------------------------------------
__global__ void rmsnorm_kernel(const float* __restrict__ x,
                               const float* __restrict__ w,
                               float* __restrict__ o) {
    int row = blockIdx.x;
    int tid = threadIdx.x;
    const float4* x4 = (const float4*)(x + (size_t)row * D);
    float4 v = x4[tid];
    float ss = v.x*v.x + v.y*v.y + v.z*v.z + v.w*v.w;
    __shared__ float red[8];
    #pragma unroll
    for (int s = 16; s; s >>= 1) ss += __shfl_xor_sync(0xffffffffu, ss, s);
    if ((tid & 31) == 0) red[tid >> 5] = ss;
    __syncthreads();
    if (tid < 32) {
        float t = (tid < 8) ? red[tid] : 0.f;
        #pragma unroll
        for (int s = 4; s; s >>= 1) t += __shfl_xor_sync(0xffffffffu, t, s);
        if (tid == 0) red[0] = t;
    }
    __syncthreads();
    float r = rsqrtf(red[0] * (1.0f / (float)D) + 1e-6f);
    const float4* w4 = (const float4*)w;
    float4 wv = w4[tid];
    float4 out;
    out.x = v.x * r * wv.x; out.y = v.y * r * wv.y;
    out.z = v.z * r * wv.z; out.w = v.w * r * wv.w;
    ((float4*)(o + (size_t)row * D))[tid] = out;
}

// =============================================================================
// GEMM geometry: CTA tile 64x128x16, 8 warps, warp 32x32.
// Attention path: bf16 3-term split (12 mma16/slab, ~fp32 accuracy).
// MoE path (post-router): fp16 1-term (4 mma16/slab, ~tf32 accuracy).
// =============================================================================
#define BM 64
#define BN 128
#define BKT 16

#define ASTRH 12
#define BSTRH 136
#define APLANEH (BM*ASTRH)       // 768 words
#define BPLANEH (8*BSTRH)        // 1088 words
#define HSTAGE (2*APLANEH + 2*BPLANEH)   // 3712 words (bf16 3-term)
#define FSTAGE (APLANEH + BPLANEH)       // 1856 words (fp16 1-term)

static __device__ __forceinline__ uint32_t packbf2(float lo_k, float hi_k) {
    uint32_t r; asm("cvt.rn.bf16x2.f32 %0, %1, %2;" : "=r"(r) : "f"(hi_k), "f"(lo_k));
    return r;
}
static __device__ __forceinline__ uint32_t packhf2(float lo_k, float hi_k) {
    uint32_t r; asm("cvt.rn.f16x2.f32 %0, %1, %2;" : "=r"(r) : "f"(hi_k), "f"(lo_k));
    return r;
}
static __device__ __forceinline__ void mma16(float* d, const uint32_t* a, const uint32_t* b) {
    asm volatile("mma.sync.aligned.m16n8k16.row.col.f32.bf16.bf16.f32 "
        "{%0,%1,%2,%3}, {%4,%5,%6,%7}, {%8,%9}, {%0,%1,%2,%3};\n"
        : "+f"(d[0]), "+f"(d[1]), "+f"(d[2]), "+f"(d[3])
        : "r"(a[0]), "r"(a[1]), "r"(a[2]), "r"(a[3]), "r"(b[0]), "r"(b[1]));
}
static __device__ __forceinline__ void mma16f(float* d, const uint32_t* a, const uint32_t* b) {
    asm volatile("mma.sync.aligned.m16n8k16.row.col.f32.f16.f16.f32 "
        "{%0,%1,%2,%3}, {%4,%5,%6,%7}, {%8,%9}, {%0,%1,%2,%3};\n"
        : "+f"(d[0]), "+f"(d[1]), "+f"(d[2]), "+f"(d[3])
        : "r"(a[0]), "r"(a[1]), "r"(a[2]), "r"(a[3]), "r"(b[0]), "r"(b[1]));
}

// shared epilogue: bias [+resid][silu], write C
template<int XEPI>
static __device__ __forceinline__ void gemm_epilogue(
    float acc[2][4][4], const float* __restrict__ bias, const float* __restrict__ resid,
    float* __restrict__ C, int M, int Nld, int m0, int n0, int wm, int wn, int g, int tg)
{
    #pragma unroll
    for (int i = 0; i < 2; i++) {
        int rr0 = m0 + wm + i*16 + g;
        int rr1 = rr0 + 8;
        #pragma unroll
        for (int j = 0; j < 4; j++) {
            int c = n0 + wn + j*8 + tg*2;
            float b0v = bias[c], b1v = bias[c+1];
            if (rr0 < M) {
                float t0 = acc[i][j][0] + b0v;
                float t1 = acc[i][j][1] + b1v;
                if (XEPI == 1) {
                    t0 += resid[(size_t)rr0*Nld + c];
                    t1 += resid[(size_t)rr0*Nld + c + 1];
                }
                if (XEPI == 2) {
                    t0 = t0 / (1.f + expf(-t0));
                    t1 = t1 / (1.f + expf(-t1));
                }
                float2 o; o.x = t0; o.y = t1;
                *(float2*)&C[(size_t)rr0*Nld + c] = o;
            }
            if (rr1 < M) {
                float t0 = acc[i][j][2] + b0v;
                float t1 = acc[i][j][3] + b1v;
                if (XEPI == 1) {
                    t0 += resid[(size_t)rr1*Nld + c];
                    t1 += resid[(size_t)rr1*Nld + c + 1];
                }
                if (XEPI == 2) {
                    t0 = t0 / (1.f + expf(-t0));
                    t1 = t1 / (1.f + expf(-t1));
                }
                float2 o; o.x = t0; o.y = t1;
                *(float2*)&C[(size_t)rr1*Nld + c] = o;
            }
        }
    }
}

// =============================================================================
// bf16 3-term split GEMM core (attention path)
// =============================================================================
static __device__ __forceinline__ void store_stage_bf16(
    uint32_t* base, float4 ra, float4 rb0v, float4 rb1v,
    int arow, int pa0, int pr, int bc)
{
    uint32_t p0 = packbf2(ra.x, ra.y);
    uint32_t p1 = packbf2(ra.z, ra.w);
    base[arow*ASTRH + pa0]     = p0;
    base[arow*ASTRH + pa0 + 1] = p1;
    float l0 = ra.x - __uint_as_float(p0 << 16);
    float l1 = ra.y - __uint_as_float(p0 & 0xffff0000u);
    float l2 = ra.z - __uint_as_float(p1 << 16);
    float l3 = ra.w - __uint_as_float(p1 & 0xffff0000u);
    base[APLANEH + arow*ASTRH + pa0]     = packbf2(l0, l1);
    base[APLANEH + arow*ASTRH + pa0 + 1] = packbf2(l2, l3);
    float b0a[4] = {rb0v.x, rb0v.y, rb0v.z, rb0v.w};
    float b1a[4] = {rb1v.x, rb1v.y, rb1v.z, rb1v.w};
    uint32_t hp[4], lp[4];
    #pragma unroll
    for (int j = 0; j < 4; j++) {
        uint32_t h = packbf2(b0a[j], b1a[j]);
        hp[j] = h;
        float ll0 = b0a[j] - __uint_as_float(h << 16);
        float ll1 = b1a[j] - __uint_as_float(h & 0xffff0000u);
        lp[j] = packbf2(ll0, ll1);
    }
    *(uint4*)&base[2*APLANEH + pr*BSTRH + bc] = make_uint4(hp[0], hp[1], hp[2], hp[3]);
    *(uint4*)&base[2*APLANEH + BPLANEH + pr*BSTRH + bc] = make_uint4(lp[0], lp[1], lp[2], lp[3]);
}

template<int XEPI, int XGATHER>
static __device__ __forceinline__ void gemm_core_bf16(
    uint32_t* Hsm,
    const float* __restrict__ A, const float* __restrict__ B,
    const float* __restrict__ bias, const float* __restrict__ resid,
    float* __restrict__ C, int M, int Nld, int K, int m0, int n0,
    const int* __restrict__ rowidx)
{
    int tid = threadIdx.x;
    int arow = tid >> 2;
    int ac = (tid & 3) * 4;
    int pa0 = (tid & 3) * 2;
    int r0 = m0 + arow;
    bool v0 = r0 < M;
    int gr0 = v0 ? (XGATHER ? rowidx[r0] : r0) : 0;
    const float* Ar0 = A + (size_t)gr0 * K;
    int pr = tid >> 5;
    int bc = (tid & 31) * 4;
    const float* Bp0 = B + (size_t)(2*pr) * Nld + n0 + bc;
    const float* Bp1 = Bp0 + Nld;

    int lane = tid & 31, g = lane >> 2, tg = lane & 3;
    int wm = (tid >> 7) * 32;
    int wn = ((tid >> 5) & 3) * 32;

    float acc[2][4][4];
    #pragma unroll
    for (int i = 0; i < 2; i++)
        #pragma unroll
        for (int j = 0; j < 4; j++)
            #pragma unroll
            for (int c = 0; c < 4; c++) acc[i][j][c] = 0.f;

    float4 ra   = v0 ? *(const float4*)(Ar0 + ac) : make_float4(0.f,0.f,0.f,0.f);
    float4 rb0v = *(const float4*)(Bp0);
    float4 rb1v = *(const float4*)(Bp1);
    store_stage_bf16(Hsm, ra, rb0v, rb1v, arow, pa0, pr, bc);
    __syncthreads();
    int cur = 0;

    for (int k0 = 0; k0 < K; k0 += BKT) {
        int kn = k0 + BKT;
        bool more = kn < K;
        if (more) {
            ra   = v0 ? *(const float4*)(Ar0 + kn + ac) : make_float4(0.f,0.f,0.f,0.f);
            rb0v = *(const float4*)(Bp0 + (size_t)kn * Nld);
            rb1v = *(const float4*)(Bp1 + (size_t)kn * Nld);
        }
        const uint32_t* Ah = Hsm + cur * HSTAGE;
        const uint32_t* Al = Ah + APLANEH;
        const uint32_t* Bh = Ah + 2*APLANEH;
        const uint32_t* Bl = Bh + BPLANEH;

        uint32_t ah[2][4], al[2][4], bh[4][2], bl[4][2];
        #pragma unroll
        for (int i = 0; i < 2; i++) {
            int mb = wm + i*16 + g;
            ah[i][0] = Ah[mb*ASTRH + tg];       ah[i][1] = Ah[(mb+8)*ASTRH + tg];
            ah[i][2] = Ah[mb*ASTRH + tg+4];     ah[i][3] = Ah[(mb+8)*ASTRH + tg+4];
            al[i][0] = Al[mb*ASTRH + tg];       al[i][1] = Al[(mb+8)*ASTRH + tg];
            al[i][2] = Al[mb*ASTRH + tg+4];     al[i][3] = Al[(mb+8)*ASTRH + tg+4];
        }
        #pragma unroll
        for (int j = 0; j < 4; j++) {
            int nb = wn + j*8 + g;
            bh[j][0] = Bh[tg*BSTRH + nb];       bh[j][1] = Bh[(tg+4)*BSTRH + nb];
            bl[j][0] = Bl[tg*BSTRH + nb];       bl[j][1] = Bl[(tg+4)*BSTRH + nb];
        }
        #pragma unroll
        for (int i = 0; i < 2; i++)
            #pragma unroll
            for (int j = 0; j < 4; j++) mma16(acc[i][j], ah[i], bh[j]);
        #pragma unroll
        for (int i = 0; i < 2; i++)
            #pragma unroll
            for (int j = 0; j < 4; j++) mma16(acc[i][j], ah[i], bl[j]);
        #pragma unroll
        for (int i = 0; i < 2; i++)
            #pragma unroll
            for (int j = 0; j < 4; j++) mma16(acc[i][j], al[i], bh[j]);

        if (more) {
            store_stage_bf16(Hsm + (cur ^ 1) * HSTAGE, ra, rb0v, rb1v, arow, pa0, pr, bc);
            __syncthreads();
            cur ^= 1;
        }
    }
    gemm_epilogue<XEPI>(acc, bias, resid, C, M, Nld, m0, n0, wm, wn, g, tg);
}

// =============================================================================
// fp16 1-term GEMM core (MoE path, post-router; ~tf32 accuracy)
// =============================================================================
static __device__ __forceinline__ void store_stage_f16(
    uint32_t* base, float4 ra, float4 rb0v, float4 rb1v,
    int arow, int pa0, int pr, int bc)
{
    base[arow*ASTRH + pa0]     = packhf2(ra.x, ra.y);
    base[arow*ASTRH + pa0 + 1] = packhf2(ra.z, ra.w);
    uint32_t hp[4];
    hp[0] = packhf2(rb0v.x, rb1v.x);
    hp[1] = packhf2(rb0v.y, rb1v.y);
    hp[2] = packhf2(rb0v.z, rb1v.z);
    hp[3] = packhf2(rb0v.w, rb1v.w);
    *(uint4*)&base[APLANEH + pr*BSTRH + bc] = make_uint4(hp[0], hp[1], hp[2], hp[3]);
}

template<int XEPI, int XGATHER>
static __device__ __forceinline__ void gemm_core_f16(
    uint32_t* Fsm,
    const float* __restrict__ A, const float* __restrict__ B,
    const float* __restrict__ bias, const float* __restrict__ resid,
    float* __restrict__ C, int M, int Nld, int K, int m0, int n0,
    const int* __restrict__ rowidx)
{
    int tid = threadIdx.x;
    int arow = tid >> 2;
    int ac = (tid & 3) * 4;
    int pa0 = (tid & 3) * 2;
    int r0 = m0 + arow;
    bool v0 = r0 < M;
    int gr0 = v0 ? (XGATHER ? rowidx[r0] : r0) : 0;
    const float* Ar0 = A + (size_t)gr0 * K;
    int pr = tid >> 5;
    int bc = (tid & 31) * 4;
    const float* Bp0 = B + (size_t)(2*pr) * Nld + n0 + bc;
    const float* Bp1 = Bp0 + Nld;

    int lane = tid & 31, g = lane >> 2, tg = lane & 3;
    int wm = (tid >> 7) * 32;
    int wn = ((tid >> 5) & 3) * 32;

    float acc[2][4][4];
    #pragma unroll
    for (int i = 0; i < 2; i++)
        #pragma unroll
        for (int j = 0; j < 4; j++)
            #pragma unroll
            for (int c = 0; c < 4; c++) acc[i][j][c] = 0.f;

    float4 ra   = v0 ? *(const float4*)(Ar0 + ac) : make_float4(0.f,0.f,0.f,0.f);
    float4 rb0v = *(const float4*)(Bp0);
    float4 rb1v = *(const float4*)(Bp1);
    store_stage_f16(Fsm, ra, rb0v, rb1v, arow, pa0, pr, bc);
    __syncthreads();
    int cur = 0;

    for (int k0 = 0; k0 < K; k0 += BKT) {
        int kn = k0 + BKT;
        bool more = kn < K;
        if (more) {
            ra   = v0 ? *(const float4*)(Ar0 + kn + ac) : make_float4(0.f,0.f,0.f,0.f);
            rb0v = *(const float4*)(Bp0 + (size_t)kn * Nld);
            rb1v = *(const float4*)(Bp1 + (size_t)kn * Nld);
        }
        const uint32_t* Ah = Fsm + cur * FSTAGE;
        const uint32_t* Bh = Ah + APLANEH;

        uint32_t ah[2][4], bh[4][2];
        #pragma unroll
        for (int i = 0; i < 2; i++) {
            int mb = wm + i*16 + g;
            ah[i][0] = Ah[mb*ASTRH + tg];       ah[i][1] = Ah[(mb+8)*ASTRH + tg];
            ah[i][2] = Ah[mb*ASTRH + tg+4];     ah[i][3] = Ah[(mb+8)*ASTRH + tg+4];
        }
        #pragma unroll
        for (int j = 0; j < 4; j++) {
            int nb = wn + j*8 + g;
            bh[j][0] = Bh[tg*BSTRH + nb];       bh[j][1] = Bh[(tg+4)*BSTRH + nb];
        }
        #pragma unroll
        for (int i = 0; i < 2; i++)
            #pragma unroll
            for (int j = 0; j < 4; j++) mma16f(acc[i][j], ah[i], bh[j]);

        if (more) {
            store_stage_f16(Fsm + (cur ^ 1) * FSTAGE, ra, rb0v, rb1v, arow, pa0, pr, bc);
            __syncthreads();
            cur ^= 1;
        }
    }
    gemm_epilogue<XEPI>(acc, bias, resid, C, M, Nld, m0, n0, wm, wn, g, tg);
}

// ---- fused QKV: grid (12, 32) ------------------------------------------------
__global__ void __launch_bounds__(256, 2) qkv_kernel(
    const float* __restrict__ h,
    const float* __restrict__ wq, const float* __restrict__ bq,
    const float* __restrict__ wk, const float* __restrict__ bk,
    const float* __restrict__ wv, const float* __restrict__ bv)
{
    __shared__ __align__(16) uint32_t Hsm[2*HSTAGE];
    int x = blockIdx.x, m0 = blockIdx.y * BM;
    if (x < 8)
        gemm_core_bf16<0,0>(Hsm, h, wq, bq, nullptr, g_q, S, 1024, 1024, m0, x*128, nullptr);
    else if (x < 10)
        gemm_core_bf16<0,0>(Hsm, h, wk, bk, nullptr, g_k, S, 256, 1024, m0, (x-8)*128, nullptr);
    else
        gemm_core_bf16<0,0>(Hsm, h, wv, bv, nullptr, g_v, S, 256, 1024, m0, (x-10)*128, nullptr);
}

// ---- O-proj + residual: grid (8, 32) -----------------------------------------
__global__ void __launch_bounds__(256, 2) oproj_kernel(
    const float* __restrict__ wo, const float* __restrict__ bo,
    const float* __restrict__ x)
{
    __shared__ __align__(16) uint32_t Hsm[2*HSTAGE];
    gemm_core_bf16<1,0>(Hsm, g_attn, wo, bo, x, g_x1, S, 1024, 1024,
                        blockIdx.y*BM, blockIdx.x*BN, nullptr);
}

// ---- MoE expert GEMMs (fp16 1-term, grouped) ----------------------------------
__global__ void __launch_bounds__(256, 2) moe1_kernel(
    const float* __restrict__ h2, const float* __restrict__ w1,
    const float* __restrict__ b1)
{
    int e = blockIdx.z;
    int M = g_cnt[e];
    int m0 = blockIdx.y * BM;
    if (m0 >= M) return;
    int o = g_off[e];
    __shared__ __align__(16) uint32_t Fsm[2*FSTAGE];
    gemm_core_f16<2,1>(Fsm, h2, w1 + (size_t)e*1024*512, b1 + (size_t)e*512,
                       nullptr, g_hmid + (size_t)o*512, M, 512, 1024,
                       m0, blockIdx.x*BN, g_atok + o);
}

__global__ void __launch_bounds__(256, 2) moe2_kernel(
    const float* __restrict__ w2, const float* __restrict__ b2)
{
    int e = blockIdx.z;
    int M = g_cnt[e];
    int m0 = blockIdx.y * BM;
    if (m0 >= M) return;
    int o = g_off[e];
    __shared__ __align__(16) uint32_t Fsm[2*FSTAGE];
    gemm_core_f16<0,0>(Fsm, g_hmid + (size_t)o*512, w2 + (size_t)e*512*1024,
                       b2 + (size_t)e*1024, nullptr, g_y + (size_t)o*1024,
                       M, 1024, 512, m0, blockIdx.x*BN, nullptr);
}

// =============================================================================
// sliding-window attention: smem-staged K/V window, lane-parallel scores.
// =============================================================================
#define AROWS 72
#define ASTRIDE 132
#define ATTN_SMEM ((2*AROWS*ASTRIDE + 8*ASTRIDE) * 4)

__global__ void __launch_bounds__(256, 2) attn_kernel(const float* __restrict__ sinkp) {
    extern __shared__ float sm[];
    float* sK = sm;
    float* sV = sm + AROWS*ASTRIDE;
    float* sQ = sm + 2*AROWS*ASTRIDE;
    int tid = threadIdx.x, warp = tid >> 5, lane = tid & 31;
    int b = blockIdx.x, h = blockIdx.y, kvh = h >> 2;
    int i0 = b * 8;
    int jmin = (i0 >= (WS-1)) ? (i0 - (WS-1)) : 0;
    int nrows = (i0 + 8) - jmin;

    for (int idx = tid; idx < nrows * 32; idx += 256) {
        int r = idx >> 5, c = idx & 31;
        const float* kp = g_k + (size_t)(jmin + r) * (NKV*HD) + kvh*HD + c*4;
        const float* vp = g_v + (size_t)(jmin + r) * (NKV*HD) + kvh*HD + c*4;
        *(float4*)(sK + r*ASTRIDE + c*4) = *(const float4*)kp;
        *(float4*)(sV + r*ASTRIDE + c*4) = *(const float4*)vp;
    }
    for (int idx = tid; idx < 8 * 32; idx += 256) {
        int r = idx >> 5, c = idx & 31;
        *(float4*)(sQ + r*ASTRIDE + c*4) =
            *(const float4*)(g_q + (size_t)(i0 + r) * D + h*HD + c*4);
    }
    __syncthreads();

    int i = i0 + warp;
    int jstart = (i >= (WS-1)) ? (i - (WS-1)) : 0;
    int cnt = i - jstart + 1;
    int base = jstart - jmin;
    const float scale = 0.08838834764831845f;

    float s0 = -1e30f, s1 = -1e30f;
    {
        bool u0 = lane < cnt, u1 = (32 + lane) < cnt;
        const float* q  = sQ + warp * ASTRIDE;
        const float* k0 = sK + (base + lane) * ASTRIDE;
        const float* k1 = sK + (base + 32 + lane) * ASTRIDE;
        float a0=0.f,a1=0.f,a2=0.f,a3=0.f, c0=0.f,c1=0.f,c2=0.f,c3=0.f;
        #pragma unroll 8
        for (int c4 = 0; c4 < 32; c4++) {
            float4 q4  = *(const float4*)(q  + c4*4);
            float4 k04 = *(const float4*)(k0 + c4*4);
            float4 k14 = *(const float4*)(k1 + c4*4);
            a0 += q4.x*k04.x; a1 += q4.y*k04.y; a2 += q4.z*k04.z; a3 += q4.w*k04.w;
            c0 += q4.x*k14.x; c1 += q4.y*k14.y; c2 += q4.z*k14.z; c3 += q4.w*k14.w;
        }
        if (u0) s0 = ((a0+a1) + (a2+a3)) * scale;
        if (u1) s1 = ((c0+c1) + (c2+c3)) * scale;
    }

    float sink = *sinkp;
    float m = fmaxf(s0, s1);
    #pragma unroll
    for (int s = 16; s; s >>= 1) m = fmaxf(m, __shfl_xor_sync(0xffffffffu, m, s));
    m = fmaxf(m, sink);
    float e0 = expf(s0 - m), e1 = expf(s1 - m);
    float dsum = e0 + e1;
    #pragma unroll
    for (int s = 16; s; s >>= 1) dsum += __shfl_xor_sync(0xffffffffu, dsum, s);
    dsum += expf(sink - m);
    float inv = 1.f / dsum;

    float o0 = 0.f, o1 = 0.f, o2 = 0.f, o3 = 0.f;
    for (int jj = 0; jj < cnt; ++jj) {
        float pv = (jj < 32) ? e0 : e1;
        float p = __shfl_sync(0xffffffffu, pv, jj & 31);
        const float* vr = sV + (base + jj) * ASTRIDE;
        o0 += p * vr[lane];      o1 += p * vr[lane + 32];
        o2 += p * vr[lane + 64]; o3 += p * vr[lane + 96];
    }
    float* op = g_attn + (size_t)i * D + h * HD;
    op[lane]      = o0 * inv; op[lane + 32] = o1 * inv;
    op[lane + 64] = o2 * inv; op[lane + 96] = o3 * inv;
}

// ---------------- router: 1 warp = 1 token ----------------------------------
__global__ void router_kernel(const float* __restrict__ rw, const float* __restrict__ rb) {
    int warp = threadIdx.x >> 5, lane = threadIdx.x & 31;
    int t = blockIdx.x * 8 + warp;
    float acc[NE];
    #pragma unroll
    for (int e = 0; e < NE; e++) acc[e] = 0.f;
    const float* xr = g_h2 + (size_t)t * D;
    for (int d = lane; d < D; d += 32) {
        float xv = xr[d];
        const float* rr = rw + d * NE;
        #pragma unroll
        for (int e = 0; e < NE; e++) acc[e] += xv * rr[e];
    }
    #pragma unroll
    for (int e = 0; e < NE; e++) {
        float a = acc[e];
        #pragma unroll
        for (int s = 16; s; s >>= 1) a += __shfl_xor_sync(0xffffffffu, a, s);
        acc[e] = a;
    }
    if (lane == 0) {
        float logit[NE]; float m = -1e30f;
        #pragma unroll
        for (int e = 0; e < NE; e++) { logit[e] = (acc[e] + rb[e]) * 10.f; m = fmaxf(m, logit[e]); }
        float pe[NE]; float ssum = 0.f;
        #pragma unroll
        for (int e = 0; e < NE; e++) { pe[e] = expf(logit[e] - m); ssum += pe[e]; }
        float invs = 1.f / ssum;
        #pragma unroll
        for (int e = 0; e < NE; e++) g_probs[t * NE + e] = pe[e] * invs;
        int i0 = 0; float v0 = logit[0];
        #pragma unroll
        for (int e = 1; e < NE; e++) if (logit[e] > v0) { v0 = logit[e]; i0 = e; }
        int i1 = -1; float v1 = -1e30f;
        #pragma unroll
        for (int e = 0; e < NE; e++) if (e != i0 && logit[e] > v1) { v1 = logit[e]; i1 = e; }
        float ex = expf(v1 - v0);
        float w0 = 1.f / (1.f + ex);
        g_topi[t*2] = i0; g_topi[t*2+1] = i1;
        g_topw[t*2] = w0; g_topw[t*2+1] = 1.f - w0;
        atomicAdd(&g_cnt[i0], 1); atomicAdd(&g_cnt[i1], 1);
    }
}

__global__ void zero_kernel() {
    int t = threadIdx.x;
    if (t < NE) { g_cnt[t] = 0; g_cur[t] = 0; }
}

// offsets + place merged: one block, 1024 threads, 2 tokens each
__global__ void place_kernel() {
    if (threadIdx.x == 0) {
        int s = 0;
        for (int e = 0; e < NE; e++) { g_off[e] = s; s += g_cnt[e]; }
    }
    __syncthreads();
    #pragma unroll
    for (int half = 0; half < 2; half++) {
        int t = threadIdx.x + half * 1024;
        #pragma unroll
        for (int k2 = 0; k2 < 2; k2++) {
            int e = g_topi[t*2 + k2];
            int slot = g_off[e] + atomicAdd(&g_cur[e], 1);
            g_atok[slot] = t;
            g_aw[slot] = g_topw[t*2 + k2];
            g_tslot[t*2 + k2] = slot;
        }
    }
}

__global__ void colsum_kernel() {
    int e = blockIdx.x; int tid = threadIdx.x;
    float s = 0.f;
    for (int t = tid; t < S; t += 256) s += g_probs[t * NE + e];
    __shared__ float red[256];
    red[tid] = s; __syncthreads();
    for (int st = 128; st; st >>= 1) { if (tid < st) red[tid] += red[tid + st]; __syncthreads(); }
    if (tid == 0) g_colsum[e] = red[0];
}

__global__ void combine_kernel(float* __restrict__ out) {
    int t = blockIdx.x; int c = threadIdx.x;
    int s0 = g_tslot[t*2], s1 = g_tslot[t*2+1];
    float w0 = g_aw[s0], w1 = g_aw[s1];
    const float4* x14 = (const float4*)(g_x1 + (size_t)t * D);
    const float4* y0  = (const float4*)(g_y + (size_t)s0 * D);
    const float4* y1  = (const float4*)(g_y + (size_t)s1 * D);
    float4 a = x14[c], b = y0[c], d2 = y1[c];
    float4 o;
    o.x = a.x + w0*b.x + w1*d2.x; o.y = a.y + w0*b.y + w1*d2.y;
    o.z = a.z + w0*b.z + w1*d2.z; o.w = a.w + w0*b.w + w1*d2.w;
    ((float4*)out)[(size_t)t * (D/4) + c] = o;
}

__global__ void aux_kernel(float* __restrict__ out, int out_size) {
    int tid = threadIdx.x;
    float v = (tid < NE) ? g_colsum[tid] * g_colsum[tid] : 0.f;
    #pragma unroll
    for (int s = 16; s; s >>= 1) v += __shfl_xor_sync(0xffffffffu, v, s);
    if (tid == 0) {
        float aux = v * (1.0f / (float)NE) * 1e-5f;
        for (int idx = S * D; idx < out_size; ++idx) out[idx] = aux;
    }
}

// ---------------- launch -----------------------------------------------------
extern "C" void kernel_launch(void* const* d_in, const int* in_sizes, int n_in,
                              void* d_out, int out_size) {
    const float* x    = (const float*)d_in[0];
    const float* n1w  = (const float*)d_in[1];
    const float* wq   = (const float*)d_in[2];
    const float* bq   = (const float*)d_in[3];
    const float* wk   = (const float*)d_in[4];
    const float* bk   = (const float*)d_in[5];
    const float* wv   = (const float*)d_in[6];
    const float* bv   = (const float*)d_in[7];
    const float* wo   = (const float*)d_in[8];
    const float* bo   = (const float*)d_in[9];
    const float* sink = (const float*)d_in[10];
    const float* n2w  = (const float*)d_in[11];
    const float* rw   = (const float*)d_in[12];
    const float* rb   = (const float*)d_in[13];
    const float* w1   = (const float*)d_in[14];
    const float* b1   = (const float*)d_in[15];
    const float* w2   = (const float*)d_in[16];
    const float* b2   = (const float*)d_in[17];
    float* out = (float*)d_out;

    void* p;
    cudaGetSymbolAddress(&p, g_h);    float* hB    = (float*)p;
    cudaGetSymbolAddress(&p, g_x1);   float* x1B   = (float*)p;
    cudaGetSymbolAddress(&p, g_h2);   float* h2B   = (float*)p;

    cudaFuncSetAttribute(attn_kernel, cudaFuncAttributeMaxDynamicSharedMemorySize, ATTN_SMEM);

    // 1) RMSNorm1
    rmsnorm_kernel<<<S, 256>>>(x, n1w, hB);

    // 2) fused QKV projections (bf16 3-term tensor cores)
    qkv_kernel<<<dim3(12, 32), 256>>>(hB, wq, bq, wk, bk, wv, bv);

    // 3) sliding-window attention (smem-staged window)
    attn_kernel<<<dim3(S/8, NH), 256, ATTN_SMEM>>>(sink);

    // 4) O-proj + residual
    oproj_kernel<<<dim3(8, 32), 256>>>(wo, bo, x);

    // 5) RMSNorm2
    rmsnorm_kernel<<<S, 256>>>(x1B, n2w, h2B);

    // 6) router + grouping
    zero_kernel<<<1, 32>>>();
    router_kernel<<<S/8, 256>>>(rw, rb);
    place_kernel<<<1, 1024>>>();
    colsum_kernel<<<NE, 256>>>();

    // 7) grouped MoE GEMMs (top-2 only, fp16 1-term)
    moe1_kernel<<<dim3(4, 32, NE), 256>>>(h2B, w1, b1);
    moe2_kernel<<<dim3(8, 32, NE), 256>>>(w2, b2);

    // 8) combine + residual, aux loss
    combine_kernel<<<S, 256>>>(out);
    aux_kernel<<<1, 32>>>(out, out_size);
}

// round 14
// speedup vs baseline: 1.1297x; 1.0371x over previous
#include <cuda_runtime.h>
#include <cuda_fp16.h>
#include <math.h>
#include <stdint.h>

#define S 2048
#define D 1024
#define NH 8
#define NKV 2
#define HD 128
#define WS 64
#define NE 16
#define HDIM 512
#define NA (S*2)

// ---------------- scratch (static device globals; no allocation) ------------
__device__ float g_h[S*D];
__device__ float g_q[S*D];
__device__ float g_k[S*NKV*HD];
__device__ float g_v[S*NKV*HD];
__device__ float g_attn[S*D];
__device__ float g_x1[S*D];
__device__ float g_h2[S*D];
__device__ __half g_h2h[S*D];
__device__ __half g_hmidh[NA*HDIM];
__device__ float g_probs[S*NE];
__device__ float g_topw[S*2];
__device__ int   g_topi[S*2];
__device__ int   g_cnt[NE];
__device__ int   g_off[NE];
__device__ int   g_cur[NE];
__device__ int   g_atok[NA];
__device__ float g_aw[NA];
__device__ int   g_tslot[S*2];
__device__ float g_y[NA*D];
__device__ float g_colsum[NE];

// ---------------- RMSNorm (optional fp16 copy of output) --------------------
__global__ void rmsnorm_kernel(const float* __restrict__ x,
                               const float* __restrict__ w,
                               float* __restrict__ o,
                               __half* __restrict__ oh) {
    int row = blockIdx.x;
    int tid = threadIdx.x;
    const float4* x4 = (const float4*)(x + (size_t)row * D);
    float4 v = x4[tid];
    float ss = v.x*v.x + v.y*v.y + v.z*v.z + v.w*v.w;
    __shared__ float red[8];
    #pragma unroll
    for (int s = 16; s; s >>= 1) ss += __shfl_xor_sync(0xffffffffu, ss, s);
    if ((tid & 31) == 0) red[tid >> 5] = ss;
    __syncthreads();
    if (tid < 32) {
        float t = (tid < 8) ? red[tid] : 0.f;
        #pragma unroll
        for (int s = 4; s; s >>= 1) t += __shfl_xor_sync(0xffffffffu, t, s);
        if (tid == 0) red[0] = t;
    }
    __syncthreads();
    float r = rsqrtf(red[0] * (1.0f / (float)D) + 1e-6f);
    const float4* w4 = (const float4*)w;
    float4 wv = w4[tid];
    float4 out;
    out.x = v.x * r * wv.x; out.y = v.y * r * wv.y;
    out.z = v.z * r * wv.z; out.w = v.w * r * wv.w;
    ((float4*)(o + (size_t)row * D))[tid] = out;
    if (oh) {
        half2 h0 = __floats2half2_rn(out.x, out.y);
        half2 h1 = __floats2half2_rn(out.z, out.w);
        *(half2*)&oh[(size_t)row * D + tid*4]     = h0;
        *(half2*)&oh[(size_t)row * D + tid*4 + 2] = h1;
    }
}

// =============================================================================
// Attention-path GEMMs: CTA 64x128x16, bf16 3-term split (~fp32 accuracy).
// MoE GEMMs: CTA 128x128x16, fp16 1-term, fp16 activations (memory-lean).
// =============================================================================
#define BM 64
#define BN 128
#define BKT 16

#define ASTRH 12
#define BSTRH 136
#define APLANEH (BM*ASTRH)       // 768 words
#define BPLANEH (8*BSTRH)        // 1088 words
#define HSTAGE (2*APLANEH + 2*BPLANEH)   // 3712 words (bf16 3-term)

#define BMF 128
#define FAPLANE (BMF*ASTRH)      // 1536 words
#define FSTAGE (FAPLANE + BPLANEH)  // 2624 words (fp16 1-term)

static __device__ __forceinline__ uint32_t packbf2(float lo_k, float hi_k) {
    uint32_t r; asm("cvt.rn.bf16x2.f32 %0, %1, %2;" : "=r"(r) : "f"(hi_k), "f"(lo_k));
    return r;
}
static __device__ __forceinline__ uint32_t packhf2(float lo_k, float hi_k) {
    uint32_t r; asm("cvt.rn.f16x2.f32 %0, %1, %2;" : "=r"(r) : "f"(hi_k), "f"(lo_k));
    return r;
}
static __device__ __forceinline__ void mma16(float* d, const uint32_t* a, const uint32_t* b) {
    asm volatile("mma.sync.aligned.m16n8k16.row.col.f32.bf16.bf16.f32 "
        "{%0,%1,%2,%3}, {%4,%5,%6,%7}, {%8,%9}, {%0,%1,%2,%3};\n"
        : "+f"(d[0]), "+f"(d[1]), "+f"(d[2]), "+f"(d[3])
        : "r"(a[0]), "r"(a[1]), "r"(a[2]), "r"(a[3]), "r"(b[0]), "r"(b[1]));
}
static __device__ __forceinline__ void mma16f(float* d, const uint32_t* a, const uint32_t* b) {
    asm volatile("mma.sync.aligned.m16n8k16.row.col.f32.f16.f16.f32 "
        "{%0,%1,%2,%3}, {%4,%5,%6,%7}, {%8,%9}, {%0,%1,%2,%3};\n"
        : "+f"(d[0]), "+f"(d[1]), "+f"(d[2]), "+f"(d[3])
        : "r"(a[0]), "r"(a[1]), "r"(a[2]), "r"(a[3]), "r"(b[0]), "r"(b[1]));
}

// shared epilogue for bf16 path (2 row-tiles): bias [+resid], write C
template<int XEPI>
static __device__ __forceinline__ void gemm_epilogue(
    float acc[2][4][4], const float* __restrict__ bias, const float* __restrict__ resid,
    float* __restrict__ C, int M, int Nld, int m0, int n0, int wm, int wn, int g, int tg)
{
    #pragma unroll
    for (int i = 0; i < 2; i++) {
        int rr0 = m0 + wm + i*16 + g;
        int rr1 = rr0 + 8;
        #pragma unroll
        for (int j = 0; j < 4; j++) {
            int c = n0 + wn + j*8 + tg*2;
            float b0v = bias[c], b1v = bias[c+1];
            if (rr0 < M) {
                float t0 = acc[i][j][0] + b0v;
                float t1 = acc[i][j][1] + b1v;
                if (XEPI == 1) {
                    t0 += resid[(size_t)rr0*Nld + c];
                    t1 += resid[(size_t)rr0*Nld + c + 1];
                }
                float2 o; o.x = t0; o.y = t1;
                *(float2*)&C[(size_t)rr0*Nld + c] = o;
            }
            if (rr1 < M) {
                float t0 = acc[i][j][2] + b0v;
                float t1 = acc[i][j][3] + b1v;
                if (XEPI == 1) {
                    t0 += resid[(size_t)rr1*Nld + c];
                    t1 += resid[(size_t)rr1*Nld + c + 1];
                }
                float2 o; o.x = t0; o.y = t1;
                *(float2*)&C[(size_t)rr1*Nld + c] = o;
            }
        }
    }
}

// =============================================================================
// bf16 3-term split GEMM core (attention path) — unchanged from R13
// =============================================================================
static __device__ __forceinline__ void store_stage_bf16(
    uint32_t* base, float4 ra, float4 rb0v, float4 rb1v,
    int arow, int pa0, int pr, int bc)
{
    uint32_t p0 = packbf2(ra.x, ra.y);
    uint32_t p1 = packbf2(ra.z, ra.w);
    base[arow*ASTRH + pa0]     = p0;
    base[arow*ASTRH + pa0 + 1] = p1;
    float l0 = ra.x - __uint_as_float(p0 << 16);
    float l1 = ra.y - __uint_as_float(p0 & 0xffff0000u);
    float l2 = ra.z - __uint_as_float(p1 << 16);
    float l3 = ra.w - __uint_as_float(p1 & 0xffff0000u);
    base[APLANEH + arow*ASTRH + pa0]     = packbf2(l0, l1);
    base[APLANEH + arow*ASTRH + pa0 + 1] = packbf2(l2, l3);
    float b0a[4] = {rb0v.x, rb0v.y, rb0v.z, rb0v.w};
    float b1a[4] = {rb1v.x, rb1v.y, rb1v.z, rb1v.w};
    uint32_t hp[4], lp[4];
    #pragma unroll
    for (int j = 0; j < 4; j++) {
        uint32_t h = packbf2(b0a[j], b1a[j]);
        hp[j] = h;
        float ll0 = b0a[j] - __uint_as_float(h << 16);
        float ll1 = b1a[j] - __uint_as_float(h & 0xffff0000u);
        lp[j] = packbf2(ll0, ll1);
    }
    *(uint4*)&base[2*APLANEH + pr*BSTRH + bc] = make_uint4(hp[0], hp[1], hp[2], hp[3]);
    *(uint4*)&base[2*APLANEH + BPLANEH + pr*BSTRH + bc] = make_uint4(lp[0], lp[1], lp[2], lp[3]);
}

template<int XEPI>
static __device__ __forceinline__ void gemm_core_bf16(
    uint32_t* Hsm,
    const float* __restrict__ A, const float* __restrict__ B,
    const float* __restrict__ bias, const float* __restrict__ resid,
    float* __restrict__ C, int M, int Nld, int K, int m0, int n0)
{
    int tid = threadIdx.x;
    int arow = tid >> 2;
    int ac = (tid & 3) * 4;
    int pa0 = (tid & 3) * 2;
    int r0 = m0 + arow;
    bool v0 = r0 < M;
    const float* Ar0 = A + (size_t)(v0 ? r0 : 0) * K;
    int pr = tid >> 5;
    int bc = (tid & 31) * 4;
    const float* Bp0 = B + (size_t)(2*pr) * Nld + n0 + bc;
    const float* Bp1 = Bp0 + Nld;

    int lane = tid & 31, g = lane >> 2, tg = lane & 3;
    int wm = (tid >> 7) * 32;
    int wn = ((tid >> 5) & 3) * 32;

    float acc[2][4][4];
    #pragma unroll
    for (int i = 0; i < 2; i++)
        #pragma unroll
        for (int j = 0; j < 4; j++)
            #pragma unroll
            for (int c = 0; c < 4; c++) acc[i][j][c] = 0.f;

    float4 ra   = v0 ? *(const float4*)(Ar0 + ac) : make_float4(0.f,0.f,0.f,0.f);
    float4 rb0v = *(const float4*)(Bp0);
    float4 rb1v = *(const float4*)(Bp1);
    store_stage_bf16(Hsm, ra, rb0v, rb1v, arow, pa0, pr, bc);
    __syncthreads();
    int cur = 0;

    for (int k0 = 0; k0 < K; k0 += BKT) {
        int kn = k0 + BKT;
        bool more = kn < K;
        if (more) {
            ra   = v0 ? *(const float4*)(Ar0 + kn + ac) : make_float4(0.f,0.f,0.f,0.f);
            rb0v = *(const float4*)(Bp0 + (size_t)kn * Nld);
            rb1v = *(const float4*)(Bp1 + (size_t)kn * Nld);
        }
        const uint32_t* Ah = Hsm + cur * HSTAGE;
        const uint32_t* Al = Ah + APLANEH;
        const uint32_t* Bh = Ah + 2*APLANEH;
        const uint32_t* Bl = Bh + BPLANEH;

        uint32_t ah[2][4], al[2][4], bh[4][2], bl[4][2];
        #pragma unroll
        for (int i = 0; i < 2; i++) {
            int mb = wm + i*16 + g;
            ah[i][0] = Ah[mb*ASTRH + tg];       ah[i][1] = Ah[(mb+8)*ASTRH + tg];
            ah[i][2] = Ah[mb*ASTRH + tg+4];     ah[i][3] = Ah[(mb+8)*ASTRH + tg+4];
            al[i][0] = Al[mb*ASTRH + tg];       al[i][1] = Al[(mb+8)*ASTRH + tg];
            al[i][2] = Al[mb*ASTRH + tg+4];     al[i][3] = Al[(mb+8)*ASTRH + tg+4];
        }
        #pragma unroll
        for (int j = 0; j < 4; j++) {
            int nb = wn + j*8 + g;
            bh[j][0] = Bh[tg*BSTRH + nb];       bh[j][1] = Bh[(tg+4)*BSTRH + nb];
            bl[j][0] = Bl[tg*BSTRH + nb];       bl[j][1] = Bl[(tg+4)*BSTRH + nb];
        }
        #pragma unroll
        for (int i = 0; i < 2; i++)
            #pragma unroll
            for (int j = 0; j < 4; j++) mma16(acc[i][j], ah[i], bh[j]);
        #pragma unroll
        for (int i = 0; i < 2; i++)
            #pragma unroll
            for (int j = 0; j < 4; j++) mma16(acc[i][j], ah[i], bl[j]);
        #pragma unroll
        for (int i = 0; i < 2; i++)
            #pragma unroll
            for (int j = 0; j < 4; j++) mma16(acc[i][j], al[i], bh[j]);

        if (more) {
            store_stage_bf16(Hsm + (cur ^ 1) * HSTAGE, ra, rb0v, rb1v, arow, pa0, pr, bc);
            __syncthreads();
            cur ^= 1;
        }
    }
    gemm_epilogue<XEPI>(acc, bias, resid, C, M, Nld, m0, n0, wm, wn, g, tg);
}

// =============================================================================
// fp16 1-term GEMM core, BM=128, fp16 A in global (MoE path).
// XEPI: 0 = bias (fp32 out), 2 = bias+silu (fp16 out).
// =============================================================================
static __device__ __forceinline__ void store_stage_f16(
    uint32_t* base, uint4 ra, float4 rb0v, float4 rb1v,
    int arow, int paw, int pr, int bc)
{
    // A: fp16 data already packed as pairs (k ascending within word)
    base[arow*ASTRH + paw]     = ra.x;
    base[arow*ASTRH + paw + 1] = ra.y;
    base[arow*ASTRH + paw + 2] = ra.z;
    base[arow*ASTRH + paw + 3] = ra.w;
    // B: pair-row pr packs k=2pr (lo) and k=2pr+1 (hi)
    uint32_t hp[4];
    hp[0] = packhf2(rb0v.x, rb1v.x);
    hp[1] = packhf2(rb0v.y, rb1v.y);
    hp[2] = packhf2(rb0v.z, rb1v.z);
    hp[3] = packhf2(rb0v.w, rb1v.w);
    *(uint4*)&base[FAPLANE + pr*BSTRH + bc] = make_uint4(hp[0], hp[1], hp[2], hp[3]);
}

template<int XEPI, int XGATHER>
static __device__ __forceinline__ void gemm_core_f16(
    uint32_t* Fsm,
    const __half* __restrict__ A, const float* __restrict__ B,
    const float* __restrict__ bias,
    float* __restrict__ C, __half* __restrict__ Ch,
    int M, int Nld, int K, int m0, int n0,
    const int* __restrict__ rowidx)
{
    int tid = threadIdx.x;
    int arow = tid >> 1;             // 0..127
    int ah0 = (tid & 1) * 8;         // half offset within k16
    int paw = (tid & 1) * 4;         // word offset in smem row
    int r0 = m0 + arow;
    bool v0 = r0 < M;
    int gr0 = v0 ? (XGATHER ? rowidx[r0] : r0) : 0;
    const __half* Ar0 = A + (size_t)gr0 * K + ah0;
    int pr = tid >> 5;
    int bc = (tid & 31) * 4;
    const float* Bp0 = B + (size_t)(2*pr) * Nld + n0 + bc;
    const float* Bp1 = Bp0 + Nld;

    int lane = tid & 31, g = lane >> 2, tg = lane & 3;
    int wm = (tid >> 7) * 64;
    int wn = ((tid >> 5) & 3) * 32;

    float acc[4][4][4];
    #pragma unroll
    for (int i = 0; i < 4; i++)
        #pragma unroll
        for (int j = 0; j < 4; j++)
            #pragma unroll
            for (int c = 0; c < 4; c++) acc[i][j][c] = 0.f;

    uint4 ra    = v0 ? *(const uint4*)(Ar0) : make_uint4(0,0,0,0);
    float4 rb0v = *(const float4*)(Bp0);
    float4 rb1v = *(const float4*)(Bp1);
    store_stage_f16(Fsm, ra, rb0v, rb1v, arow, paw, pr, bc);
    __syncthreads();
    int cur = 0;

    for (int k0 = 0; k0 < K; k0 += BKT) {
        int kn = k0 + BKT;
        bool more = kn < K;
        if (more) {
            ra    = v0 ? *(const uint4*)(Ar0 + kn) : make_uint4(0,0,0,0);
            rb0v  = *(const float4*)(Bp0 + (size_t)kn * Nld);
            rb1v  = *(const float4*)(Bp1 + (size_t)kn * Nld);
        }
        const uint32_t* Ah = Fsm + cur * FSTAGE;
        const uint32_t* Bh = Ah + FAPLANE;

        uint32_t bh[4][2];
        #pragma unroll
        for (int j = 0; j < 4; j++) {
            int nb = wn + j*8 + g;
            bh[j][0] = Bh[tg*BSTRH + nb];       bh[j][1] = Bh[(tg+4)*BSTRH + nb];
        }
        #pragma unroll
        for (int i = 0; i < 4; i++) {
            int mb = wm + i*16 + g;
            uint32_t ah[4];
            ah[0] = Ah[mb*ASTRH + tg];       ah[1] = Ah[(mb+8)*ASTRH + tg];
            ah[2] = Ah[mb*ASTRH + tg+4];     ah[3] = Ah[(mb+8)*ASTRH + tg+4];
            #pragma unroll
            for (int j = 0; j < 4; j++) mma16f(acc[i][j], ah, bh[j]);
        }

        if (more) {
            store_stage_f16(Fsm + (cur ^ 1) * FSTAGE, ra, rb0v, rb1v, arow, paw, pr, bc);
            __syncthreads();
            cur ^= 1;
        }
    }

    // epilogue (4 row-tiles)
    #pragma unroll
    for (int i = 0; i < 4; i++) {
        int rr0 = m0 + wm + i*16 + g;
        int rr1 = rr0 + 8;
        #pragma unroll
        for (int j = 0; j < 4; j++) {
            int c = n0 + wn + j*8 + tg*2;
            float b0v = bias[c], b1v = bias[c+1];
            #pragma unroll
            for (int half2i = 0; half2i < 2; half2i++) {
                int rr = half2i ? rr1 : rr0;
                if (rr >= M) continue;
                float t0 = acc[i][j][half2i*2+0] + b0v;
                float t1 = acc[i][j][half2i*2+1] + b1v;
                if (XEPI == 2) {
                    t0 = t0 / (1.f + expf(-t0));
                    t1 = t1 / (1.f + expf(-t1));
                    *(half2*)&Ch[(size_t)rr*Nld + c] = __floats2half2_rn(t0, t1);
                } else {
                    float2 o; o.x = t0; o.y = t1;
                    *(float2*)&C[(size_t)rr*Nld + c] = o;
                }
            }
        }
    }
}

// ---- fused QKV: grid (12, 32) ------------------------------------------------
__global__ void __launch_bounds__(256, 2) qkv_kernel(
    const float* __restrict__ h,
    const float* __restrict__ wq, const float* __restrict__ bq,
    const float* __restrict__ wk, const float* __restrict__ bk,
    const float* __restrict__ wv, const float* __restrict__ bv)
{
    __shared__ __align__(16) uint32_t Hsm[2*HSTAGE];
    int x = blockIdx.x, m0 = blockIdx.y * BM;
    if (x < 8)
        gemm_core_bf16<0>(Hsm, h, wq, bq, nullptr, g_q, S, 1024, 1024, m0, x*128);
    else if (x < 10)
        gemm_core_bf16<0>(Hsm, h, wk, bk, nullptr, g_k, S, 256, 1024, m0, (x-8)*128);
    else
        gemm_core_bf16<0>(Hsm, h, wv, bv, nullptr, g_v, S, 256, 1024, m0, (x-10)*128);
}

// ---- O-proj + residual: grid (8, 32) -----------------------------------------
__global__ void __launch_bounds__(256, 2) oproj_kernel(
    const float* __restrict__ wo, const float* __restrict__ bo,
    const float* __restrict__ x)
{
    __shared__ __align__(16) uint32_t Hsm[2*HSTAGE];
    gemm_core_bf16<1>(Hsm, g_attn, wo, bo, x, g_x1, S, 1024, 1024,
                      blockIdx.y*BM, blockIdx.x*BN);
}

// ---- MoE expert GEMMs (fp16, BM=128, fp16 activations) ------------------------
__global__ void __launch_bounds__(256, 2) moe1_kernel(
    const float* __restrict__ w1, const float* __restrict__ b1)
{
    int e = blockIdx.z;
    int M = g_cnt[e];
    int m0 = blockIdx.y * BMF;
    if (m0 >= M) return;
    int o = g_off[e];
    __shared__ __align__(16) uint32_t Fsm[2*FSTAGE];
    gemm_core_f16<2,1>(Fsm, g_h2h, w1 + (size_t)e*1024*512, b1 + (size_t)e*512,
                       nullptr, g_hmidh + (size_t)o*512, M, 512, 1024,
                       m0, blockIdx.x*BN, g_atok + o);
}

__global__ void __launch_bounds__(256, 2) moe2_kernel(
    const float* __restrict__ w2, const float* __restrict__ b2)
{
    int e = blockIdx.z;
    int M = g_cnt[e];
    int m0 = blockIdx.y * BMF;
    if (m0 >= M) return;
    int o = g_off[e];
    __shared__ __align__(16) uint32_t Fsm[2*FSTAGE];
    gemm_core_f16<0,0>(Fsm, g_hmidh + (size_t)o*512, w2 + (size_t)e*512*1024,
                       b2 + (size_t)e*1024, g_y + (size_t)o*1024, nullptr,
                       M, 1024, 512, m0, blockIdx.x*BN, nullptr);
}

// =============================================================================
// sliding-window attention: smem-staged K/V window, lane-parallel scores.
// =============================================================================
#define AROWS 72
#define ASTRIDE 132
#define ATTN_SMEM ((2*AROWS*ASTRIDE + 8*ASTRIDE) * 4)

__global__ void __launch_bounds__(256, 2) attn_kernel(const float* __restrict__ sinkp) {
    extern __shared__ float sm[];
    float* sK = sm;
    float* sV = sm + AROWS*ASTRIDE;
    float* sQ = sm + 2*AROWS*ASTRIDE;
    int tid = threadIdx.x, warp = tid >> 5, lane = tid & 31;
    int b = blockIdx.x, h = blockIdx.y, kvh = h >> 2;
    int i0 = b * 8;
    int jmin = (i0 >= (WS-1)) ? (i0 - (WS-1)) : 0;
    int nrows = (i0 + 8) - jmin;

    for (int idx = tid; idx < nrows * 32; idx += 256) {
        int r = idx >> 5, c = idx & 31;
        const float* kp = g_k + (size_t)(jmin + r) * (NKV*HD) + kvh*HD + c*4;
        const float* vp = g_v + (size_t)(jmin + r) * (NKV*HD) + kvh*HD + c*4;
        *(float4*)(sK + r*ASTRIDE + c*4) = *(const float4*)kp;
        *(float4*)(sV + r*ASTRIDE + c*4) = *(const float4*)vp;
    }
    for (int idx = tid; idx < 8 * 32; idx += 256) {
        int r = idx >> 5, c = idx & 31;
        *(float4*)(sQ + r*ASTRIDE + c*4) =
            *(const float4*)(g_q + (size_t)(i0 + r) * D + h*HD + c*4);
    }
    __syncthreads();

    int i = i0 + warp;
    int jstart = (i >= (WS-1)) ? (i - (WS-1)) : 0;
    int cnt = i - jstart + 1;
    int base = jstart - jmin;
    const float scale = 0.08838834764831845f;

    float s0 = -1e30f, s1 = -1e30f;
    {
        bool u0 = lane < cnt, u1 = (32 + lane) < cnt;
        const float* q  = sQ + warp * ASTRIDE;
        const float* k0 = sK + (base + lane) * ASTRIDE;
        const float* k1 = sK + (base + 32 + lane) * ASTRIDE;
        float a0=0.f,a1=0.f,a2=0.f,a3=0.f, c0=0.f,c1=0.f,c2=0.f,c3=0.f;
        #pragma unroll 8
        for (int c4 = 0; c4 < 32; c4++) {
            float4 q4  = *(const float4*)(q  + c4*4);
            float4 k04 = *(const float4*)(k0 + c4*4);
            float4 k14 = *(const float4*)(k1 + c4*4);
            a0 += q4.x*k04.x; a1 += q4.y*k04.y; a2 += q4.z*k04.z; a3 += q4.w*k04.w;
            c0 += q4.x*k14.x; c1 += q4.y*k14.y; c2 += q4.z*k14.z; c3 += q4.w*k14.w;
        }
        if (u0) s0 = ((a0+a1) + (a2+a3)) * scale;
        if (u1) s1 = ((c0+c1) + (c2+c3)) * scale;
    }

    float sink = *sinkp;
    float m = fmaxf(s0, s1);
    #pragma unroll
    for (int s = 16; s; s >>= 1) m = fmaxf(m, __shfl_xor_sync(0xffffffffu, m, s));
    m = fmaxf(m, sink);
    float e0 = expf(s0 - m), e1 = expf(s1 - m);
    float dsum = e0 + e1;
    #pragma unroll
    for (int s = 16; s; s >>= 1) dsum += __shfl_xor_sync(0xffffffffu, dsum, s);
    dsum += expf(sink - m);
    float inv = 1.f / dsum;

    float o0 = 0.f, o1 = 0.f, o2 = 0.f, o3 = 0.f;
    for (int jj = 0; jj < cnt; ++jj) {
        float pv = (jj < 32) ? e0 : e1;
        float p = __shfl_sync(0xffffffffu, pv, jj & 31);
        const float* vr = sV + (base + jj) * ASTRIDE;
        o0 += p * vr[lane];      o1 += p * vr[lane + 32];
        o2 += p * vr[lane + 64]; o3 += p * vr[lane + 96];
    }
    float* op = g_attn + (size_t)i * D + h * HD;
    op[lane]      = o0 * inv; op[lane + 32] = o1 * inv;
    op[lane + 64] = o2 * inv; op[lane + 96] = o3 * inv;
}

// ---------------- router: 1 warp = 1 token ----------------------------------
__global__ void router_kernel(const float* __restrict__ rw, const float* __restrict__ rb) {
    int warp = threadIdx.x >> 5, lane = threadIdx.x & 31;
    int t = blockIdx.x * 8 + warp;
    float acc[NE];
    #pragma unroll
    for (int e = 0; e < NE; e++) acc[e] = 0.f;
    const float* xr = g_h2 + (size_t)t * D;
    for (int d = lane; d < D; d += 32) {
        float xv = xr[d];
        const float* rr = rw + d * NE;
        #pragma unroll
        for (int e = 0; e < NE; e++) acc[e] += xv * rr[e];
    }
    #pragma unroll
    for (int e = 0; e < NE; e++) {
        float a = acc[e];
        #pragma unroll
        for (int s = 16; s; s >>= 1) a += __shfl_xor_sync(0xffffffffu, a, s);
        acc[e] = a;
    }
    if (lane == 0) {
        float logit[NE]; float m = -1e30f;
        #pragma unroll
        for (int e = 0; e < NE; e++) { logit[e] = (acc[e] + rb[e]) * 10.f; m = fmaxf(m, logit[e]); }
        float pe[NE]; float ssum = 0.f;
        #pragma unroll
        for (int e = 0; e < NE; e++) { pe[e] = expf(logit[e] - m); ssum += pe[e]; }
        float invs = 1.f / ssum;
        #pragma unroll
        for (int e = 0; e < NE; e++) g_probs[t * NE + e] = pe[e] * invs;
        int i0 = 0; float v0 = logit[0];
        #pragma unroll
        for (int e = 1; e < NE; e++) if (logit[e] > v0) { v0 = logit[e]; i0 = e; }
        int i1 = -1; float v1 = -1e30f;
        #pragma unroll
        for (int e = 0; e < NE; e++) if (e != i0 && logit[e] > v1) { v1 = logit[e]; i1 = e; }
        float ex = expf(v1 - v0);
        float w0 = 1.f / (1.f + ex);
        g_topi[t*2] = i0; g_topi[t*2+1] = i1;
        g_topw[t*2] = w0; g_topw[t*2+1] = 1.f - w0;
        atomicAdd(&g_cnt[i0], 1); atomicAdd(&g_cnt[i1], 1);
    }
}

__global__ void zero_kernel() {
    int t = threadIdx.x;
    if (t < NE) { g_cnt[t] = 0; g_cur[t] = 0; }
}

// offsets + place merged: one block, 1024 threads, 2 tokens each
__global__ void place_kernel() {
    if (threadIdx.x == 0) {
        int s = 0;
        for (int e = 0; e < NE; e++) { g_off[e] = s; s += g_cnt[e]; }
    }
    __syncthreads();
    #pragma unroll
    for (int half = 0; half < 2; half++) {
        int t = threadIdx.x + half * 1024;
        #pragma unroll
        for (int k2 = 0; k2 < 2; k2++) {
            int e = g_topi[t*2 + k2];
            int slot = g_off[e] + atomicAdd(&g_cur[e], 1);
            g_atok[slot] = t;
            g_aw[slot] = g_topw[t*2 + k2];
            g_tslot[t*2 + k2] = slot;
        }
    }
}

__global__ void colsum_kernel() {
    int e = blockIdx.x; int tid = threadIdx.x;
    float s = 0.f;
    for (int t = tid; t < S; t += 256) s += g_probs[t * NE + e];
    __shared__ float red[256];
    red[tid] = s; __syncthreads();
    for (int st = 128; st; st >>= 1) { if (tid < st) red[tid] += red[tid + st]; __syncthreads(); }
    if (tid == 0) g_colsum[e] = red[0];
}

__global__ void combine_kernel(float* __restrict__ out) {
    int t = blockIdx.x; int c = threadIdx.x;
    int s0 = g_tslot[t*2], s1 = g_tslot[t*2+1];
    float w0 = g_aw[s0], w1 = g_aw[s1];
    const float4* x14 = (const float4*)(g_x1 + (size_t)t * D);
    const float4* y0  = (const float4*)(g_y + (size_t)s0 * D);
    const float4* y1  = (const float4*)(g_y + (size_t)s1 * D);
    float4 a = x14[c], b = y0[c], d2 = y1[c];
    float4 o;
    o.x = a.x + w0*b.x + w1*d2.x; o.y = a.y + w0*b.y + w1*d2.y;
    o.z = a.z + w0*b.z + w1*d2.z; o.w = a.w + w0*b.w + w1*d2.w;
    ((float4*)out)[(size_t)t * (D/4) + c] = o;
}

__global__ void aux_kernel(float* __restrict__ out, int out_size) {
    int tid = threadIdx.x;
    float v = (tid < NE) ? g_colsum[tid] * g_colsum[tid] : 0.f;
    #pragma unroll
    for (int s = 16; s; s >>= 1) v += __shfl_xor_sync(0xffffffffu, v, s);
    if (tid == 0) {
        float aux = v * (1.0f / (float)NE) * 1e-5f;
        for (int idx = S * D; idx < out_size; ++idx) out[idx] = aux;
    }
}

// ---------------- launch -----------------------------------------------------
extern "C" void kernel_launch(void* const* d_in, const int* in_sizes, int n_in,
                              void* d_out, int out_size) {
    const float* x    = (const float*)d_in[0];
    const float* n1w  = (const float*)d_in[1];
    const float* wq   = (const float*)d_in[2];
    const float* bq   = (const float*)d_in[3];
    const float* wk   = (const float*)d_in[4];
    const float* bk   = (const float*)d_in[5];
    const float* wv   = (const float*)d_in[6];
    const float* bv   = (const float*)d_in[7];
    const float* wo   = (const float*)d_in[8];
    const float* bo   = (const float*)d_in[9];
    const float* sink = (const float*)d_in[10];
    const float* n2w  = (const float*)d_in[11];
    const float* rw   = (const float*)d_in[12];
    const float* rb   = (const float*)d_in[13];
    const float* w1   = (const float*)d_in[14];
    const float* b1   = (const float*)d_in[15];
    const float* w2   = (const float*)d_in[16];
    const float* b2   = (const float*)d_in[17];
    float* out = (float*)d_out;

    void* p;
    cudaGetSymbolAddress(&p, g_h);    float* hB    = (float*)p;
    cudaGetSymbolAddress(&p, g_x1);   float* x1B   = (float*)p;
    cudaGetSymbolAddress(&p, g_h2);   float* h2B   = (float*)p;
    cudaGetSymbolAddress(&p, g_h2h);  __half* h2hB = (__half*)p;

    cudaFuncSetAttribute(attn_kernel, cudaFuncAttributeMaxDynamicSharedMemorySize, ATTN_SMEM);

    // 1) RMSNorm1
    rmsnorm_kernel<<<S, 256>>>(x, n1w, hB, nullptr);

    // 2) fused QKV projections (bf16 3-term tensor cores)
    qkv_kernel<<<dim3(12, 32), 256>>>(hB, wq, bq, wk, bk, wv, bv);

    // 3) sliding-window attention (smem-staged window)
    attn_kernel<<<dim3(S/8, NH), 256, ATTN_SMEM>>>(sink);

    // 4) O-proj + residual
    oproj_kernel<<<dim3(8, 32), 256>>>(wo, bo, x);

    // 5) RMSNorm2 (fp32 + fp16 planes)
    rmsnorm_kernel<<<S, 256>>>(x1B, n2w, h2B, h2hB);

    // 6) router + grouping
    zero_kernel<<<1, 32>>>();
    router_kernel<<<S/8, 256>>>(rw, rb);
    place_kernel<<<1, 1024>>>();
    colsum_kernel<<<NE, 256>>>();

    // 7) grouped MoE GEMMs (top-2 only, fp16, BM=128, fp16 activations)
    moe1_kernel<<<dim3(4, 16, NE), 256>>>(w1, b1);
    moe2_kernel<<<dim3(8, 16, NE), 256>>>(w2, b2);

    // 8) combine + residual, aux loss
    combine_kernel<<<S, 256>>>(out);
    aux_kernel<<<1, 32>>>(out, out_size);
}

// round 15
// speedup vs baseline: 1.1725x; 1.0379x over previous
#include <cuda_runtime.h>
#include <cuda_fp16.h>
#include <math.h>
#include <stdint.h>

#define S 2048
#define D 1024
#define NH 8
#define NKV 2
#define HD 128
#define WS 64
#define NE 16
#define HDIM 512
#define NA (S*2)

// ---------------- scratch (static device globals; no allocation) ------------
__device__ float g_h[S*D];
__device__ float g_q[S*D];
__device__ float g_k[S*NKV*HD];
__device__ float g_v[S*NKV*HD];
__device__ float g_attn[S*D];
__device__ float g_x1[S*D];
__device__ float g_h2[S*D];
__device__ __half g_h2h[S*D];
__device__ __half g_hmidh[NA*HDIM];
__device__ float g_probs[S*NE];
__device__ float g_topw[S*2];
__device__ int   g_topi[S*2];
__device__ int   g_cnt[NE];
__device__ int   g_off[NE];
__device__ int   g_cur[NE];
__device__ int   g_atok[NA];
__device__ float g_aw[NA];
__device__ int   g_tslot[S*2];
__device__ float g_y[NA*D];
__device__ float g_colsum[NE];

// ---------------- RMSNorm (optional fp16 copy of output) --------------------
__global__ void rmsnorm_kernel(const float* __restrict__ x,
                               const float* __restrict__ w,
                               float* __restrict__ o,
                               __half* __restrict__ oh) {
    int row = blockIdx.x;
    int tid = threadIdx.x;
    const float4* x4 = (const float4*)(x + (size_t)row * D);
    float4 v = x4[tid];
    float ss = v.x*v.x + v.y*v.y + v.z*v.z + v.w*v.w;
    __shared__ float red[8];
    #pragma unroll
    for (int s = 16; s; s >>= 1) ss += __shfl_xor_sync(0xffffffffu, ss, s);
    if ((tid & 31) == 0) red[tid >> 5] = ss;
    __syncthreads();
    if (tid < 32) {
        float t = (tid < 8) ? red[tid] : 0.f;
        #pragma unroll
        for (int s = 4; s; s >>= 1) t += __shfl_xor_sync(0xffffffffu, t, s);
        if (tid == 0) red[0] = t;
    }
    __syncthreads();
    float r = rsqrtf(red[0] * (1.0f / (float)D) + 1e-6f);
    const float4* w4 = (const float4*)w;
    float4 wv = w4[tid];
    float4 out;
    out.x = v.x * r * wv.x; out.y = v.y * r * wv.y;
    out.z = v.z * r * wv.z; out.w = v.w * r * wv.w;
    ((float4*)(o + (size_t)row * D))[tid] = out;
    if (oh) {
        half2 h0 = __floats2half2_rn(out.x, out.y);
        half2 h1 = __floats2half2_rn(out.z, out.w);
        *(half2*)&oh[(size_t)row * D + tid*4]     = h0;
        *(half2*)&oh[(size_t)row * D + tid*4 + 2] = h1;
    }
}

// =============================================================================
// Attention-path GEMMs: CTA 64x128x16, bf16 3-term split (~fp32 accuracy).
// MoE GEMMs: CTA 128x128x16, fp16 1-term, fp16 activations (memory-lean).
// Occupancy: NO minBlocks cap — reg/smem limited (~5-7 CTAs/SM).
// =============================================================================
#define BM 64
#define BN 128
#define BKT 16

#define ASTRH 12
#define BSTRH 136
#define APLANEH (BM*ASTRH)       // 768 words
#define BPLANEH (8*BSTRH)        // 1088 words
#define HSTAGE (2*APLANEH + 2*BPLANEH)   // 3712 words (bf16 3-term)

#define BMF 128
#define FAPLANE (BMF*ASTRH)      // 1536 words
#define FSTAGE (FAPLANE + BPLANEH)  // 2624 words (fp16 1-term)

static __device__ __forceinline__ uint32_t packbf2(float lo_k, float hi_k) {
    uint32_t r; asm("cvt.rn.bf16x2.f32 %0, %1, %2;" : "=r"(r) : "f"(hi_k), "f"(lo_k));
    return r;
}
static __device__ __forceinline__ uint32_t packhf2(float lo_k, float hi_k) {
    uint32_t r; asm("cvt.rn.f16x2.f32 %0, %1, %2;" : "=r"(r) : "f"(hi_k), "f"(lo_k));
    return r;
}
static __device__ __forceinline__ void mma16(float* d, const uint32_t* a, const uint32_t* b) {
    asm volatile("mma.sync.aligned.m16n8k16.row.col.f32.bf16.bf16.f32 "
        "{%0,%1,%2,%3}, {%4,%5,%6,%7}, {%8,%9}, {%0,%1,%2,%3};\n"
        : "+f"(d[0]), "+f"(d[1]), "+f"(d[2]), "+f"(d[3])
        : "r"(a[0]), "r"(a[1]), "r"(a[2]), "r"(a[3]), "r"(b[0]), "r"(b[1]));
}
static __device__ __forceinline__ void mma16f(float* d, const uint32_t* a, const uint32_t* b) {
    asm volatile("mma.sync.aligned.m16n8k16.row.col.f32.f16.f16.f32 "
        "{%0,%1,%2,%3}, {%4,%5,%6,%7}, {%8,%9}, {%0,%1,%2,%3};\n"
        : "+f"(d[0]), "+f"(d[1]), "+f"(d[2]), "+f"(d[3])
        : "r"(a[0]), "r"(a[1]), "r"(a[2]), "r"(a[3]), "r"(b[0]), "r"(b[1]));
}

// shared epilogue for bf16 path (2 row-tiles): bias [+resid], write C
template<int XEPI>
static __device__ __forceinline__ void gemm_epilogue(
    float acc[2][4][4], const float* __restrict__ bias, const float* __restrict__ resid,
    float* __restrict__ C, int M, int Nld, int m0, int n0, int wm, int wn, int g, int tg)
{
    #pragma unroll
    for (int i = 0; i < 2; i++) {
        int rr0 = m0 + wm + i*16 + g;
        int rr1 = rr0 + 8;
        #pragma unroll
        for (int j = 0; j < 4; j++) {
            int c = n0 + wn + j*8 + tg*2;
            float b0v = bias[c], b1v = bias[c+1];
            if (rr0 < M) {
                float t0 = acc[i][j][0] + b0v;
                float t1 = acc[i][j][1] + b1v;
                if (XEPI == 1) {
                    t0 += resid[(size_t)rr0*Nld + c];
                    t1 += resid[(size_t)rr0*Nld + c + 1];
                }
                float2 o; o.x = t0; o.y = t1;
                *(float2*)&C[(size_t)rr0*Nld + c] = o;
            }
            if (rr1 < M) {
                float t0 = acc[i][j][2] + b0v;
                float t1 = acc[i][j][3] + b1v;
                if (XEPI == 1) {
                    t0 += resid[(size_t)rr1*Nld + c];
                    t1 += resid[(size_t)rr1*Nld + c + 1];
                }
                float2 o; o.x = t0; o.y = t1;
                *(float2*)&C[(size_t)rr1*Nld + c] = o;
            }
        }
    }
}

// =============================================================================
// bf16 3-term split GEMM core (attention path)
// =============================================================================
static __device__ __forceinline__ void store_stage_bf16(
    uint32_t* base, float4 ra, float4 rb0v, float4 rb1v,
    int arow, int pa0, int pr, int bc)
{
    uint32_t p0 = packbf2(ra.x, ra.y);
    uint32_t p1 = packbf2(ra.z, ra.w);
    base[arow*ASTRH + pa0]     = p0;
    base[arow*ASTRH + pa0 + 1] = p1;
    float l0 = ra.x - __uint_as_float(p0 << 16);
    float l1 = ra.y - __uint_as_float(p0 & 0xffff0000u);
    float l2 = ra.z - __uint_as_float(p1 << 16);
    float l3 = ra.w - __uint_as_float(p1 & 0xffff0000u);
    base[APLANEH + arow*ASTRH + pa0]     = packbf2(l0, l1);
    base[APLANEH + arow*ASTRH + pa0 + 1] = packbf2(l2, l3);
    float b0a[4] = {rb0v.x, rb0v.y, rb0v.z, rb0v.w};
    float b1a[4] = {rb1v.x, rb1v.y, rb1v.z, rb1v.w};
    uint32_t hp[4], lp[4];
    #pragma unroll
    for (int j = 0; j < 4; j++) {
        uint32_t h = packbf2(b0a[j], b1a[j]);
        hp[j] = h;
        float ll0 = b0a[j] - __uint_as_float(h << 16);
        float ll1 = b1a[j] - __uint_as_float(h & 0xffff0000u);
        lp[j] = packbf2(ll0, ll1);
    }
    *(uint4*)&base[2*APLANEH + pr*BSTRH + bc] = make_uint4(hp[0], hp[1], hp[2], hp[3]);
    *(uint4*)&base[2*APLANEH + BPLANEH + pr*BSTRH + bc] = make_uint4(lp[0], lp[1], lp[2], lp[3]);
}

template<int XEPI>
static __device__ __forceinline__ void gemm_core_bf16(
    uint32_t* Hsm,
    const float* __restrict__ A, const float* __restrict__ B,
    const float* __restrict__ bias, const float* __restrict__ resid,
    float* __restrict__ C, int M, int Nld, int K, int m0, int n0)
{
    int tid = threadIdx.x;
    int arow = tid >> 2;
    int ac = (tid & 3) * 4;
    int pa0 = (tid & 3) * 2;
    int r0 = m0 + arow;
    bool v0 = r0 < M;
    const float* Ar0 = A + (size_t)(v0 ? r0 : 0) * K;
    int pr = tid >> 5;
    int bc = (tid & 31) * 4;
    const float* Bp0 = B + (size_t)(2*pr) * Nld + n0 + bc;
    const float* Bp1 = Bp0 + Nld;

    int lane = tid & 31, g = lane >> 2, tg = lane & 3;
    int wm = (tid >> 7) * 32;
    int wn = ((tid >> 5) & 3) * 32;

    float acc[2][4][4];
    #pragma unroll
    for (int i = 0; i < 2; i++)
        #pragma unroll
        for (int j = 0; j < 4; j++)
            #pragma unroll
            for (int c = 0; c < 4; c++) acc[i][j][c] = 0.f;

    float4 ra   = v0 ? *(const float4*)(Ar0 + ac) : make_float4(0.f,0.f,0.f,0.f);
    float4 rb0v = *(const float4*)(Bp0);
    float4 rb1v = *(const float4*)(Bp1);
    store_stage_bf16(Hsm, ra, rb0v, rb1v, arow, pa0, pr, bc);
    __syncthreads();
    int cur = 0;

    for (int k0 = 0; k0 < K; k0 += BKT) {
        int kn = k0 + BKT;
        bool more = kn < K;
        if (more) {
            ra   = v0 ? *(const float4*)(Ar0 + kn + ac) : make_float4(0.f,0.f,0.f,0.f);
            rb0v = *(const float4*)(Bp0 + (size_t)kn * Nld);
            rb1v = *(const float4*)(Bp1 + (size_t)kn * Nld);
        }
        const uint32_t* Ah = Hsm + cur * HSTAGE;
        const uint32_t* Al = Ah + APLANEH;
        const uint32_t* Bh = Ah + 2*APLANEH;
        const uint32_t* Bl = Bh + BPLANEH;

        uint32_t ah[2][4], al[2][4], bh[4][2], bl[4][2];
        #pragma unroll
        for (int i = 0; i < 2; i++) {
            int mb = wm + i*16 + g;
            ah[i][0] = Ah[mb*ASTRH + tg];       ah[i][1] = Ah[(mb+8)*ASTRH + tg];
            ah[i][2] = Ah[mb*ASTRH + tg+4];     ah[i][3] = Ah[(mb+8)*ASTRH + tg+4];
            al[i][0] = Al[mb*ASTRH + tg];       al[i][1] = Al[(mb+8)*ASTRH + tg];
            al[i][2] = Al[mb*ASTRH + tg+4];     al[i][3] = Al[(mb+8)*ASTRH + tg+4];
        }
        #pragma unroll
        for (int j = 0; j < 4; j++) {
            int nb = wn + j*8 + g;
            bh[j][0] = Bh[tg*BSTRH + nb];       bh[j][1] = Bh[(tg+4)*BSTRH + nb];
            bl[j][0] = Bl[tg*BSTRH + nb];       bl[j][1] = Bl[(tg+4)*BSTRH + nb];
        }
        #pragma unroll
        for (int i = 0; i < 2; i++)
            #pragma unroll
            for (int j = 0; j < 4; j++) mma16(acc[i][j], ah[i], bh[j]);
        #pragma unroll
        for (int i = 0; i < 2; i++)
            #pragma unroll
            for (int j = 0; j < 4; j++) mma16(acc[i][j], ah[i], bl[j]);
        #pragma unroll
        for (int i = 0; i < 2; i++)
            #pragma unroll
            for (int j = 0; j < 4; j++) mma16(acc[i][j], al[i], bh[j]);

        if (more) {
            store_stage_bf16(Hsm + (cur ^ 1) * HSTAGE, ra, rb0v, rb1v, arow, pa0, pr, bc);
            __syncthreads();
            cur ^= 1;
        }
    }
    gemm_epilogue<XEPI>(acc, bias, resid, C, M, Nld, m0, n0, wm, wn, g, tg);
}

// =============================================================================
// fp16 1-term GEMM core, BM=128, fp16 A in global (MoE path).
// XEPI: 0 = bias (fp32 out), 2 = bias+silu (fp16 out).
// =============================================================================
static __device__ __forceinline__ void store_stage_f16(
    uint32_t* base, uint4 ra, float4 rb0v, float4 rb1v,
    int arow, int paw, int pr, int bc)
{
    base[arow*ASTRH + paw]     = ra.x;
    base[arow*ASTRH + paw + 1] = ra.y;
    base[arow*ASTRH + paw + 2] = ra.z;
    base[arow*ASTRH + paw + 3] = ra.w;
    uint32_t hp[4];
    hp[0] = packhf2(rb0v.x, rb1v.x);
    hp[1] = packhf2(rb0v.y, rb1v.y);
    hp[2] = packhf2(rb0v.z, rb1v.z);
    hp[3] = packhf2(rb0v.w, rb1v.w);
    *(uint4*)&base[FAPLANE + pr*BSTRH + bc] = make_uint4(hp[0], hp[1], hp[2], hp[3]);
}

template<int XEPI, int XGATHER>
static __device__ __forceinline__ void gemm_core_f16(
    uint32_t* Fsm,
    const __half* __restrict__ A, const float* __restrict__ B,
    const float* __restrict__ bias,
    float* __restrict__ C, __half* __restrict__ Ch,
    int M, int Nld, int K, int m0, int n0,
    const int* __restrict__ rowidx)
{
    int tid = threadIdx.x;
    int arow = tid >> 1;
    int ah0 = (tid & 1) * 8;
    int paw = (tid & 1) * 4;
    int r0 = m0 + arow;
    bool v0 = r0 < M;
    int gr0 = v0 ? (XGATHER ? rowidx[r0] : r0) : 0;
    const __half* Ar0 = A + (size_t)gr0 * K + ah0;
    int pr = tid >> 5;
    int bc = (tid & 31) * 4;
    const float* Bp0 = B + (size_t)(2*pr) * Nld + n0 + bc;
    const float* Bp1 = Bp0 + Nld;

    int lane = tid & 31, g = lane >> 2, tg = lane & 3;
    int wm = (tid >> 7) * 64;
    int wn = ((tid >> 5) & 3) * 32;

    float acc[4][4][4];
    #pragma unroll
    for (int i = 0; i < 4; i++)
        #pragma unroll
        for (int j = 0; j < 4; j++)
            #pragma unroll
            for (int c = 0; c < 4; c++) acc[i][j][c] = 0.f;

    uint4 ra    = v0 ? *(const uint4*)(Ar0) : make_uint4(0,0,0,0);
    float4 rb0v = *(const float4*)(Bp0);
    float4 rb1v = *(const float4*)(Bp1);
    store_stage_f16(Fsm, ra, rb0v, rb1v, arow, paw, pr, bc);
    __syncthreads();
    int cur = 0;

    for (int k0 = 0; k0 < K; k0 += BKT) {
        int kn = k0 + BKT;
        bool more = kn < K;
        if (more) {
            ra    = v0 ? *(const uint4*)(Ar0 + kn) : make_uint4(0,0,0,0);
            rb0v  = *(const float4*)(Bp0 + (size_t)kn * Nld);
            rb1v  = *(const float4*)(Bp1 + (size_t)kn * Nld);
        }
        const uint32_t* Ah = Fsm + cur * FSTAGE;
        const uint32_t* Bh = Ah + FAPLANE;

        uint32_t bh[4][2];
        #pragma unroll
        for (int j = 0; j < 4; j++) {
            int nb = wn + j*8 + g;
            bh[j][0] = Bh[tg*BSTRH + nb];       bh[j][1] = Bh[(tg+4)*BSTRH + nb];
        }
        #pragma unroll
        for (int i = 0; i < 4; i++) {
            int mb = wm + i*16 + g;
            uint32_t ah[4];
            ah[0] = Ah[mb*ASTRH + tg];       ah[1] = Ah[(mb+8)*ASTRH + tg];
            ah[2] = Ah[mb*ASTRH + tg+4];     ah[3] = Ah[(mb+8)*ASTRH + tg+4];
            #pragma unroll
            for (int j = 0; j < 4; j++) mma16f(acc[i][j], ah, bh[j]);
        }

        if (more) {
            store_stage_f16(Fsm + (cur ^ 1) * FSTAGE, ra, rb0v, rb1v, arow, paw, pr, bc);
            __syncthreads();
            cur ^= 1;
        }
    }

    #pragma unroll
    for (int i = 0; i < 4; i++) {
        int rr0 = m0 + wm + i*16 + g;
        int rr1 = rr0 + 8;
        #pragma unroll
        for (int j = 0; j < 4; j++) {
            int c = n0 + wn + j*8 + tg*2;
            float b0v = bias[c], b1v = bias[c+1];
            #pragma unroll
            for (int half2i = 0; half2i < 2; half2i++) {
                int rr = half2i ? rr1 : rr0;
                if (rr >= M) continue;
                float t0 = acc[i][j][half2i*2+0] + b0v;
                float t1 = acc[i][j][half2i*2+1] + b1v;
                if (XEPI == 2) {
                    t0 = t0 / (1.f + expf(-t0));
                    t1 = t1 / (1.f + expf(-t1));
                    *(half2*)&Ch[(size_t)rr*Nld + c] = __floats2half2_rn(t0, t1);
                } else {
                    float2 o; o.x = t0; o.y = t1;
                    *(float2*)&C[(size_t)rr*Nld + c] = o;
                }
            }
        }
    }
}

// ---- fused QKV: grid (12, 32) ------------------------------------------------
__global__ void __launch_bounds__(256) qkv_kernel(
    const float* __restrict__ h,
    const float* __restrict__ wq, const float* __restrict__ bq,
    const float* __restrict__ wk, const float* __restrict__ bk,
    const float* __restrict__ wv, const float* __restrict__ bv)
{
    __shared__ __align__(16) uint32_t Hsm[2*HSTAGE];
    int x = blockIdx.x, m0 = blockIdx.y * BM;
    if (x < 8)
        gemm_core_bf16<0>(Hsm, h, wq, bq, nullptr, g_q, S, 1024, 1024, m0, x*128);
    else if (x < 10)
        gemm_core_bf16<0>(Hsm, h, wk, bk, nullptr, g_k, S, 256, 1024, m0, (x-8)*128);
    else
        gemm_core_bf16<0>(Hsm, h, wv, bv, nullptr, g_v, S, 256, 1024, m0, (x-10)*128);
}

// ---- O-proj + residual: grid (8, 32) -----------------------------------------
__global__ void __launch_bounds__(256) oproj_kernel(
    const float* __restrict__ wo, const float* __restrict__ bo,
    const float* __restrict__ x)
{
    __shared__ __align__(16) uint32_t Hsm[2*HSTAGE];
    gemm_core_bf16<1>(Hsm, g_attn, wo, bo, x, g_x1, S, 1024, 1024,
                      blockIdx.y*BM, blockIdx.x*BN);
}

// ---- MoE expert GEMMs (fp16, BM=128, fp16 activations) ------------------------
__global__ void __launch_bounds__(256) moe1_kernel(
    const float* __restrict__ w1, const float* __restrict__ b1)
{
    int e = blockIdx.z;
    int M = g_cnt[e];
    int m0 = blockIdx.y * BMF;
    if (m0 >= M) return;
    int o = g_off[e];
    __shared__ __align__(16) uint32_t Fsm[2*FSTAGE];
    gemm_core_f16<2,1>(Fsm, g_h2h, w1 + (size_t)e*1024*512, b1 + (size_t)e*512,
                       nullptr, g_hmidh + (size_t)o*512, M, 512, 1024,
                       m0, blockIdx.x*BN, g_atok + o);
}

__global__ void __launch_bounds__(256) moe2_kernel(
    const float* __restrict__ w2, const float* __restrict__ b2)
{
    int e = blockIdx.z;
    int M = g_cnt[e];
    int m0 = blockIdx.y * BMF;
    if (m0 >= M) return;
    int o = g_off[e];
    __shared__ __align__(16) uint32_t Fsm[2*FSTAGE];
    gemm_core_f16<0,0>(Fsm, g_hmidh + (size_t)o*512, w2 + (size_t)e*512*1024,
                       b2 + (size_t)e*1024, g_y + (size_t)o*1024, nullptr,
                       M, 1024, 512, m0, blockIdx.x*BN, nullptr);
}

// =============================================================================
// sliding-window attention: smem-staged K/V window, lane-parallel scores.
// =============================================================================
#define AROWS 72
#define ASTRIDE 132
#define ATTN_SMEM ((2*AROWS*ASTRIDE + 8*ASTRIDE) * 4)

__global__ void __launch_bounds__(256) attn_kernel(const float* __restrict__ sinkp) {
    extern __shared__ float sm[];
    float* sK = sm;
    float* sV = sm + AROWS*ASTRIDE;
    float* sQ = sm + 2*AROWS*ASTRIDE;
    int tid = threadIdx.x, warp = tid >> 5, lane = tid & 31;
    int b = blockIdx.x, h = blockIdx.y, kvh = h >> 2;
    int i0 = b * 8;
    int jmin = (i0 >= (WS-1)) ? (i0 - (WS-1)) : 0;
    int nrows = (i0 + 8) - jmin;

    for (int idx = tid; idx < nrows * 32; idx += 256) {
        int r = idx >> 5, c = idx & 31;
        const float* kp = g_k + (size_t)(jmin + r) * (NKV*HD) + kvh*HD + c*4;
        const float* vp = g_v + (size_t)(jmin + r) * (NKV*HD) + kvh*HD + c*4;
        *(float4*)(sK + r*ASTRIDE + c*4) = *(const float4*)kp;
        *(float4*)(sV + r*ASTRIDE + c*4) = *(const float4*)vp;
    }
    for (int idx = tid; idx < 8 * 32; idx += 256) {
        int r = idx >> 5, c = idx & 31;
        *(float4*)(sQ + r*ASTRIDE + c*4) =
            *(const float4*)(g_q + (size_t)(i0 + r) * D + h*HD + c*4);
    }
    __syncthreads();

    int i = i0 + warp;
    int jstart = (i >= (WS-1)) ? (i - (WS-1)) : 0;
    int cnt = i - jstart + 1;
    int base = jstart - jmin;
    const float scale = 0.08838834764831845f;

    float s0 = -1e30f, s1 = -1e30f;
    {
        bool u0 = lane < cnt, u1 = (32 + lane) < cnt;
        const float* q  = sQ + warp * ASTRIDE;
        const float* k0 = sK + (base + lane) * ASTRIDE;
        const float* k1 = sK + (base + 32 + lane) * ASTRIDE;
        float a0=0.f,a1=0.f,a2=0.f,a3=0.f, c0=0.f,c1=0.f,c2=0.f,c3=0.f;
        #pragma unroll 8
        for (int c4 = 0; c4 < 32; c4++) {
            float4 q4  = *(const float4*)(q  + c4*4);
            float4 k04 = *(const float4*)(k0 + c4*4);
            float4 k14 = *(const float4*)(k1 + c4*4);
            a0 += q4.x*k04.x; a1 += q4.y*k04.y; a2 += q4.z*k04.z; a3 += q4.w*k04.w;
            c0 += q4.x*k14.x; c1 += q4.y*k14.y; c2 += q4.z*k14.z; c3 += q4.w*k14.w;
        }
        if (u0) s0 = ((a0+a1) + (a2+a3)) * scale;
        if (u1) s1 = ((c0+c1) + (c2+c3)) * scale;
    }

    float sink = *sinkp;
    float m = fmaxf(s0, s1);
    #pragma unroll
    for (int s = 16; s; s >>= 1) m = fmaxf(m, __shfl_xor_sync(0xffffffffu, m, s));
    m = fmaxf(m, sink);
    float e0 = expf(s0 - m), e1 = expf(s1 - m);
    float dsum = e0 + e1;
    #pragma unroll
    for (int s = 16; s; s >>= 1) dsum += __shfl_xor_sync(0xffffffffu, dsum, s);
    dsum += expf(sink - m);
    float inv = 1.f / dsum;

    float o0 = 0.f, o1 = 0.f, o2 = 0.f, o3 = 0.f;
    for (int jj = 0; jj < cnt; ++jj) {
        float pv = (jj < 32) ? e0 : e1;
        float p = __shfl_sync(0xffffffffu, pv, jj & 31);
        const float* vr = sV + (base + jj) * ASTRIDE;
        o0 += p * vr[lane];      o1 += p * vr[lane + 32];
        o2 += p * vr[lane + 64]; o3 += p * vr[lane + 96];
    }
    float* op = g_attn + (size_t)i * D + h * HD;
    op[lane]      = o0 * inv; op[lane + 32] = o1 * inv;
    op[lane + 64] = o2 * inv; op[lane + 96] = o3 * inv;
}

// ---------------- router: 1 warp = 1 token ----------------------------------
__global__ void router_kernel(const float* __restrict__ rw, const float* __restrict__ rb) {
    int warp = threadIdx.x >> 5, lane = threadIdx.x & 31;
    int t = blockIdx.x * 8 + warp;
    float acc[NE];
    #pragma unroll
    for (int e = 0; e < NE; e++) acc[e] = 0.f;
    const float* xr = g_h2 + (size_t)t * D;
    for (int d = lane; d < D; d += 32) {
        float xv = xr[d];
        const float* rr = rw + d * NE;
        #pragma unroll
        for (int e = 0; e < NE; e++) acc[e] += xv * rr[e];
    }
    #pragma unroll
    for (int e = 0; e < NE; e++) {
        float a = acc[e];
        #pragma unroll
        for (int s = 16; s; s >>= 1) a += __shfl_xor_sync(0xffffffffu, a, s);
        acc[e] = a;
    }
    if (lane == 0) {
        float logit[NE]; float m = -1e30f;
        #pragma unroll
        for (int e = 0; e < NE; e++) { logit[e] = (acc[e] + rb[e]) * 10.f; m = fmaxf(m, logit[e]); }
        float pe[NE]; float ssum = 0.f;
        #pragma unroll
        for (int e = 0; e < NE; e++) { pe[e] = expf(logit[e] - m); ssum += pe[e]; }
        float invs = 1.f / ssum;
        #pragma unroll
        for (int e = 0; e < NE; e++) g_probs[t * NE + e] = pe[e] * invs;
        int i0 = 0; float v0 = logit[0];
        #pragma unroll
        for (int e = 1; e < NE; e++) if (logit[e] > v0) { v0 = logit[e]; i0 = e; }
        int i1 = -1; float v1 = -1e30f;
        #pragma unroll
        for (int e = 0; e < NE; e++) if (e != i0 && logit[e] > v1) { v1 = logit[e]; i1 = e; }
        float ex = expf(v1 - v0);
        float w0 = 1.f / (1.f + ex);
        g_topi[t*2] = i0; g_topi[t*2+1] = i1;
        g_topw[t*2] = w0; g_topw[t*2+1] = 1.f - w0;
        atomicAdd(&g_cnt[i0], 1); atomicAdd(&g_cnt[i1], 1);
    }
}

__global__ void zero_kernel() {
    int t = threadIdx.x;
    if (t < NE) { g_cnt[t] = 0; g_cur[t] = 0; }
}

// offsets + place merged: one block, 1024 threads, 2 tokens each
__global__ void place_kernel() {
    if (threadIdx.x == 0) {
        int s = 0;
        for (int e = 0; e < NE; e++) { g_off[e] = s; s += g_cnt[e]; }
    }
    __syncthreads();
    #pragma unroll
    for (int half = 0; half < 2; half++) {
        int t = threadIdx.x + half * 1024;
        #pragma unroll
        for (int k2 = 0; k2 < 2; k2++) {
            int e = g_topi[t*2 + k2];
            int slot = g_off[e] + atomicAdd(&g_cur[e], 1);
            g_atok[slot] = t;
            g_aw[slot] = g_topw[t*2 + k2];
            g_tslot[t*2 + k2] = slot;
        }
    }
}

__global__ void colsum_kernel() {
    int e = blockIdx.x; int tid = threadIdx.x;
    float s = 0.f;
    for (int t = tid; t < S; t += 256) s += g_probs[t * NE + e];
    __shared__ float red[256];
    red[tid] = s; __syncthreads();
    for (int st = 128; st; st >>= 1) { if (tid < st) red[tid] += red[tid + st]; __syncthreads(); }
    if (tid == 0) g_colsum[e] = red[0];
}

__global__ void combine_kernel(float* __restrict__ out) {
    int t = blockIdx.x; int c = threadIdx.x;
    int s0 = g_tslot[t*2], s1 = g_tslot[t*2+1];
    float w0 = g_aw[s0], w1 = g_aw[s1];
    const float4* x14 = (const float4*)(g_x1 + (size_t)t * D);
    const float4* y0  = (const float4*)(g_y + (size_t)s0 * D);
    const float4* y1  = (const float4*)(g_y + (size_t)s1 * D);
    float4 a = x14[c], b = y0[c], d2 = y1[c];
    float4 o;
    o.x = a.x + w0*b.x + w1*d2.x; o.y = a.y + w0*b.y + w1*d2.y;
    o.z = a.z + w0*b.z + w1*d2.z; o.w = a.w + w0*b.w + w1*d2.w;
    ((float4*)out)[(size_t)t * (D/4) + c] = o;
}

__global__ void aux_kernel(float* __restrict__ out, int out_size) {
    int tid = threadIdx.x;
    float v = (tid < NE) ? g_colsum[tid] * g_colsum[tid] : 0.f;
    #pragma unroll
    for (int s = 16; s; s >>= 1) v += __shfl_xor_sync(0xffffffffu, v, s);
    if (tid == 0) {
        float aux = v * (1.0f / (float)NE) * 1e-5f;
        for (int idx = S * D; idx < out_size; ++idx) out[idx] = aux;
    }
}

// ---------------- launch -----------------------------------------------------
extern "C" void kernel_launch(void* const* d_in, const int* in_sizes, int n_in,
                              void* d_out, int out_size) {
    const float* x    = (const float*)d_in[0];
    const float* n1w  = (const float*)d_in[1];
    const float* wq   = (const float*)d_in[2];
    const float* bq   = (const float*)d_in[3];
    const float* wk   = (const float*)d_in[4];
    const float* bk   = (const float*)d_in[5];
    const float* wv   = (const float*)d_in[6];
    const float* bv   = (const float*)d_in[7];
    const float* wo   = (const float*)d_in[8];
    const float* bo   = (const float*)d_in[9];
    const float* sink = (const float*)d_in[10];
    const float* n2w  = (const float*)d_in[11];
    const float* rw   = (const float*)d_in[12];
    const float* rb   = (const float*)d_in[13];
    const float* w1   = (const float*)d_in[14];
    const float* b1   = (const float*)d_in[15];
    const float* w2   = (const float*)d_in[16];
    const float* b2   = (const float*)d_in[17];
    float* out = (float*)d_out;

    void* p;
    cudaGetSymbolAddress(&p, g_h);    float* hB    = (float*)p;
    cudaGetSymbolAddress(&p, g_x1);   float* x1B   = (float*)p;
    cudaGetSymbolAddress(&p, g_h2);   float* h2B   = (float*)p;
    cudaGetSymbolAddress(&p, g_h2h);  __half* h2hB = (__half*)p;

    cudaFuncSetAttribute(attn_kernel, cudaFuncAttributeMaxDynamicSharedMemorySize, ATTN_SMEM);

    // 1) RMSNorm1
    rmsnorm_kernel<<<S, 256>>>(x, n1w, hB, nullptr);

    // 2) fused QKV projections (bf16 3-term tensor cores)
    qkv_kernel<<<dim3(12, 32), 256>>>(hB, wq, bq, wk, bk, wv, bv);

    // 3) sliding-window attention (smem-staged window)
    attn_kernel<<<dim3(S/8, NH), 256, ATTN_SMEM>>>(sink);

    // 4) O-proj + residual
    oproj_kernel<<<dim3(8, 32), 256>>>(wo, bo, x);

    // 5) RMSNorm2 (fp32 + fp16 planes)
    rmsnorm_kernel<<<S, 256>>>(x1B, n2w, h2B, h2hB);

    // 6) router + grouping
    zero_kernel<<<1, 32>>>();
    router_kernel<<<S/8, 256>>>(rw, rb);
    place_kernel<<<1, 1024>>>();
    colsum_kernel<<<NE, 256>>>();

    // 7) grouped MoE GEMMs (top-2 only, fp16, BM=128, fp16 activations)
    moe1_kernel<<<dim3(4, 16, NE), 256>>>(w1, b1);
    moe2_kernel<<<dim3(8, 16, NE), 256>>>(w2, b2);

    // 8) combine + residual, aux loss
    combine_kernel<<<S, 256>>>(out);
    aux_kernel<<<1, 32>>>(out, out_size);
}

// round 16
// speedup vs baseline: 1.1835x; 1.0094x over previous
#include <cuda_runtime.h>
#include <cuda_fp16.h>
#include <math.h>
#include <stdint.h>

#define S 2048
#define D 1024
#define NH 8
#define NKV 2
#define HD 128
#define WS 64
#define NE 16
#define HDIM 512
#define NA (S*2)

// ---------------- scratch (static device globals; no allocation) ------------
__device__ float g_h[S*D];
__device__ float g_q[S*D];
__device__ float g_k[S*NKV*HD];
__device__ float g_v[S*NKV*HD];
__device__ float g_attn[S*D];
__device__ float g_x1[S*D];
__device__ float g_h2[S*D];
__device__ __half g_h2h[S*D];
__device__ __half g_hmidh[NA*HDIM];
__device__ float g_probs[S*NE];
__device__ float g_topw[S*2];
__device__ int   g_topi[S*2];
__device__ int   g_cnt[NE];
__device__ int   g_off[NE];
__device__ int   g_cur[NE];
__device__ int   g_atok[NA];
__device__ float g_aw[NA];
__device__ int   g_tslot[S*2];
__device__ float g_y[NA*D];
__device__ float g_colsum[NE];

// ---------------- RMSNorm (optional fp16 copy of output) --------------------
__global__ void rmsnorm_kernel(const float* __restrict__ x,
                               const float* __restrict__ w,
                               float* __restrict__ o,
                               __half* __restrict__ oh) {
    int row = blockIdx.x;
    int tid = threadIdx.x;
    const float4* x4 = (const float4*)(x + (size_t)row * D);
    float4 v = x4[tid];
    float ss = v.x*v.x + v.y*v.y + v.z*v.z + v.w*v.w;
    __shared__ float red[8];
    #pragma unroll
    for (int s = 16; s; s >>= 1) ss += __shfl_xor_sync(0xffffffffu, ss, s);
    if ((tid & 31) == 0) red[tid >> 5] = ss;
    __syncthreads();
    if (tid < 32) {
        float t = (tid < 8) ? red[tid] : 0.f;
        #pragma unroll
        for (int s = 4; s; s >>= 1) t += __shfl_xor_sync(0xffffffffu, t, s);
        if (tid == 0) red[0] = t;
    }
    __syncthreads();
    float r = rsqrtf(red[0] * (1.0f / (float)D) + 1e-6f);
    const float4* w4 = (const float4*)w;
    float4 wv = w4[tid];
    float4 out;
    out.x = v.x * r * wv.x; out.y = v.y * r * wv.y;
    out.z = v.z * r * wv.z; out.w = v.w * r * wv.w;
    ((float4*)(o + (size_t)row * D))[tid] = out;
    if (oh) {
        half2 h0 = __floats2half2_rn(out.x, out.y);
        half2 h1 = __floats2half2_rn(out.z, out.w);
        *(half2*)&oh[(size_t)row * D + tid*4]     = h0;
        *(half2*)&oh[(size_t)row * D + tid*4 + 2] = h1;
    }
}

// =============================================================================
// GEMM geometry: CTA 64x128x16, 8 warps, warp 32x32.
// Attention path: bf16 3-term split (~fp32 accuracy).
// MoE path: fp16 1-term, fp16 activations, BM=64 (more live CTAs).
// =============================================================================
#define BM 64
#define BN 128
#define BKT 16

#define ASTRH 12
#define BSTRH 136
#define APLANEH (BM*ASTRH)       // 768 words
#define BPLANEH (8*BSTRH)        // 1088 words
#define HSTAGE (2*APLANEH + 2*BPLANEH)   // 3712 words (bf16 3-term)
#define FSTAGE (APLANEH + BPLANEH)       // 1856 words (fp16 1-term)

static __device__ __forceinline__ uint32_t packbf2(float lo_k, float hi_k) {
    uint32_t r; asm("cvt.rn.bf16x2.f32 %0, %1, %2;" : "=r"(r) : "f"(hi_k), "f"(lo_k));
    return r;
}
static __device__ __forceinline__ uint32_t packhf2(float lo_k, float hi_k) {
    uint32_t r; asm("cvt.rn.f16x2.f32 %0, %1, %2;" : "=r"(r) : "f"(hi_k), "f"(lo_k));
    return r;
}
static __device__ __forceinline__ void mma16(float* d, const uint32_t* a, const uint32_t* b) {
    asm volatile("mma.sync.aligned.m16n8k16.row.col.f32.bf16.bf16.f32 "
        "{%0,%1,%2,%3}, {%4,%5,%6,%7}, {%8,%9}, {%0,%1,%2,%3};\n"
        : "+f"(d[0]), "+f"(d[1]), "+f"(d[2]), "+f"(d[3])
        : "r"(a[0]), "r"(a[1]), "r"(a[2]), "r"(a[3]), "r"(b[0]), "r"(b[1]));
}
static __device__ __forceinline__ void mma16f(float* d, const uint32_t* a, const uint32_t* b) {
    asm volatile("mma.sync.aligned.m16n8k16.row.col.f32.f16.f16.f32 "
        "{%0,%1,%2,%3}, {%4,%5,%6,%7}, {%8,%9}, {%0,%1,%2,%3};\n"
        : "+f"(d[0]), "+f"(d[1]), "+f"(d[2]), "+f"(d[3])
        : "r"(a[0]), "r"(a[1]), "r"(a[2]), "r"(a[3]), "r"(b[0]), "r"(b[1]));
}

// shared fp32 epilogue (2 row-tiles): bias [+resid], write C
template<int XEPI>
static __device__ __forceinline__ void gemm_epilogue(
    float acc[2][4][4], const float* __restrict__ bias, const float* __restrict__ resid,
    float* __restrict__ C, int M, int Nld, int m0, int n0, int wm, int wn, int g, int tg)
{
    #pragma unroll
    for (int i = 0; i < 2; i++) {
        int rr0 = m0 + wm + i*16 + g;
        int rr1 = rr0 + 8;
        #pragma unroll
        for (int j = 0; j < 4; j++) {
            int c = n0 + wn + j*8 + tg*2;
            float b0v = bias[c], b1v = bias[c+1];
            if (rr0 < M) {
                float t0 = acc[i][j][0] + b0v;
                float t1 = acc[i][j][1] + b1v;
                if (XEPI == 1) {
                    t0 += resid[(size_t)rr0*Nld + c];
                    t1 += resid[(size_t)rr0*Nld + c + 1];
                }
                float2 o; o.x = t0; o.y = t1;
                *(float2*)&C[(size_t)rr0*Nld + c] = o;
            }
            if (rr1 < M) {
                float t0 = acc[i][j][2] + b0v;
                float t1 = acc[i][j][3] + b1v;
                if (XEPI == 1) {
                    t0 += resid[(size_t)rr1*Nld + c];
                    t1 += resid[(size_t)rr1*Nld + c + 1];
                }
                float2 o; o.x = t0; o.y = t1;
                *(float2*)&C[(size_t)rr1*Nld + c] = o;
            }
        }
    }
}

// =============================================================================
// bf16 3-term split GEMM core (attention path)
// =============================================================================
static __device__ __forceinline__ void store_stage_bf16(
    uint32_t* base, float4 ra, float4 rb0v, float4 rb1v,
    int arow, int pa0, int pr, int bc)
{
    uint32_t p0 = packbf2(ra.x, ra.y);
    uint32_t p1 = packbf2(ra.z, ra.w);
    base[arow*ASTRH + pa0]     = p0;
    base[arow*ASTRH + pa0 + 1] = p1;
    float l0 = ra.x - __uint_as_float(p0 << 16);
    float l1 = ra.y - __uint_as_float(p0 & 0xffff0000u);
    float l2 = ra.z - __uint_as_float(p1 << 16);
    float l3 = ra.w - __uint_as_float(p1 & 0xffff0000u);
    base[APLANEH + arow*ASTRH + pa0]     = packbf2(l0, l1);
    base[APLANEH + arow*ASTRH + pa0 + 1] = packbf2(l2, l3);
    float b0a[4] = {rb0v.x, rb0v.y, rb0v.z, rb0v.w};
    float b1a[4] = {rb1v.x, rb1v.y, rb1v.z, rb1v.w};
    uint32_t hp[4], lp[4];
    #pragma unroll
    for (int j = 0; j < 4; j++) {
        uint32_t h = packbf2(b0a[j], b1a[j]);
        hp[j] = h;
        float ll0 = b0a[j] - __uint_as_float(h << 16);
        float ll1 = b1a[j] - __uint_as_float(h & 0xffff0000u);
        lp[j] = packbf2(ll0, ll1);
    }
    *(uint4*)&base[2*APLANEH + pr*BSTRH + bc] = make_uint4(hp[0], hp[1], hp[2], hp[3]);
    *(uint4*)&base[2*APLANEH + BPLANEH + pr*BSTRH + bc] = make_uint4(lp[0], lp[1], lp[2], lp[3]);
}

template<int XEPI>
static __device__ __forceinline__ void gemm_core_bf16(
    uint32_t* Hsm,
    const float* __restrict__ A, const float* __restrict__ B,
    const float* __restrict__ bias, const float* __restrict__ resid,
    float* __restrict__ C, int M, int Nld, int K, int m0, int n0)
{
    int tid = threadIdx.x;
    int arow = tid >> 2;
    int ac = (tid & 3) * 4;
    int pa0 = (tid & 3) * 2;
    int r0 = m0 + arow;
    bool v0 = r0 < M;
    const float* Ar0 = A + (size_t)(v0 ? r0 : 0) * K;
    int pr = tid >> 5;
    int bc = (tid & 31) * 4;
    const float* Bp0 = B + (size_t)(2*pr) * Nld + n0 + bc;
    const float* Bp1 = Bp0 + Nld;

    int lane = tid & 31, g = lane >> 2, tg = lane & 3;
    int wm = (tid >> 7) * 32;
    int wn = ((tid >> 5) & 3) * 32;

    float acc[2][4][4];
    #pragma unroll
    for (int i = 0; i < 2; i++)
        #pragma unroll
        for (int j = 0; j < 4; j++)
            #pragma unroll
            for (int c = 0; c < 4; c++) acc[i][j][c] = 0.f;

    float4 ra   = v0 ? *(const float4*)(Ar0 + ac) : make_float4(0.f,0.f,0.f,0.f);
    float4 rb0v = *(const float4*)(Bp0);
    float4 rb1v = *(const float4*)(Bp1);
    store_stage_bf16(Hsm, ra, rb0v, rb1v, arow, pa0, pr, bc);
    __syncthreads();
    int cur = 0;

    for (int k0 = 0; k0 < K; k0 += BKT) {
        int kn = k0 + BKT;
        bool more = kn < K;
        if (more) {
            ra   = v0 ? *(const float4*)(Ar0 + kn + ac) : make_float4(0.f,0.f,0.f,0.f);
            rb0v = *(const float4*)(Bp0 + (size_t)kn * Nld);
            rb1v = *(const float4*)(Bp1 + (size_t)kn * Nld);
        }
        const uint32_t* Ah = Hsm + cur * HSTAGE;
        const uint32_t* Al = Ah + APLANEH;
        const uint32_t* Bh = Ah + 2*APLANEH;
        const uint32_t* Bl = Bh + BPLANEH;

        uint32_t ah[2][4], al[2][4], bh[4][2], bl[4][2];
        #pragma unroll
        for (int i = 0; i < 2; i++) {
            int mb = wm + i*16 + g;
            ah[i][0] = Ah[mb*ASTRH + tg];       ah[i][1] = Ah[(mb+8)*ASTRH + tg];
            ah[i][2] = Ah[mb*ASTRH + tg+4];     ah[i][3] = Ah[(mb+8)*ASTRH + tg+4];
            al[i][0] = Al[mb*ASTRH + tg];       al[i][1] = Al[(mb+8)*ASTRH + tg];
            al[i][2] = Al[mb*ASTRH + tg+4];     al[i][3] = Al[(mb+8)*ASTRH + tg+4];
        }
        #pragma unroll
        for (int j = 0; j < 4; j++) {
            int nb = wn + j*8 + g;
            bh[j][0] = Bh[tg*BSTRH + nb];       bh[j][1] = Bh[(tg+4)*BSTRH + nb];
            bl[j][0] = Bl[tg*BSTRH + nb];       bl[j][1] = Bl[(tg+4)*BSTRH + nb];
        }
        #pragma unroll
        for (int i = 0; i < 2; i++)
            #pragma unroll
            for (int j = 0; j < 4; j++) mma16(acc[i][j], ah[i], bh[j]);
        #pragma unroll
        for (int i = 0; i < 2; i++)
            #pragma unroll
            for (int j = 0; j < 4; j++) mma16(acc[i][j], ah[i], bl[j]);
        #pragma unroll
        for (int i = 0; i < 2; i++)
            #pragma unroll
            for (int j = 0; j < 4; j++) mma16(acc[i][j], al[i], bh[j]);

        if (more) {
            store_stage_bf16(Hsm + (cur ^ 1) * HSTAGE, ra, rb0v, rb1v, arow, pa0, pr, bc);
            __syncthreads();
            cur ^= 1;
        }
    }
    gemm_epilogue<XEPI>(acc, bias, resid, C, M, Nld, m0, n0, wm, wn, g, tg);
}

// =============================================================================
// fp16 1-term GEMM core, BM=64, fp16 A in global (MoE path).
// XEPI: 0 = bias (fp32 out), 2 = bias+silu (fp16 out).
// =============================================================================
static __device__ __forceinline__ void store_stage_f16(
    uint32_t* base, uint2 ra, float4 rb0v, float4 rb1v,
    int arow, int kw, int pr, int bc)
{
    base[arow*ASTRH + kw]     = ra.x;
    base[arow*ASTRH + kw + 1] = ra.y;
    uint32_t hp[4];
    hp[0] = packhf2(rb0v.x, rb1v.x);
    hp[1] = packhf2(rb0v.y, rb1v.y);
    hp[2] = packhf2(rb0v.z, rb1v.z);
    hp[3] = packhf2(rb0v.w, rb1v.w);
    *(uint4*)&base[APLANEH + pr*BSTRH + bc] = make_uint4(hp[0], hp[1], hp[2], hp[3]);
}

template<int XEPI, int XGATHER>
static __device__ __forceinline__ void gemm_core_f16(
    uint32_t* Fsm,
    const __half* __restrict__ A, const float* __restrict__ B,
    const float* __restrict__ bias,
    float* __restrict__ C, __half* __restrict__ Ch,
    int M, int Nld, int K, int m0, int n0,
    const int* __restrict__ rowidx)
{
    int tid = threadIdx.x;
    int arow = tid >> 2;             // 0..63
    int kw = (tid & 3) * 2;          // word offset in smem row
    int r0 = m0 + arow;
    bool v0 = r0 < M;
    int gr0 = v0 ? (XGATHER ? rowidx[r0] : r0) : 0;
    const __half* Ar0 = A + (size_t)gr0 * K + (tid & 3) * 4;
    int pr = tid >> 5;
    int bc = (tid & 31) * 4;
    const float* Bp0 = B + (size_t)(2*pr) * Nld + n0 + bc;
    const float* Bp1 = Bp0 + Nld;

    int lane = tid & 31, g = lane >> 2, tg = lane & 3;
    int wm = (tid >> 7) * 32;
    int wn = ((tid >> 5) & 3) * 32;

    float acc[2][4][4];
    #pragma unroll
    for (int i = 0; i < 2; i++)
        #pragma unroll
        for (int j = 0; j < 4; j++)
            #pragma unroll
            for (int c = 0; c < 4; c++) acc[i][j][c] = 0.f;

    uint2 ra    = v0 ? *(const uint2*)(Ar0) : make_uint2(0, 0);
    float4 rb0v = *(const float4*)(Bp0);
    float4 rb1v = *(const float4*)(Bp1);
    store_stage_f16(Fsm, ra, rb0v, rb1v, arow, kw, pr, bc);
    __syncthreads();
    int cur = 0;

    for (int k0 = 0; k0 < K; k0 += BKT) {
        int kn = k0 + BKT;
        bool more = kn < K;
        if (more) {
            ra    = v0 ? *(const uint2*)(Ar0 + kn) : make_uint2(0, 0);
            rb0v  = *(const float4*)(Bp0 + (size_t)kn * Nld);
            rb1v  = *(const float4*)(Bp1 + (size_t)kn * Nld);
        }
        const uint32_t* Ah = Fsm + cur * FSTAGE;
        const uint32_t* Bh = Ah + APLANEH;

        uint32_t ah[2][4], bh[4][2];
        #pragma unroll
        for (int i = 0; i < 2; i++) {
            int mb = wm + i*16 + g;
            ah[i][0] = Ah[mb*ASTRH + tg];       ah[i][1] = Ah[(mb+8)*ASTRH + tg];
            ah[i][2] = Ah[mb*ASTRH + tg+4];     ah[i][3] = Ah[(mb+8)*ASTRH + tg+4];
        }
        #pragma unroll
        for (int j = 0; j < 4; j++) {
            int nb = wn + j*8 + g;
            bh[j][0] = Bh[tg*BSTRH + nb];       bh[j][1] = Bh[(tg+4)*BSTRH + nb];
        }
        #pragma unroll
        for (int i = 0; i < 2; i++)
            #pragma unroll
            for (int j = 0; j < 4; j++) mma16f(acc[i][j], ah[i], bh[j]);

        if (more) {
            store_stage_f16(Fsm + (cur ^ 1) * FSTAGE, ra, rb0v, rb1v, arow, kw, pr, bc);
            __syncthreads();
            cur ^= 1;
        }
    }

    #pragma unroll
    for (int i = 0; i < 2; i++) {
        int rr0 = m0 + wm + i*16 + g;
        int rr1 = rr0 + 8;
        #pragma unroll
        for (int j = 0; j < 4; j++) {
            int c = n0 + wn + j*8 + tg*2;
            float b0v = bias[c], b1v = bias[c+1];
            #pragma unroll
            for (int hh = 0; hh < 2; hh++) {
                int rr = hh ? rr1 : rr0;
                if (rr >= M) continue;
                float t0 = acc[i][j][hh*2+0] + b0v;
                float t1 = acc[i][j][hh*2+1] + b1v;
                if (XEPI == 2) {
                    t0 = t0 / (1.f + expf(-t0));
                    t1 = t1 / (1.f + expf(-t1));
                    *(half2*)&Ch[(size_t)rr*Nld + c] = __floats2half2_rn(t0, t1);
                } else {
                    float2 o; o.x = t0; o.y = t1;
                    *(float2*)&C[(size_t)rr*Nld + c] = o;
                }
            }
        }
    }
}

// ---- fused QKV: grid (12, 32) ------------------------------------------------
__global__ void __launch_bounds__(256) qkv_kernel(
    const float* __restrict__ h,
    const float* __restrict__ wq, const float* __restrict__ bq,
    const float* __restrict__ wk, const float* __restrict__ bk,
    const float* __restrict__ wv, const float* __restrict__ bv)
{
    __shared__ __align__(16) uint32_t Hsm[2*HSTAGE];
    int x = blockIdx.x, m0 = blockIdx.y * BM;
    if (x < 8)
        gemm_core_bf16<0>(Hsm, h, wq, bq, nullptr, g_q, S, 1024, 1024, m0, x*128);
    else if (x < 10)
        gemm_core_bf16<0>(Hsm, h, wk, bk, nullptr, g_k, S, 256, 1024, m0, (x-8)*128);
    else
        gemm_core_bf16<0>(Hsm, h, wv, bv, nullptr, g_v, S, 256, 1024, m0, (x-10)*128);
}

// ---- O-proj + residual: grid (8, 32) -----------------------------------------
__global__ void __launch_bounds__(256) oproj_kernel(
    const float* __restrict__ wo, const float* __restrict__ bo,
    const float* __restrict__ x)
{
    __shared__ __align__(16) uint32_t Hsm[2*HSTAGE];
    gemm_core_bf16<1>(Hsm, g_attn, wo, bo, x, g_x1, S, 1024, 1024,
                      blockIdx.y*BM, blockIdx.x*BN);
}

// ---- MoE expert GEMMs (fp16, BM=64, fp16 activations) -------------------------
__global__ void __launch_bounds__(256) moe1_kernel(
    const float* __restrict__ w1, const float* __restrict__ b1)
{
    int e = blockIdx.z;
    int M = g_cnt[e];
    int m0 = blockIdx.y * BM;
    if (m0 >= M) return;
    int o = g_off[e];
    __shared__ __align__(16) uint32_t Fsm[2*FSTAGE];
    gemm_core_f16<2,1>(Fsm, g_h2h, w1 + (size_t)e*1024*512, b1 + (size_t)e*512,
                       nullptr, g_hmidh + (size_t)o*512, M, 512, 1024,
                       m0, blockIdx.x*BN, g_atok + o);
}

__global__ void __launch_bounds__(256) moe2_kernel(
    const float* __restrict__ w2, const float* __restrict__ b2)
{
    int e = blockIdx.z;
    int M = g_cnt[e];
    int m0 = blockIdx.y * BM;
    if (m0 >= M) return;
    int o = g_off[e];
    __shared__ __align__(16) uint32_t Fsm[2*FSTAGE];
    gemm_core_f16<0,0>(Fsm, g_hmidh + (size_t)o*512, w2 + (size_t)e*512*1024,
                       b2 + (size_t)e*1024, g_y + (size_t)o*1024, nullptr,
                       M, 1024, 512, m0, blockIdx.x*BN, nullptr);
}

// =============================================================================
// sliding-window attention: K/V window staged ONCE per kv-head, shared by the
// 4 query heads of the group. block = 8 queries x 1 kvh; warp = 1 query x 4 heads.
// =============================================================================
#define AROWS 72
#define ASTRIDE 132
#define ATTN_SMEM ((2*AROWS*ASTRIDE + 32*ASTRIDE) * 4)

__global__ void __launch_bounds__(256) attn_kernel(const float* __restrict__ sinkp) {
    extern __shared__ float sm[];
    float* sK = sm;
    float* sV = sm + AROWS*ASTRIDE;
    float* sQ = sm + 2*AROWS*ASTRIDE;      // [4 heads * 8 queries][ASTRIDE]
    int tid = threadIdx.x, warp = tid >> 5, lane = tid & 31;
    int b = blockIdx.x, kvh = blockIdx.y;
    int i0 = b * 8;
    int jmin = (i0 >= (WS-1)) ? (i0 - (WS-1)) : 0;
    int nrows = (i0 + 8) - jmin;

    // stage K,V window once for the whole kv-group
    for (int idx = tid; idx < nrows * 32; idx += 256) {
        int r = idx >> 5, c = idx & 31;
        const float* kp = g_k + (size_t)(jmin + r) * (NKV*HD) + kvh*HD + c*4;
        const float* vp = g_v + (size_t)(jmin + r) * (NKV*HD) + kvh*HD + c*4;
        *(float4*)(sK + r*ASTRIDE + c*4) = *(const float4*)kp;
        *(float4*)(sV + r*ASTRIDE + c*4) = *(const float4*)vp;
    }
    // stage Q rows for all 4 heads of this group
    for (int idx = tid; idx < 32 * 32; idx += 256) {
        int r = idx >> 5, c = idx & 31;       // r: h4*8 + q
        int h4 = r >> 3, q = r & 7;
        *(float4*)(sQ + r*ASTRIDE + c*4) =
            *(const float4*)(g_q + (size_t)(i0 + q) * D + (kvh*4 + h4)*HD + c*4);
    }
    __syncthreads();

    int i = i0 + warp;
    int jstart = (i >= (WS-1)) ? (i - (WS-1)) : 0;
    int cnt = i - jstart + 1;
    int base = jstart - jmin;
    const float scale = 0.08838834764831845f;
    float sink = *sinkp;
    bool u0 = lane < cnt, u1 = (32 + lane) < cnt;
    const float* k0 = sK + (base + lane) * ASTRIDE;
    const float* k1 = sK + (base + 32 + lane) * ASTRIDE;

    #pragma unroll
    for (int h4 = 0; h4 < 4; h4++) {
        const float* q = sQ + (h4*8 + warp) * ASTRIDE;
        float s0 = -1e30f, s1 = -1e30f;
        {
            float a0=0.f,a1=0.f,a2=0.f,a3=0.f, c0=0.f,c1=0.f,c2=0.f,c3=0.f;
            #pragma unroll 8
            for (int c4 = 0; c4 < 32; c4++) {
                float4 q4  = *(const float4*)(q  + c4*4);
                float4 k04 = *(const float4*)(k0 + c4*4);
                float4 k14 = *(const float4*)(k1 + c4*4);
                a0 += q4.x*k04.x; a1 += q4.y*k04.y; a2 += q4.z*k04.z; a3 += q4.w*k04.w;
                c0 += q4.x*k14.x; c1 += q4.y*k14.y; c2 += q4.z*k14.z; c3 += q4.w*k14.w;
            }
            if (u0) s0 = ((a0+a1) + (a2+a3)) * scale;
            if (u1) s1 = ((c0+c1) + (c2+c3)) * scale;
        }

        float m = fmaxf(s0, s1);
        #pragma unroll
        for (int s = 16; s; s >>= 1) m = fmaxf(m, __shfl_xor_sync(0xffffffffu, m, s));
        m = fmaxf(m, sink);
        float e0 = expf(s0 - m), e1 = expf(s1 - m);
        float dsum = e0 + e1;
        #pragma unroll
        for (int s = 16; s; s >>= 1) dsum += __shfl_xor_sync(0xffffffffu, dsum, s);
        dsum += expf(sink - m);
        float inv = 1.f / dsum;

        float o0 = 0.f, o1 = 0.f, o2 = 0.f, o3 = 0.f;
        for (int jj = 0; jj < cnt; ++jj) {
            float pv = (jj < 32) ? e0 : e1;
            float p = __shfl_sync(0xffffffffu, pv, jj & 31);
            const float* vr = sV + (base + jj) * ASTRIDE;
            o0 += p * vr[lane];      o1 += p * vr[lane + 32];
            o2 += p * vr[lane + 64]; o3 += p * vr[lane + 96];
        }
        float* op = g_attn + (size_t)i * D + (kvh*4 + h4) * HD;
        op[lane]      = o0 * inv; op[lane + 32] = o1 * inv;
        op[lane + 64] = o2 * inv; op[lane + 96] = o3 * inv;
    }
}

// ---------------- router: 1 warp = 1 token ----------------------------------
__global__ void router_kernel(const float* __restrict__ rw, const float* __restrict__ rb) {
    int warp = threadIdx.x >> 5, lane = threadIdx.x & 31;
    int t = blockIdx.x * 8 + warp;
    float acc[NE];
    #pragma unroll
    for (int e = 0; e < NE; e++) acc[e] = 0.f;
    const float* xr = g_h2 + (size_t)t * D;
    for (int d = lane; d < D; d += 32) {
        float xv = xr[d];
        const float* rr = rw + d * NE;
        #pragma unroll
        for (int e = 0; e < NE; e++) acc[e] += xv * rr[e];
    }
    #pragma unroll
    for (int e = 0; e < NE; e++) {
        float a = acc[e];
        #pragma unroll
        for (int s = 16; s; s >>= 1) a += __shfl_xor_sync(0xffffffffu, a, s);
        acc[e] = a;
    }
    if (lane == 0) {
        float logit[NE]; float m = -1e30f;
        #pragma unroll
        for (int e = 0; e < NE; e++) { logit[e] = (acc[e] + rb[e]) * 10.f; m = fmaxf(m, logit[e]); }
        float pe[NE]; float ssum = 0.f;
        #pragma unroll
        for (int e = 0; e < NE; e++) { pe[e] = expf(logit[e] - m); ssum += pe[e]; }
        float invs = 1.f / ssum;
        #pragma unroll
        for (int e = 0; e < NE; e++) g_probs[t * NE + e] = pe[e] * invs;
        int i0 = 0; float v0 = logit[0];
        #pragma unroll
        for (int e = 1; e < NE; e++) if (logit[e] > v0) { v0 = logit[e]; i0 = e; }
        int i1 = -1; float v1 = -1e30f;
        #pragma unroll
        for (int e = 0; e < NE; e++) if (e != i0 && logit[e] > v1) { v1 = logit[e]; i1 = e; }
        float ex = expf(v1 - v0);
        float w0 = 1.f / (1.f + ex);
        g_topi[t*2] = i0; g_topi[t*2+1] = i1;
        g_topw[t*2] = w0; g_topw[t*2+1] = 1.f - w0;
        atomicAdd(&g_cnt[i0], 1); atomicAdd(&g_cnt[i1], 1);
    }
}

__global__ void zero_kernel() {
    int t = threadIdx.x;
    if (t < NE) { g_cnt[t] = 0; g_cur[t] = 0; }
}

// offsets + place merged: one block, 1024 threads, 2 tokens each
__global__ void place_kernel() {
    if (threadIdx.x == 0) {
        int s = 0;
        for (int e = 0; e < NE; e++) { g_off[e] = s; s += g_cnt[e]; }
    }
    __syncthreads();
    #pragma unroll
    for (int half = 0; half < 2; half++) {
        int t = threadIdx.x + half * 1024;
        #pragma unroll
        for (int k2 = 0; k2 < 2; k2++) {
            int e = g_topi[t*2 + k2];
            int slot = g_off[e] + atomicAdd(&g_cur[e], 1);
            g_atok[slot] = t;
            g_aw[slot] = g_topw[t*2 + k2];
            g_tslot[t*2 + k2] = slot;
        }
    }
}

__global__ void colsum_kernel() {
    int e = blockIdx.x; int tid = threadIdx.x;
    float s = 0.f;
    for (int t = tid; t < S; t += 256) s += g_probs[t * NE + e];
    __shared__ float red[256];
    red[tid] = s; __syncthreads();
    for (int st = 128; st; st >>= 1) { if (tid < st) red[tid] += red[tid + st]; __syncthreads(); }
    if (tid == 0) g_colsum[e] = red[0];
}

__global__ void combine_kernel(float* __restrict__ out) {
    int t = blockIdx.x; int c = threadIdx.x;
    int s0 = g_tslot[t*2], s1 = g_tslot[t*2+1];
    float w0 = g_aw[s0], w1 = g_aw[s1];
    const float4* x14 = (const float4*)(g_x1 + (size_t)t * D);
    const float4* y0  = (const float4*)(g_y + (size_t)s0 * D);
    const float4* y1  = (const float4*)(g_y + (size_t)s1 * D);
    float4 a = x14[c], b = y0[c], d2 = y1[c];
    float4 o;
    o.x = a.x + w0*b.x + w1*d2.x; o.y = a.y + w0*b.y + w1*d2.y;
    o.z = a.z + w0*b.z + w1*d2.z; o.w = a.w + w0*b.w + w1*d2.w;
    ((float4*)out)[(size_t)t * (D/4) + c] = o;
}

__global__ void aux_kernel(float* __restrict__ out, int out_size) {
    int tid = threadIdx.x;
    float v = (tid < NE) ? g_colsum[tid] * g_colsum[tid] : 0.f;
    #pragma unroll
    for (int s = 16; s; s >>= 1) v += __shfl_xor_sync(0xffffffffu, v, s);
    if (tid == 0) {
        float aux = v * (1.0f / (float)NE) * 1e-5f;
        for (int idx = S * D; idx < out_size; ++idx) out[idx] = aux;
    }
}

// ---------------- launch -----------------------------------------------------
extern "C" void kernel_launch(void* const* d_in, const int* in_sizes, int n_in,
                              void* d_out, int out_size) {
    const float* x    = (const float*)d_in[0];
    const float* n1w  = (const float*)d_in[1];
    const float* wq   = (const float*)d_in[2];
    const float* bq   = (const float*)d_in[3];
    const float* wk   = (const float*)d_in[4];
    const float* bk   = (const float*)d_in[5];
    const float* wv   = (const float*)d_in[6];
    const float* bv   = (const float*)d_in[7];
    const float* wo   = (const float*)d_in[8];
    const float* bo   = (const float*)d_in[9];
    const float* sink = (const float*)d_in[10];
    const float* n2w  = (const float*)d_in[11];
    const float* rw   = (const float*)d_in[12];
    const float* rb   = (const float*)d_in[13];
    const float* w1   = (const float*)d_in[14];
    const float* b1   = (const float*)d_in[15];
    const float* w2   = (const float*)d_in[16];
    const float* b2   = (const float*)d_in[17];
    float* out = (float*)d_out;

    void* p;
    cudaGetSymbolAddress(&p, g_h);    float* hB    = (float*)p;
    cudaGetSymbolAddress(&p, g_x1);   float* x1B   = (float*)p;
    cudaGetSymbolAddress(&p, g_h2);   float* h2B   = (float*)p;
    cudaGetSymbolAddress(&p, g_h2h);  __half* h2hB = (__half*)p;

    cudaFuncSetAttribute(attn_kernel, cudaFuncAttributeMaxDynamicSharedMemorySize, ATTN_SMEM);

    // 1) RMSNorm1
    rmsnorm_kernel<<<S, 256>>>(x, n1w, hB, nullptr);

    // 2) fused QKV projections (bf16 3-term tensor cores)
    qkv_kernel<<<dim3(12, 32), 256>>>(hB, wq, bq, wk, bk, wv, bv);

    // 3) sliding-window attention (K/V shared across kv-group)
    attn_kernel<<<dim3(S/8, NKV), 256, ATTN_SMEM>>>(sink);

    // 4) O-proj + residual
    oproj_kernel<<<dim3(8, 32), 256>>>(wo, bo, x);

    // 5) RMSNorm2 (fp32 + fp16 planes)
    rmsnorm_kernel<<<S, 256>>>(x1B, n2w, h2B, h2hB);

    // 6) router + grouping
    zero_kernel<<<1, 32>>>();
    router_kernel<<<S/8, 256>>>(rw, rb);
    place_kernel<<<1, 1024>>>();
    colsum_kernel<<<NE, 256>>>();

    // 7) grouped MoE GEMMs (top-2 only, fp16, BM=64, fp16 activations)
    moe1_kernel<<<dim3(4, 32, NE), 256>>>(w1, b1);
    moe2_kernel<<<dim3(8, 32, NE), 256>>>(w2, b2);

    // 8) combine + residual, aux loss
    combine_kernel<<<S, 256>>>(out);
    aux_kernel<<<1, 32>>>(out, out_size);
}